// round 2
// baseline (speedup 1.0000x reference)
#include <cuda_runtime.h>
#include <cuda_bf16.h>
#include <math.h>

// Problem constants (fixed-shape problem)
#define Nn     50000
#define Cc     128
#define D1     256
#define D2     64
#define Ereal  800000
#define Etot   (Ereal + Nn)

// ---------------- scratch (static device globals; no runtime alloc) ----------
__device__ float    g_h [(size_t)Nn * D1];   // GEMM output / per-layer features
__device__ float    g_o [(size_t)Nn * D1];   // aggregated layer output
__device__ float    g_as[Nn];                // alpha_src per node
__device__ float    g_ad[Nn];                // alpha_dst per node
__device__ unsigned g_m [Nn];                // segment max (ordered-uint encoding)
__device__ float    g_den[Nn];               // segment sum of exp
__device__ float    g_ex[Etot];              // per-edge exp values
__device__ int      g_src[Ereal];
__device__ int      g_dst[Ereal];

// order-preserving float<->uint for atomicMax on floats of any sign
__device__ __forceinline__ unsigned fenc(float f) {
    unsigned u = __float_as_uint(f);
    return (u & 0x80000000u) ? ~u : (u | 0x80000000u);
}
__device__ __forceinline__ float fdec(unsigned u) {
    return __uint_as_float((u & 0x80000000u) ? (u & 0x7FFFFFFFu) : ~u);
}
// fenc(-inf) = ~0xFF800000 = 0x007FFFFF
#define ENC_NEG_INF 0x007FFFFFu

// ---------------- edge index copy (int32 input: JAX x64 is disabled) ---------
__global__ void conv_edges(const int* __restrict__ ei) {
    int e = blockIdx.x * blockDim.x + threadIdx.x;
    if (e < Ereal) {
        g_src[e] = ei[e];
        g_dst[e] = ei[Ereal + e];
    }
}

// ---------------- simple tiled SGEMM: C[M,Nc] = A[M,K] @ B[K,Nc] -------------
// BM=BN=64, BK=16, 256 threads, 4x4 per thread. Nc must be multiple of 64,
// K multiple of 16 (true: 128/256/256,64).
__global__ void sgemm(const float* __restrict__ A, const float* __restrict__ B,
                      float* __restrict__ C, int M, int K, int Nc) {
    __shared__ float As[16][64];
    __shared__ float Bs[16][64];
    const int block_row = blockIdx.y * 64;
    const int block_col = blockIdx.x * 64;
    const int tid = threadIdx.x;
    const int tr = tid >> 4, tc = tid & 15;

    float acc[4][4] = {};
    for (int k0 = 0; k0 < K; k0 += 16) {
        #pragma unroll
        for (int t = 0; t < 4; t++) {
            int idx = tid + t * 256;          // 0..1023 over 64x16 A tile
            int i = idx >> 4, j = idx & 15;
            int gr = block_row + i;
            As[j][i] = (gr < M) ? A[(size_t)gr * K + k0 + j] : 0.f;
        }
        #pragma unroll
        for (int t = 0; t < 4; t++) {
            int idx = tid + t * 256;          // 16x64 B tile
            int j = idx >> 6, c = idx & 63;
            Bs[j][c] = B[(size_t)(k0 + j) * Nc + block_col + c];
        }
        __syncthreads();
        #pragma unroll
        for (int kk = 0; kk < 16; kk++) {
            float a[4], b[4];
            #pragma unroll
            for (int m = 0; m < 4; m++) a[m] = As[kk][tr * 4 + m];
            #pragma unroll
            for (int n = 0; n < 4; n++) b[n] = Bs[kk][tc * 4 + n];
            #pragma unroll
            for (int m = 0; m < 4; m++)
                #pragma unroll
                for (int n = 0; n < 4; n++)
                    acc[m][n] += a[m] * b[n];
        }
        __syncthreads();
    }
    #pragma unroll
    for (int m = 0; m < 4; m++) {
        int gr = block_row + tr * 4 + m;
        if (gr < M) {
            #pragma unroll
            for (int n = 0; n < 4; n++)
                C[(size_t)gr * Nc + block_col + tc * 4 + n] = acc[m][n];
        }
    }
}

// ---------------- per-node attention dots: as[n]=h.a_src, ad[n]=h.a_dst ------
__global__ void alpha_k(const float* __restrict__ h, const float* __restrict__ av,
                        const float* __restrict__ bv, int d) {
    int gw = (blockIdx.x * blockDim.x + threadIdx.x) >> 5;
    int lane = threadIdx.x & 31;
    if (gw >= Nn) return;
    float s1 = 0.f, s2 = 0.f;
    for (int j = lane; j < d; j += 32) {
        float v = h[(size_t)gw * d + j];
        s1 += v * av[j];
        s2 += v * bv[j];
    }
    #pragma unroll
    for (int o = 16; o; o >>= 1) {
        s1 += __shfl_xor_sync(0xFFFFFFFFu, s1, o);
        s2 += __shfl_xor_sync(0xFFFFFFFFu, s2, o);
    }
    if (lane == 0) { g_as[gw] = s1; g_ad[gw] = s2; }
}

// ---------------- inits ------------------------------------------------------
__global__ void init_md() {
    int n = blockIdx.x * blockDim.x + threadIdx.x;
    if (n < Nn) { g_m[n] = ENC_NEG_INF; g_den[n] = 0.f; }
}
__global__ void bias_init(float* __restrict__ out, const float* __restrict__ b,
                          int d, int total) {
    int i = blockIdx.x * blockDim.x + threadIdx.x;
    if (i < total) out[i] = b[i % d];
}
__global__ void out_init1(float* __restrict__ out, const float* __restrict__ b) {
    int n = blockIdx.x * blockDim.x + threadIdx.x;
    if (n < Nn) out[n] = b[0];
}

// ---------------- edge pass 1: segment max of leaky-relu logits --------------
__global__ void edge_max() {
    int e = blockIdx.x * blockDim.x + threadIdx.x;
    if (e >= Etot) return;
    int s, d;
    if (e < Ereal) { s = g_src[e]; d = g_dst[e]; } else { s = d = e - Ereal; }
    float l = g_as[s] + g_ad[d];
    l = l > 0.f ? l : 0.2f * l;
    atomicMax(&g_m[d], fenc(l));
}

// ---------------- edge pass 2: exp + segment sum ------------------------------
__global__ void edge_exp() {
    int e = blockIdx.x * blockDim.x + threadIdx.x;
    if (e >= Etot) return;
    int s, d;
    if (e < Ereal) { s = g_src[e]; d = g_dst[e]; } else { s = d = e - Ereal; }
    float l = g_as[s] + g_ad[d];
    l = l > 0.f ? l : 0.2f * l;
    float v = expf(l - fdec(g_m[d]));
    g_ex[e] = v;
    atomicAdd(&g_den[d], v);
}

// ---------------- edge pass 3: weighted scatter (vector, d % 4 == 0) ----------
__global__ void edge_scatter_vec(const float* __restrict__ h, float* __restrict__ out,
                                 int d) {
    int gw = (blockIdx.x * blockDim.x + threadIdx.x) >> 5;
    int lane = threadIdx.x & 31;
    if (gw >= Etot) return;
    int s, dn;
    if (gw < Ereal) { s = g_src[gw]; dn = g_dst[gw]; } else { s = dn = gw - Ereal; }
    float coef = g_ex[gw] / g_den[dn];
    const float4* hv = (const float4*)(h + (size_t)s * d);
    float4* ov = (float4*)(out + (size_t)dn * d);
    int d4 = d >> 2;
    for (int j = lane; j < d4; j += 32) {
        float4 v = hv[j];
        v.x *= coef; v.y *= coef; v.z *= coef; v.w *= coef;
        atomicAdd(&ov[j], v);   // REDG.128 on sm_90+
    }
}

// ---------------- edge pass 3 for d == 1 --------------------------------------
__global__ void edge_scatter1(const float* __restrict__ h, float* __restrict__ out) {
    int e = blockIdx.x * blockDim.x + threadIdx.x;
    if (e >= Etot) return;
    int s, dn;
    if (e < Ereal) { s = g_src[e]; dn = g_dst[e]; } else { s = dn = e - Ereal; }
    float coef = g_ex[e] / g_den[dn];
    atomicAdd(&out[dn], coef * h[s]);
}

// ---------------- ELU in place -------------------------------------------------
__global__ void elu_k(float* __restrict__ p, int total) {
    int i = blockIdx.x * blockDim.x + threadIdx.x;
    if (i < total) {
        float v = p[i];
        p[i] = v > 0.f ? v : expm1f(v);
    }
}

// ---------------- layer 3 matvec + alpha scalars -------------------------------
__global__ void matvec_alpha3(const float* __restrict__ A, const float* __restrict__ w,
                              const float* __restrict__ as3, const float* __restrict__ ad3,
                              float* __restrict__ y, int k) {
    int gw = (blockIdx.x * blockDim.x + threadIdx.x) >> 5;
    int lane = threadIdx.x & 31;
    if (gw >= Nn) return;
    float s = 0.f;
    for (int j = lane; j < k; j += 32) s += A[(size_t)gw * k + j] * w[j];
    #pragma unroll
    for (int o = 16; o; o >>= 1) s += __shfl_xor_sync(0xFFFFFFFFu, s, o);
    if (lane == 0) {
        y[gw] = s;
        g_as[gw] = s * as3[0];
        g_ad[gw] = s * ad3[0];
    }
}

// =============================== launcher ======================================
extern "C" void kernel_launch(void* const* d_in, const int* in_sizes, int n_in,
                              void* d_out, int out_size) {
    const float* x   = (const float*)d_in[0];
    const int*   ei  = (const int*)d_in[1];    // int32: JAX x64 disabled
    const float *W1 = (const float*)d_in[2],  *as1 = (const float*)d_in[3],
                *ad1 = (const float*)d_in[4], *b1  = (const float*)d_in[5];
    const float *W2 = (const float*)d_in[6],  *as2 = (const float*)d_in[7],
                *ad2 = (const float*)d_in[8], *b2  = (const float*)d_in[9];
    const float *W3 = (const float*)d_in[10], *as3 = (const float*)d_in[11],
                *ad3 = (const float*)d_in[12], *b3 = (const float*)d_in[13];
    float* out = (float*)d_out;

    float *ph, *po;
    cudaGetSymbolAddress((void**)&ph, g_h);
    cudaGetSymbolAddress((void**)&po, g_o);

    const int TB = 256;
    const int nodeBlocks  = (Nn + TB - 1) / TB;
    const int edgeBlocks  = (Etot + TB - 1) / TB;
    const int warpEdgeBlk = (Etot * 32 + TB - 1) / TB;   // warp per edge
    const int warpNodeBlk = (Nn * 32 + TB - 1) / TB;     // warp per node

    conv_edges<<<(Ereal + TB - 1) / TB, TB>>>(ei);

    // ---------------- layer 1: 128 -> 256 ----------------
    {
        dim3 grid(D1 / 64, (Nn + 63) / 64);
        sgemm<<<grid, 256>>>(x, W1, ph, Nn, Cc, D1);
        alpha_k<<<warpNodeBlk, TB>>>(ph, as1, ad1, D1);
        init_md<<<nodeBlocks, TB>>>();
        bias_init<<<((size_t)Nn * D1 + TB - 1) / TB, TB>>>(po, b1, D1, Nn * D1);
        edge_max<<<edgeBlocks, TB>>>();
        edge_exp<<<edgeBlocks, TB>>>();
        edge_scatter_vec<<<warpEdgeBlk, TB>>>(ph, po, D1);
        elu_k<<<((size_t)Nn * D1 + TB - 1) / TB, TB>>>(po, Nn * D1);
    }

    // ---------------- layer 2: 256 -> 64 ----------------
    {
        dim3 grid(D2 / 64, (Nn + 63) / 64);
        sgemm<<<grid, 256>>>(po, W2, ph, Nn, D1, D2);
        alpha_k<<<warpNodeBlk, TB>>>(ph, as2, ad2, D2);
        init_md<<<nodeBlocks, TB>>>();
        bias_init<<<((size_t)Nn * D2 + TB - 1) / TB, TB>>>(po, b2, D2, Nn * D2);
        edge_max<<<edgeBlocks, TB>>>();
        edge_exp<<<edgeBlocks, TB>>>();
        edge_scatter_vec<<<warpEdgeBlk, TB>>>(ph, po, D2);
        elu_k<<<((size_t)Nn * D2 + TB - 1) / TB, TB>>>(po, Nn * D2);
    }

    // ---------------- layer 3: 64 -> 1 ----------------
    {
        matvec_alpha3<<<warpNodeBlk, TB>>>(po, W3, as3, ad3, ph, D2);
        init_md<<<nodeBlocks, TB>>>();
        out_init1<<<nodeBlocks, TB>>>(out, b3);
        edge_max<<<edgeBlocks, TB>>>();
        edge_exp<<<edgeBlocks, TB>>>();
        edge_scatter1<<<edgeBlocks, TB>>>(ph, out);
    }
}

// round 3
// speedup vs baseline: 1.6377x; 1.6377x over previous
#include <cuda_runtime.h>
#include <cuda_bf16.h>
#include <math.h>

#define Nn     50000
#define Cc     128
#define D1     256
#define D2     64
#define Ereal  800000
#define Etot   (Ereal + Nn)
#define FULL   0xFFFFFFFFu

// ---------------- scratch ------------------------------------------------------
__device__ float g_h [(size_t)Nn * D1];
__device__ float g_o [(size_t)Nn * D1];
__device__ float g_as[Nn];
__device__ float g_ad[Nn];
__device__ int   g_cnt [Nn];
__device__ int   g_wofs[Nn];
__device__ int   g_rowptr[Nn + 1];
__device__ int   g_csr[Etot];

// ---------------- CSR build ----------------------------------------------------
__global__ void init_cnt() {
    int n = blockIdx.x * blockDim.x + threadIdx.x;
    if (n < Nn) g_cnt[n] = 1;                    // self-loop pre-counted
}
__global__ void count_k(const int* __restrict__ ei) {
    int e = blockIdx.x * blockDim.x + threadIdx.x;
    if (e < Ereal) atomicAdd(&g_cnt[ei[Ereal + e]], 1);
}
// single-block exclusive scan over g_cnt -> g_rowptr, g_wofs
__global__ void scan_k() {
    __shared__ int buf[1024];
    __shared__ int carry;
    int tid = threadIdx.x;
    if (tid == 0) carry = 0;
    __syncthreads();
    for (int base = 0; base < Nn; base += 1024) {
        int i = base + tid;
        int v = (i < Nn) ? g_cnt[i] : 0;
        buf[tid] = v;
        __syncthreads();
        for (int off = 1; off < 1024; off <<= 1) {
            int t = (tid >= off) ? buf[tid - off] : 0;
            __syncthreads();
            buf[tid] += t;
            __syncthreads();
        }
        int c = carry;
        if (i < Nn) {
            int excl = c + buf[tid] - v;
            g_rowptr[i] = excl;
            g_wofs[i]   = excl;
        }
        __syncthreads();
        if (tid == 0) carry = c + buf[1023];
        __syncthreads();
    }
    if (tid == 0) g_rowptr[Nn] = carry;
}
__global__ void place_k(const int* __restrict__ ei) {
    int e = blockIdx.x * blockDim.x + threadIdx.x;
    if (e >= Etot) return;
    int s, d;
    if (e < Ereal) { s = ei[e]; d = ei[Ereal + e]; } else { s = d = e - Ereal; }
    int pos = atomicAdd(&g_wofs[d], 1);
    g_csr[pos] = s;
}

// ---------------- tiled SGEMM: C[M,Nc] = A[M,K] @ B[K,Nc] ----------------------
__global__ void sgemm(const float* __restrict__ A, const float* __restrict__ B,
                      float* __restrict__ C, int M, int K, int Nc) {
    __shared__ float As[16][64];
    __shared__ float Bs[16][64];
    const int block_row = blockIdx.y * 64;
    const int block_col = blockIdx.x * 64;
    const int tid = threadIdx.x;
    const int tr = tid >> 4, tc = tid & 15;

    float acc[4][4] = {};
    for (int k0 = 0; k0 < K; k0 += 16) {
        #pragma unroll
        for (int t = 0; t < 4; t++) {
            int idx = tid + t * 256;
            int i = idx >> 4, j = idx & 15;
            int gr = block_row + i;
            As[j][i] = (gr < M) ? A[(size_t)gr * K + k0 + j] : 0.f;
        }
        #pragma unroll
        for (int t = 0; t < 4; t++) {
            int idx = tid + t * 256;
            int j = idx >> 6, c = idx & 63;
            Bs[j][c] = B[(size_t)(k0 + j) * Nc + block_col + c];
        }
        __syncthreads();
        #pragma unroll
        for (int kk = 0; kk < 16; kk++) {
            float a[4], b[4];
            #pragma unroll
            for (int m = 0; m < 4; m++) a[m] = As[kk][tr * 4 + m];
            #pragma unroll
            for (int n = 0; n < 4; n++) b[n] = Bs[kk][tc * 4 + n];
            #pragma unroll
            for (int m = 0; m < 4; m++)
                #pragma unroll
                for (int n = 0; n < 4; n++)
                    acc[m][n] += a[m] * b[n];
        }
        __syncthreads();
    }
    #pragma unroll
    for (int m = 0; m < 4; m++) {
        int gr = block_row + tr * 4 + m;
        if (gr < M) {
            #pragma unroll
            for (int n = 0; n < 4; n++)
                C[(size_t)gr * Nc + block_col + tc * 4 + n] = acc[m][n];
        }
    }
}

// ---------------- per-node attention dots --------------------------------------
__global__ void alpha_k(const float* __restrict__ h, const float* __restrict__ av,
                        const float* __restrict__ bv, int d) {
    int gw = (blockIdx.x * blockDim.x + threadIdx.x) >> 5;
    int lane = threadIdx.x & 31;
    if (gw >= Nn) return;
    float s1 = 0.f, s2 = 0.f;
    for (int j = lane; j < d; j += 32) {
        float v = h[(size_t)gw * d + j];
        s1 += v * av[j];
        s2 += v * bv[j];
    }
    #pragma unroll
    for (int o = 16; o; o >>= 1) {
        s1 += __shfl_xor_sync(FULL, s1, o);
        s2 += __shfl_xor_sync(FULL, s2, o);
    }
    if (lane == 0) { g_as[gw] = s1; g_ad[gw] = s2; }
}

// ---------------- layer 3 matvec + alpha scalars --------------------------------
__global__ void matvec_alpha3(const float* __restrict__ A, const float* __restrict__ w,
                              const float* __restrict__ as3, const float* __restrict__ ad3,
                              float* __restrict__ y, int k) {
    int gw = (blockIdx.x * blockDim.x + threadIdx.x) >> 5;
    int lane = threadIdx.x & 31;
    if (gw >= Nn) return;
    float s = 0.f;
    for (int j = lane; j < k; j += 32) s += A[(size_t)gw * k + j] * w[j];
    #pragma unroll
    for (int o = 16; o; o >>= 1) s += __shfl_xor_sync(FULL, s, o);
    if (lane == 0) {
        y[gw] = s;
        g_as[gw] = s * as3[0];
        g_ad[gw] = s * ad3[0];
    }
}

// ---------------- fused softmax + aggregate (warp per node) --------------------
__device__ __forceinline__ float lrelu(float l) { return l > 0.f ? l : 0.2f * l; }
__device__ __forceinline__ float elu1(float v)  { return v > 0.f ? v : expm1f(v); }

template<int D, bool DO_ELU>
__global__ void agg_k(const float* __restrict__ h, float* __restrict__ out,
                      const float* __restrict__ bias) {
    int gw   = (blockIdx.x * blockDim.x + threadIdx.x) >> 5;
    int lane = threadIdx.x & 31;
    if (gw >= Nn) return;
    const int start = g_rowptr[gw];
    const int end   = g_rowptr[gw + 1];
    const float adn = g_ad[gw];

    // ---- online softmax stats over incoming edges (lanes parallel) ----
    float m = -3.0e38f, s = 0.f;
    for (int e = start + lane; e < end; e += 32) {
        float l = lrelu(g_as[g_csr[e]] + adn);
        float mn = fmaxf(m, l);
        s = s * __expf(m - mn) + __expf(l - mn);
        m = mn;
    }
    #pragma unroll
    for (int off = 16; off; off >>= 1) {
        float mo = __shfl_xor_sync(FULL, m, off);
        float so = __shfl_xor_sync(FULL, s, off);
        float mn = fmaxf(m, mo);
        s = s * __expf(m - mn) + so * __expf(mo - mn);
        m = mn;
    }
    const float inv_den = 1.f / s;

    if (D == 256) {
        float4 a0 = ((const float4*)bias)[lane * 2];
        float4 a1 = ((const float4*)bias)[lane * 2 + 1];
        int e = start;
        for (; e + 2 <= end; e += 2) {
            int s0 = g_csr[e], s1i = g_csr[e + 1];
            float c0 = __expf(lrelu(g_as[s0]  + adn) - m) * inv_den;
            float c1 = __expf(lrelu(g_as[s1i] + adn) - m) * inv_den;
            const float4* h0 = (const float4*)(h + (size_t)s0  * 256);
            const float4* h1 = (const float4*)(h + (size_t)s1i * 256);
            float4 v00 = h0[lane * 2], v01 = h0[lane * 2 + 1];
            float4 v10 = h1[lane * 2], v11 = h1[lane * 2 + 1];
            a0.x += c0 * v00.x + c1 * v10.x; a0.y += c0 * v00.y + c1 * v10.y;
            a0.z += c0 * v00.z + c1 * v10.z; a0.w += c0 * v00.w + c1 * v10.w;
            a1.x += c0 * v01.x + c1 * v11.x; a1.y += c0 * v01.y + c1 * v11.y;
            a1.z += c0 * v01.z + c1 * v11.z; a1.w += c0 * v01.w + c1 * v11.w;
        }
        if (e < end) {
            int s0 = g_csr[e];
            float c0 = __expf(lrelu(g_as[s0] + adn) - m) * inv_den;
            const float4* h0 = (const float4*)(h + (size_t)s0 * 256);
            float4 v00 = h0[lane * 2], v01 = h0[lane * 2 + 1];
            a0.x += c0 * v00.x; a0.y += c0 * v00.y; a0.z += c0 * v00.z; a0.w += c0 * v00.w;
            a1.x += c0 * v01.x; a1.y += c0 * v01.y; a1.z += c0 * v01.z; a1.w += c0 * v01.w;
        }
        if (DO_ELU) {
            a0.x = elu1(a0.x); a0.y = elu1(a0.y); a0.z = elu1(a0.z); a0.w = elu1(a0.w);
            a1.x = elu1(a1.x); a1.y = elu1(a1.y); a1.z = elu1(a1.z); a1.w = elu1(a1.w);
        }
        float4* ov = (float4*)(out + (size_t)gw * 256);
        ov[lane * 2] = a0; ov[lane * 2 + 1] = a1;
    } else if (D == 64) {
        float2 a = ((const float2*)bias)[lane];
        int e = start;
        for (; e + 2 <= end; e += 2) {
            int s0 = g_csr[e], s1i = g_csr[e + 1];
            float c0 = __expf(lrelu(g_as[s0]  + adn) - m) * inv_den;
            float c1 = __expf(lrelu(g_as[s1i] + adn) - m) * inv_den;
            float2 v0 = ((const float2*)(h + (size_t)s0  * 64))[lane];
            float2 v1 = ((const float2*)(h + (size_t)s1i * 64))[lane];
            a.x += c0 * v0.x + c1 * v1.x;
            a.y += c0 * v0.y + c1 * v1.y;
        }
        if (e < end) {
            int s0 = g_csr[e];
            float c0 = __expf(lrelu(g_as[s0] + adn) - m) * inv_den;
            float2 v0 = ((const float2*)(h + (size_t)s0 * 64))[lane];
            a.x += c0 * v0.x; a.y += c0 * v0.y;
        }
        if (DO_ELU) { a.x = elu1(a.x); a.y = elu1(a.y); }
        ((float2*)(out + (size_t)gw * 64))[lane] = a;
    } else { // D == 1
        float a = 0.f;
        for (int e = start + lane; e < end; e += 32) {
            int sn = g_csr[e];
            float c = __expf(lrelu(g_as[sn] + adn) - m) * inv_den;
            a += c * h[sn];
        }
        #pragma unroll
        for (int off = 16; off; off >>= 1) a += __shfl_xor_sync(FULL, a, off);
        if (lane == 0) out[gw] = a + bias[0];
    }
}

// =============================== launcher ======================================
extern "C" void kernel_launch(void* const* d_in, const int* in_sizes, int n_in,
                              void* d_out, int out_size) {
    const float* x  = (const float*)d_in[0];
    const int*   ei = (const int*)d_in[1];
    const float *W1 = (const float*)d_in[2],  *as1 = (const float*)d_in[3],
                *ad1 = (const float*)d_in[4], *b1  = (const float*)d_in[5];
    const float *W2 = (const float*)d_in[6],  *as2 = (const float*)d_in[7],
                *ad2 = (const float*)d_in[8], *b2  = (const float*)d_in[9];
    const float *W3 = (const float*)d_in[10], *as3 = (const float*)d_in[11],
                *ad3 = (const float*)d_in[12], *b3 = (const float*)d_in[13];
    float* out = (float*)d_out;

    float *ph, *po;
    cudaGetSymbolAddress((void**)&ph, g_h);
    cudaGetSymbolAddress((void**)&po, g_o);

    const int TB = 256;
    const int nodeBlocks  = (Nn + TB - 1) / TB;
    const int warpNodeBlk = (Nn * 32 + TB - 1) / TB;

    // ---- CSR build (dst-grouped) ----
    init_cnt<<<nodeBlocks, TB>>>();
    count_k<<<(Ereal + TB - 1) / TB, TB>>>(ei);
    scan_k<<<1, 1024>>>();
    place_k<<<(Etot + TB - 1) / TB, TB>>>(ei);

    // ---- layer 1: 128 -> 256 ----
    {
        dim3 grid(D1 / 64, (Nn + 63) / 64);
        sgemm<<<grid, 256>>>(x, W1, ph, Nn, Cc, D1);
        alpha_k<<<warpNodeBlk, TB>>>(ph, as1, ad1, D1);
        agg_k<256, true><<<warpNodeBlk, TB>>>(ph, po, b1);
    }
    // ---- layer 2: 256 -> 64 ----
    {
        dim3 grid(D2 / 64, (Nn + 63) / 64);
        sgemm<<<grid, 256>>>(po, W2, ph, Nn, D1, D2);
        alpha_k<<<warpNodeBlk, TB>>>(ph, as2, ad2, D2);
        agg_k<64, true><<<warpNodeBlk, TB>>>(ph, po, b2);
    }
    // ---- layer 3: 64 -> 1 ----
    {
        matvec_alpha3<<<warpNodeBlk, TB>>>(po, W3, as3, ad3, ph, D2);
        agg_k<1, false><<<warpNodeBlk, TB>>>(ph, out, b3);
    }
}

// round 4
// speedup vs baseline: 2.1445x; 1.3095x over previous
#include <cuda_runtime.h>
#include <cuda_bf16.h>
#include <math.h>

#define Nn     50000
#define Cc     128
#define D1     256
#define D2     64
#define Ereal  800000
#define Etot   (Ereal + Nn)
#define FULL   0xFFFFFFFFu

// ---------------- scratch ------------------------------------------------------
__device__ float g_h [(size_t)Nn * D1];
__device__ float g_o [(size_t)Nn * D1];
__device__ float g_as[Nn];
__device__ float g_ad[Nn];
__device__ int   g_cnt [Nn];
__device__ int   g_wofs[Nn];
__device__ int   g_rowptr[Nn + 1];
__device__ int   g_csr[Etot];

// ---------------- CSR build ----------------------------------------------------
__global__ void init_cnt() {
    int n = blockIdx.x * blockDim.x + threadIdx.x;
    if (n < Nn) g_cnt[n] = 1;                    // self-loop pre-counted
}
__global__ void count_k(const int* __restrict__ ei) {
    int e = blockIdx.x * blockDim.x + threadIdx.x;
    if (e < Ereal) atomicAdd(&g_cnt[ei[Ereal + e]], 1);
}
// single-block exclusive scan (warp-shuffle based)
__global__ void scan_k() {
    __shared__ int wsum[32];
    __shared__ int carry_s;
    int tid = threadIdx.x, lane = tid & 31, wid = tid >> 5;
    if (tid == 0) carry_s = 0;
    __syncthreads();
    for (int base = 0; base < Nn; base += 1024) {
        int i = base + tid;
        int v = (i < Nn) ? g_cnt[i] : 0;
        int p = v;
        #pragma unroll
        for (int o = 1; o < 32; o <<= 1) {
            int t = __shfl_up_sync(FULL, p, o);
            if (lane >= o) p += t;
        }
        if (lane == 31) wsum[wid] = p;
        __syncthreads();
        if (wid == 0) {
            int w = wsum[lane];
            #pragma unroll
            for (int o = 1; o < 32; o <<= 1) {
                int t = __shfl_up_sync(FULL, w, o);
                if (lane >= o) w += t;
            }
            wsum[lane] = w;
        }
        __syncthreads();
        int carry = carry_s;
        int chunk_total = wsum[31];
        int excl = carry + (wid ? wsum[wid - 1] : 0) + p - v;
        if (i < Nn) { g_rowptr[i] = excl; g_wofs[i] = excl; }
        __syncthreads();
        if (tid == 0) carry_s = carry + chunk_total;
        __syncthreads();
    }
    if (threadIdx.x == 0) g_rowptr[Nn] = carry_s;
}
__global__ void place_k(const int* __restrict__ ei) {
    int e = blockIdx.x * blockDim.x + threadIdx.x;
    if (e >= Etot) return;
    int s, d;
    if (e < Ereal) { s = ei[e]; d = ei[Ereal + e]; } else { s = d = e - Ereal; }
    int pos = atomicAdd(&g_wofs[d], 1);
    g_csr[pos] = s;
}

// ================= split-tf32 tensor-core GEMM ==================================
// C[M,N] = A[M,K] @ B[K,N], fp32 in/out, ~fp32 accuracy via hi/lo tf32 split.
// BM=128, BN=64, BK=16. 256 threads = 8 warps in 4(m) x 2(n); warp tile 32x32.
#define GSTRIDE 20   // smem row stride (conflict-free for quad access pattern)

__device__ __forceinline__ unsigned tf32_hi(float v) {
    return __float_as_uint(v) & 0xFFFFE000u;
}
__device__ __forceinline__ void mma_tf32(float (&c)[4], const unsigned* a, const unsigned* b) {
    asm volatile(
        "mma.sync.aligned.m16n8k8.row.col.f32.tf32.tf32.f32 "
        "{%0,%1,%2,%3}, {%4,%5,%6,%7}, {%8,%9}, {%0,%1,%2,%3};\n"
        : "+f"(c[0]), "+f"(c[1]), "+f"(c[2]), "+f"(c[3])
        : "r"(a[0]), "r"(a[1]), "r"(a[2]), "r"(a[3]), "r"(b[0]), "r"(b[1]));
}

__global__ void __launch_bounds__(256) gemm_tc(const float* __restrict__ A,
                                               const float* __restrict__ B,
                                               float* __restrict__ C,
                                               int M, int K, int N) {
    __shared__ unsigned AsH[128 * GSTRIDE];
    __shared__ unsigned AsL[128 * GSTRIDE];
    __shared__ unsigned BsH[64 * GSTRIDE];   // stored transposed: Bs[n][k]
    __shared__ unsigned BsL[64 * GSTRIDE];

    const int br = blockIdx.y * 128;
    const int bn = blockIdx.x * 64;
    const int tid = threadIdx.x;
    const int lane = tid & 31;
    const int warp = tid >> 5;
    const int wm = (warp >> 1) * 32;   // warp row offset in tile
    const int wn = (warp & 1) * 32;    // warp col offset in tile

    float acc[2][4][4];
    #pragma unroll
    for (int m = 0; m < 2; m++)
        #pragma unroll
        for (int n = 0; n < 4; n++)
            #pragma unroll
            for (int r = 0; r < 4; r++) acc[m][n][r] = 0.f;

    const int q = lane >> 2;       // 0..7
    const int rr = lane & 3;       // 0..3

    for (int k0 = 0; k0 < K; k0 += 16) {
        // ---- load A tile 128x16 (float4, row-guarded) ----
        #pragma unroll
        for (int t = 0; t < 2; t++) {
            int f4 = tid + t * 256;          // 0..511
            int row = f4 >> 2, c4 = (f4 & 3) * 4;
            float4 v = make_float4(0.f, 0.f, 0.f, 0.f);
            if (br + row < M)
                v = *(const float4*)(A + (size_t)(br + row) * K + k0 + c4);
            unsigned h0 = tf32_hi(v.x), h1 = tf32_hi(v.y), h2 = tf32_hi(v.z), h3 = tf32_hi(v.w);
            int o = row * GSTRIDE + c4;
            AsH[o + 0] = h0; AsH[o + 1] = h1; AsH[o + 2] = h2; AsH[o + 3] = h3;
            AsL[o + 0] = tf32_hi(v.x - __uint_as_float(h0));
            AsL[o + 1] = tf32_hi(v.y - __uint_as_float(h1));
            AsL[o + 2] = tf32_hi(v.z - __uint_as_float(h2));
            AsL[o + 3] = tf32_hi(v.w - __uint_as_float(h3));
        }
        // ---- load B tile 16x64, store transposed Bs[n][k] ----
        {
            int row = tid >> 4;              // 0..15 (k)
            int n4  = (tid & 15) * 4;        // 0..60 (n)
            float4 v = *(const float4*)(B + (size_t)(k0 + row) * N + bn + n4);
            unsigned h0 = tf32_hi(v.x), h1 = tf32_hi(v.y), h2 = tf32_hi(v.z), h3 = tf32_hi(v.w);
            BsH[(n4 + 0) * GSTRIDE + row] = h0;
            BsH[(n4 + 1) * GSTRIDE + row] = h1;
            BsH[(n4 + 2) * GSTRIDE + row] = h2;
            BsH[(n4 + 3) * GSTRIDE + row] = h3;
            BsL[(n4 + 0) * GSTRIDE + row] = tf32_hi(v.x - __uint_as_float(h0));
            BsL[(n4 + 1) * GSTRIDE + row] = tf32_hi(v.y - __uint_as_float(h1));
            BsL[(n4 + 2) * GSTRIDE + row] = tf32_hi(v.z - __uint_as_float(h2));
            BsL[(n4 + 3) * GSTRIDE + row] = tf32_hi(v.w - __uint_as_float(h3));
        }
        __syncthreads();

        #pragma unroll
        for (int kk = 0; kk < 16; kk += 8) {
            unsigned ah[2][4], al[2][4], bh[4][2], bl[4][2];
            #pragma unroll
            for (int m = 0; m < 2; m++) {
                int rbase = (wm + m * 16 + q) * GSTRIDE + kk + rr;
                ah[m][0] = AsH[rbase];
                ah[m][1] = AsH[rbase + 8 * GSTRIDE];
                ah[m][2] = AsH[rbase + 4];
                ah[m][3] = AsH[rbase + 8 * GSTRIDE + 4];
                al[m][0] = AsL[rbase];
                al[m][1] = AsL[rbase + 8 * GSTRIDE];
                al[m][2] = AsL[rbase + 4];
                al[m][3] = AsL[rbase + 8 * GSTRIDE + 4];
            }
            #pragma unroll
            for (int n = 0; n < 4; n++) {
                int nbase = (wn + n * 8 + q) * GSTRIDE + kk + rr;
                bh[n][0] = BsH[nbase];
                bh[n][1] = BsH[nbase + 4];
                bl[n][0] = BsL[nbase];
                bl[n][1] = BsL[nbase + 4];
            }
            #pragma unroll
            for (int m = 0; m < 2; m++)
                #pragma unroll
                for (int n = 0; n < 4; n++) {
                    mma_tf32(acc[m][n], ah[m], bh[n]);
                    mma_tf32(acc[m][n], ah[m], bl[n]);
                    mma_tf32(acc[m][n], al[m], bh[n]);
                }
        }
        __syncthreads();
    }

    // ---- epilogue: c0,c1 adjacent cols; c2,c3 at row+8 ----
    #pragma unroll
    for (int m = 0; m < 2; m++) {
        int row0 = br + wm + m * 16 + q;
        #pragma unroll
        for (int n = 0; n < 4; n++) {
            int col = bn + wn + n * 8 + rr * 2;
            if (row0 < M)
                *(float2*)(C + (size_t)row0 * N + col) = make_float2(acc[m][n][0], acc[m][n][1]);
            if (row0 + 8 < M)
                *(float2*)(C + (size_t)(row0 + 8) * N + col) = make_float2(acc[m][n][2], acc[m][n][3]);
        }
    }
}

// ---------------- per-node attention dots --------------------------------------
__global__ void alpha_k(const float* __restrict__ h, const float* __restrict__ av,
                        const float* __restrict__ bv, int d) {
    int gw = (blockIdx.x * blockDim.x + threadIdx.x) >> 5;
    int lane = threadIdx.x & 31;
    if (gw >= Nn) return;
    float s1 = 0.f, s2 = 0.f;
    for (int j = lane; j < d; j += 32) {
        float v = h[(size_t)gw * d + j];
        s1 += v * av[j];
        s2 += v * bv[j];
    }
    #pragma unroll
    for (int o = 16; o; o >>= 1) {
        s1 += __shfl_xor_sync(FULL, s1, o);
        s2 += __shfl_xor_sync(FULL, s2, o);
    }
    if (lane == 0) { g_as[gw] = s1; g_ad[gw] = s2; }
}

// ---------------- layer 3 matvec + alpha scalars --------------------------------
__global__ void matvec_alpha3(const float* __restrict__ A, const float* __restrict__ w,
                              const float* __restrict__ as3, const float* __restrict__ ad3,
                              float* __restrict__ y, int k) {
    int gw = (blockIdx.x * blockDim.x + threadIdx.x) >> 5;
    int lane = threadIdx.x & 31;
    if (gw >= Nn) return;
    float s = 0.f;
    for (int j = lane; j < k; j += 32) s += A[(size_t)gw * k + j] * w[j];
    #pragma unroll
    for (int o = 16; o; o >>= 1) s += __shfl_xor_sync(FULL, s, o);
    if (lane == 0) {
        y[gw] = s;
        g_as[gw] = s * as3[0];
        g_ad[gw] = s * ad3[0];
    }
}

// ---------------- fused softmax + aggregate (warp per node) --------------------
__device__ __forceinline__ float lrelu(float l) { return l > 0.f ? l : 0.2f * l; }
__device__ __forceinline__ float elu1(float v)  { return v > 0.f ? v : expm1f(v); }

template<int D, bool DO_ELU>
__global__ void agg_k(const float* __restrict__ h, float* __restrict__ out,
                      const float* __restrict__ bias) {
    int gw   = (blockIdx.x * blockDim.x + threadIdx.x) >> 5;
    int lane = threadIdx.x & 31;
    if (gw >= Nn) return;
    const int start = g_rowptr[gw];
    const int end   = g_rowptr[gw + 1];
    const float adn = g_ad[gw];

    float m = -3.0e38f, s = 0.f;
    for (int e = start + lane; e < end; e += 32) {
        float l = lrelu(g_as[g_csr[e]] + adn);
        float mn = fmaxf(m, l);
        s = s * __expf(m - mn) + __expf(l - mn);
        m = mn;
    }
    #pragma unroll
    for (int off = 16; off; off >>= 1) {
        float mo = __shfl_xor_sync(FULL, m, off);
        float so = __shfl_xor_sync(FULL, s, off);
        float mn = fmaxf(m, mo);
        s = s * __expf(m - mn) + so * __expf(mo - mn);
        m = mn;
    }
    const float inv_den = 1.f / s;

    if (D == 256) {
        float4 a0 = ((const float4*)bias)[lane * 2];
        float4 a1 = ((const float4*)bias)[lane * 2 + 1];
        int e = start;
        for (; e + 2 <= end; e += 2) {
            int s0 = g_csr[e], s1i = g_csr[e + 1];
            float c0 = __expf(lrelu(g_as[s0]  + adn) - m) * inv_den;
            float c1 = __expf(lrelu(g_as[s1i] + adn) - m) * inv_den;
            const float4* h0 = (const float4*)(h + (size_t)s0  * 256);
            const float4* h1 = (const float4*)(h + (size_t)s1i * 256);
            float4 v00 = h0[lane * 2], v01 = h0[lane * 2 + 1];
            float4 v10 = h1[lane * 2], v11 = h1[lane * 2 + 1];
            a0.x += c0 * v00.x + c1 * v10.x; a0.y += c0 * v00.y + c1 * v10.y;
            a0.z += c0 * v00.z + c1 * v10.z; a0.w += c0 * v00.w + c1 * v10.w;
            a1.x += c0 * v01.x + c1 * v11.x; a1.y += c0 * v01.y + c1 * v11.y;
            a1.z += c0 * v01.z + c1 * v11.z; a1.w += c0 * v01.w + c1 * v11.w;
        }
        if (e < end) {
            int s0 = g_csr[e];
            float c0 = __expf(lrelu(g_as[s0] + adn) - m) * inv_den;
            const float4* h0 = (const float4*)(h + (size_t)s0 * 256);
            float4 v00 = h0[lane * 2], v01 = h0[lane * 2 + 1];
            a0.x += c0 * v00.x; a0.y += c0 * v00.y; a0.z += c0 * v00.z; a0.w += c0 * v00.w;
            a1.x += c0 * v01.x; a1.y += c0 * v01.y; a1.z += c0 * v01.z; a1.w += c0 * v01.w;
        }
        if (DO_ELU) {
            a0.x = elu1(a0.x); a0.y = elu1(a0.y); a0.z = elu1(a0.z); a0.w = elu1(a0.w);
            a1.x = elu1(a1.x); a1.y = elu1(a1.y); a1.z = elu1(a1.z); a1.w = elu1(a1.w);
        }
        float4* ov = (float4*)(out + (size_t)gw * 256);
        ov[lane * 2] = a0; ov[lane * 2 + 1] = a1;
    } else if (D == 64) {
        float2 a = ((const float2*)bias)[lane];
        int e = start;
        for (; e + 2 <= end; e += 2) {
            int s0 = g_csr[e], s1i = g_csr[e + 1];
            float c0 = __expf(lrelu(g_as[s0]  + adn) - m) * inv_den;
            float c1 = __expf(lrelu(g_as[s1i] + adn) - m) * inv_den;
            float2 v0 = ((const float2*)(h + (size_t)s0  * 64))[lane];
            float2 v1 = ((const float2*)(h + (size_t)s1i * 64))[lane];
            a.x += c0 * v0.x + c1 * v1.x;
            a.y += c0 * v0.y + c1 * v1.y;
        }
        if (e < end) {
            int s0 = g_csr[e];
            float c0 = __expf(lrelu(g_as[s0] + adn) - m) * inv_den;
            float2 v0 = ((const float2*)(h + (size_t)s0 * 64))[lane];
            a.x += c0 * v0.x; a.y += c0 * v0.y;
        }
        if (DO_ELU) { a.x = elu1(a.x); a.y = elu1(a.y); }
        ((float2*)(out + (size_t)gw * 64))[lane] = a;
    } else { // D == 1
        float a = 0.f;
        for (int e = start + lane; e < end; e += 32) {
            int sn = g_csr[e];
            float c = __expf(lrelu(g_as[sn] + adn) - m) * inv_den;
            a += c * h[sn];
        }
        #pragma unroll
        for (int off = 16; off; off >>= 1) a += __shfl_xor_sync(FULL, a, off);
        if (lane == 0) out[gw] = a + bias[0];
    }
}

// =============================== launcher ======================================
extern "C" void kernel_launch(void* const* d_in, const int* in_sizes, int n_in,
                              void* d_out, int out_size) {
    const float* x  = (const float*)d_in[0];
    const int*   ei = (const int*)d_in[1];
    const float *W1 = (const float*)d_in[2],  *as1 = (const float*)d_in[3],
                *ad1 = (const float*)d_in[4], *b1  = (const float*)d_in[5];
    const float *W2 = (const float*)d_in[6],  *as2 = (const float*)d_in[7],
                *ad2 = (const float*)d_in[8], *b2  = (const float*)d_in[9];
    const float *W3 = (const float*)d_in[10], *as3 = (const float*)d_in[11],
                *ad3 = (const float*)d_in[12], *b3 = (const float*)d_in[13];
    float* out = (float*)d_out;

    float *ph, *po;
    cudaGetSymbolAddress((void**)&ph, g_h);
    cudaGetSymbolAddress((void**)&po, g_o);

    const int TB = 256;
    const int nodeBlocks  = (Nn + TB - 1) / TB;
    const int warpNodeBlk = (Nn * 32 + TB - 1) / TB;
    const int mRows = (Nn + 127) / 128;

    // ---- CSR build (dst-grouped) ----
    init_cnt<<<nodeBlocks, TB>>>();
    count_k<<<(Ereal + TB - 1) / TB, TB>>>(ei);
    scan_k<<<1, 1024>>>();
    place_k<<<(Etot + TB - 1) / TB, TB>>>(ei);

    // ---- layer 1: 128 -> 256 ----
    {
        dim3 grid(D1 / 64, mRows);
        gemm_tc<<<grid, 256>>>(x, W1, ph, Nn, Cc, D1);
        alpha_k<<<warpNodeBlk, TB>>>(ph, as1, ad1, D1);
        agg_k<256, true><<<warpNodeBlk, TB>>>(ph, po, b1);
    }
    // ---- layer 2: 256 -> 64 ----
    {
        dim3 grid(D2 / 64, mRows);
        gemm_tc<<<grid, 256>>>(po, W2, ph, Nn, D1, D2);
        alpha_k<<<warpNodeBlk, TB>>>(ph, as2, ad2, D2);
        agg_k<64, true><<<warpNodeBlk, TB>>>(ph, po, b2);
    }
    // ---- layer 3: 64 -> 1 ----
    {
        matvec_alpha3<<<warpNodeBlk, TB>>>(po, W3, as3, ad3, ph, D2);
        agg_k<1, false><<<warpNodeBlk, TB>>>(ph, out, b3);
    }
}

// round 5
// speedup vs baseline: 2.1723x; 1.0129x over previous
#include <cuda_runtime.h>
#include <cuda_bf16.h>
#include <math.h>

#define Nn     50000
#define Cc     128
#define D1     256
#define D2     64
#define Ereal  800000
#define Etot   (Ereal + Nn)
#define FULL   0xFFFFFFFFu

// ---------------- scratch ------------------------------------------------------
__device__ float g_h [(size_t)Nn * D1];
__device__ float g_o [(size_t)Nn * D1];
__device__ float g_as[Nn];
__device__ float g_ad[Nn];
__device__ float g_ps[Cc];
__device__ float g_pd[Cc];
__device__ int   g_cnt [Nn];
__device__ int   g_wofs[Nn];
__device__ int   g_rowptr[Nn + 1];
__device__ int   g_csr[Etot];

// ---------------- CSR build ----------------------------------------------------
__global__ void init_cnt() {
    int n = blockIdx.x * blockDim.x + threadIdx.x;
    if (n < Nn) g_cnt[n] = 1;                    // self-loop pre-counted
}
__global__ void count_k(const int* __restrict__ ei) {
    int e = blockIdx.x * blockDim.x + threadIdx.x;
    if (e < Ereal) atomicAdd(&g_cnt[ei[Ereal + e]], 1);
}
__global__ void scan_k() {
    __shared__ int wsum[32];
    __shared__ int carry_s;
    int tid = threadIdx.x, lane = tid & 31, wid = tid >> 5;
    if (tid == 0) carry_s = 0;
    __syncthreads();
    for (int base = 0; base < Nn; base += 1024) {
        int i = base + tid;
        int v = (i < Nn) ? g_cnt[i] : 0;
        int p = v;
        #pragma unroll
        for (int o = 1; o < 32; o <<= 1) {
            int t = __shfl_up_sync(FULL, p, o);
            if (lane >= o) p += t;
        }
        if (lane == 31) wsum[wid] = p;
        __syncthreads();
        if (wid == 0) {
            int w = wsum[lane];
            #pragma unroll
            for (int o = 1; o < 32; o <<= 1) {
                int t = __shfl_up_sync(FULL, w, o);
                if (lane >= o) w += t;
            }
            wsum[lane] = w;
        }
        __syncthreads();
        int carry = carry_s;
        int chunk_total = wsum[31];
        int excl = carry + (wid ? wsum[wid - 1] : 0) + p - v;
        if (i < Nn) { g_rowptr[i] = excl; g_wofs[i] = excl; }
        __syncthreads();
        if (tid == 0) carry_s = carry + chunk_total;
        __syncthreads();
    }
    if (threadIdx.x == 0) g_rowptr[Nn] = carry_s;
}
__global__ void place_k(const int* __restrict__ ei) {
    int e = blockIdx.x * blockDim.x + threadIdx.x;
    if (e >= Etot) return;
    int s, d;
    if (e < Ereal) { s = ei[e]; d = ei[Ereal + e]; } else { s = d = e - Ereal; }
    int pos = atomicAdd(&g_wofs[d], 1);
    g_csr[pos] = s;
}

// ---------------- fold attention vectors through W1: p = W1 @ a ----------------
__global__ void prep_p(const float* __restrict__ W1, const float* __restrict__ as1,
                       const float* __restrict__ ad1) {
    int t = threadIdx.x;            // 256 threads
    const float* a = (t < Cc) ? as1 : ad1;
    int i = t & (Cc - 1);
    float s = 0.f;
    const float* row = W1 + (size_t)i * D1;
    for (int j = 0; j < D1; j++) s += row[j] * a[j];
    if (t < Cc) g_ps[i] = s; else g_pd[i] = s;
}

// ================= split-tf32 tensor-core GEMM ==================================
#define GSTRIDE 20

__device__ __forceinline__ unsigned tf32_hi(float v) {
    return __float_as_uint(v) & 0xFFFFE000u;
}
__device__ __forceinline__ void mma_tf32(float (&c)[4], const unsigned* a, const unsigned* b) {
    asm volatile(
        "mma.sync.aligned.m16n8k8.row.col.f32.tf32.tf32.f32 "
        "{%0,%1,%2,%3}, {%4,%5,%6,%7}, {%8,%9}, {%0,%1,%2,%3};\n"
        : "+f"(c[0]), "+f"(c[1]), "+f"(c[2]), "+f"(c[3])
        : "r"(a[0]), "r"(a[1]), "r"(a[2]), "r"(a[3]), "r"(b[0]), "r"(b[1]));
}
__device__ __forceinline__ float elu1(float v) { return v > 0.f ? v : expm1f(v); }

template<bool BIAS_ELU>
__global__ void __launch_bounds__(256) gemm_tc(const float* __restrict__ A,
                                               const float* __restrict__ B,
                                               float* __restrict__ C,
                                               const float* __restrict__ bias,
                                               int M, int K, int N) {
    __shared__ unsigned AsH[128 * GSTRIDE];
    __shared__ unsigned AsL[128 * GSTRIDE];
    __shared__ unsigned BsH[64 * GSTRIDE];   // transposed: Bs[n][k]
    __shared__ unsigned BsL[64 * GSTRIDE];

    const int br = blockIdx.y * 128;
    const int bn = blockIdx.x * 64;
    const int tid = threadIdx.x;
    const int lane = tid & 31;
    const int warp = tid >> 5;
    const int wm = (warp >> 1) * 32;
    const int wn = (warp & 1) * 32;

    float acc[2][4][4];
    #pragma unroll
    for (int m = 0; m < 2; m++)
        #pragma unroll
        for (int n = 0; n < 4; n++)
            #pragma unroll
            for (int r = 0; r < 4; r++) acc[m][n][r] = 0.f;

    const int q = lane >> 2;
    const int rr = lane & 3;

    for (int k0 = 0; k0 < K; k0 += 16) {
        #pragma unroll
        for (int t = 0; t < 2; t++) {
            int f4 = tid + t * 256;
            int row = f4 >> 2, c4 = (f4 & 3) * 4;
            float4 v = make_float4(0.f, 0.f, 0.f, 0.f);
            if (br + row < M)
                v = *(const float4*)(A + (size_t)(br + row) * K + k0 + c4);
            unsigned h0 = tf32_hi(v.x), h1 = tf32_hi(v.y), h2 = tf32_hi(v.z), h3 = tf32_hi(v.w);
            int o = row * GSTRIDE + c4;
            AsH[o + 0] = h0; AsH[o + 1] = h1; AsH[o + 2] = h2; AsH[o + 3] = h3;
            AsL[o + 0] = tf32_hi(v.x - __uint_as_float(h0));
            AsL[o + 1] = tf32_hi(v.y - __uint_as_float(h1));
            AsL[o + 2] = tf32_hi(v.z - __uint_as_float(h2));
            AsL[o + 3] = tf32_hi(v.w - __uint_as_float(h3));
        }
        {
            int row = tid >> 4;
            int n4  = (tid & 15) * 4;
            float4 v = *(const float4*)(B + (size_t)(k0 + row) * N + bn + n4);
            unsigned h0 = tf32_hi(v.x), h1 = tf32_hi(v.y), h2 = tf32_hi(v.z), h3 = tf32_hi(v.w);
            BsH[(n4 + 0) * GSTRIDE + row] = h0;
            BsH[(n4 + 1) * GSTRIDE + row] = h1;
            BsH[(n4 + 2) * GSTRIDE + row] = h2;
            BsH[(n4 + 3) * GSTRIDE + row] = h3;
            BsL[(n4 + 0) * GSTRIDE + row] = tf32_hi(v.x - __uint_as_float(h0));
            BsL[(n4 + 1) * GSTRIDE + row] = tf32_hi(v.y - __uint_as_float(h1));
            BsL[(n4 + 2) * GSTRIDE + row] = tf32_hi(v.z - __uint_as_float(h2));
            BsL[(n4 + 3) * GSTRIDE + row] = tf32_hi(v.w - __uint_as_float(h3));
        }
        __syncthreads();

        #pragma unroll
        for (int kk = 0; kk < 16; kk += 8) {
            unsigned ah[2][4], al[2][4], bh[4][2], bl[4][2];
            #pragma unroll
            for (int m = 0; m < 2; m++) {
                int rbase = (wm + m * 16 + q) * GSTRIDE + kk + rr;
                ah[m][0] = AsH[rbase];
                ah[m][1] = AsH[rbase + 8 * GSTRIDE];
                ah[m][2] = AsH[rbase + 4];
                ah[m][3] = AsH[rbase + 8 * GSTRIDE + 4];
                al[m][0] = AsL[rbase];
                al[m][1] = AsL[rbase + 8 * GSTRIDE];
                al[m][2] = AsL[rbase + 4];
                al[m][3] = AsL[rbase + 8 * GSTRIDE + 4];
            }
            #pragma unroll
            for (int n = 0; n < 4; n++) {
                int nbase = (wn + n * 8 + q) * GSTRIDE + kk + rr;
                bh[n][0] = BsH[nbase];
                bh[n][1] = BsH[nbase + 4];
                bl[n][0] = BsL[nbase];
                bl[n][1] = BsL[nbase + 4];
            }
            #pragma unroll
            for (int m = 0; m < 2; m++)
                #pragma unroll
                for (int n = 0; n < 4; n++) {
                    mma_tf32(acc[m][n], ah[m], bh[n]);
                    mma_tf32(acc[m][n], ah[m], bl[n]);
                    mma_tf32(acc[m][n], al[m], bh[n]);
                }
        }
        __syncthreads();
    }

    #pragma unroll
    for (int m = 0; m < 2; m++) {
        int row0 = br + wm + m * 16 + q;
        #pragma unroll
        for (int n = 0; n < 4; n++) {
            int col = bn + wn + n * 8 + rr * 2;
            float2 v0 = make_float2(acc[m][n][0], acc[m][n][1]);
            float2 v1 = make_float2(acc[m][n][2], acc[m][n][3]);
            if (BIAS_ELU) {
                float b0 = bias[col], b1v = bias[col + 1];
                v0.x = elu1(v0.x + b0); v0.y = elu1(v0.y + b1v);
                v1.x = elu1(v1.x + b0); v1.y = elu1(v1.y + b1v);
            }
            if (row0 < M)
                *(float2*)(C + (size_t)row0 * N + col) = v0;
            if (row0 + 8 < M)
                *(float2*)(C + (size_t)(row0 + 8) * N + col) = v1;
        }
    }
}

// ---------------- per-node attention dots --------------------------------------
__global__ void alpha_k(const float* __restrict__ h, const float* __restrict__ av,
                        const float* __restrict__ bv, int d) {
    int gw = (blockIdx.x * blockDim.x + threadIdx.x) >> 5;
    int lane = threadIdx.x & 31;
    if (gw >= Nn) return;
    float s1 = 0.f, s2 = 0.f;
    for (int j = lane; j < d; j += 32) {
        float v = h[(size_t)gw * d + j];
        s1 += v * av[j];
        s2 += v * bv[j];
    }
    #pragma unroll
    for (int o = 16; o; o >>= 1) {
        s1 += __shfl_xor_sync(FULL, s1, o);
        s2 += __shfl_xor_sync(FULL, s2, o);
    }
    if (lane == 0) { g_as[gw] = s1; g_ad[gw] = s2; }
}

// ---------------- layer 3 matvec + alpha scalars --------------------------------
__global__ void matvec_alpha3(const float* __restrict__ A, const float* __restrict__ w,
                              const float* __restrict__ as3, const float* __restrict__ ad3,
                              float* __restrict__ y, int k) {
    int gw = (blockIdx.x * blockDim.x + threadIdx.x) >> 5;
    int lane = threadIdx.x & 31;
    if (gw >= Nn) return;
    float s = 0.f;
    for (int j = lane; j < k; j += 32) s += A[(size_t)gw * k + j] * w[j];
    #pragma unroll
    for (int o = 16; o; o >>= 1) s += __shfl_xor_sync(FULL, s, o);
    if (lane == 0) {
        y[gw] = s;
        g_as[gw] = s * as3[0];
        g_ad[gw] = s * ad3[0];
    }
}

// ---------------- fused softmax + aggregate (warp per node) --------------------
__device__ __forceinline__ float lrelu(float l) { return l > 0.f ? l : 0.2f * l; }

template<int D, bool DO_BIAS_ELU>
__global__ void agg_k(const float* __restrict__ h, float* __restrict__ out,
                      const float* __restrict__ bias) {
    int gw   = (blockIdx.x * blockDim.x + threadIdx.x) >> 5;
    int lane = threadIdx.x & 31;
    if (gw >= Nn) return;
    const int start = g_rowptr[gw];
    const int end   = g_rowptr[gw + 1];
    const float adn = g_ad[gw];

    float m = -3.0e38f, s = 0.f;
    for (int e = start + lane; e < end; e += 32) {
        float l = lrelu(g_as[g_csr[e]] + adn);
        float mn = fmaxf(m, l);
        s = s * __expf(m - mn) + __expf(l - mn);
        m = mn;
    }
    #pragma unroll
    for (int off = 16; off; off >>= 1) {
        float mo = __shfl_xor_sync(FULL, m, off);
        float so = __shfl_xor_sync(FULL, s, off);
        float mn = fmaxf(m, mo);
        s = s * __expf(m - mn) + so * __expf(mo - mn);
        m = mn;
    }
    const float inv_den = 1.f / s;

    if (D == 128) {
        float4 a0 = make_float4(0.f, 0.f, 0.f, 0.f);
        int e = start;
        for (; e + 2 <= end; e += 2) {
            int s0 = g_csr[e], s1i = g_csr[e + 1];
            float c0 = __expf(lrelu(g_as[s0]  + adn) - m) * inv_den;
            float c1 = __expf(lrelu(g_as[s1i] + adn) - m) * inv_den;
            float4 v0 = ((const float4*)(h + (size_t)s0  * 128))[lane];
            float4 v1 = ((const float4*)(h + (size_t)s1i * 128))[lane];
            a0.x += c0 * v0.x + c1 * v1.x; a0.y += c0 * v0.y + c1 * v1.y;
            a0.z += c0 * v0.z + c1 * v1.z; a0.w += c0 * v0.w + c1 * v1.w;
        }
        if (e < end) {
            int s0 = g_csr[e];
            float c0 = __expf(lrelu(g_as[s0] + adn) - m) * inv_den;
            float4 v0 = ((const float4*)(h + (size_t)s0 * 128))[lane];
            a0.x += c0 * v0.x; a0.y += c0 * v0.y; a0.z += c0 * v0.z; a0.w += c0 * v0.w;
        }
        ((float4*)(out + (size_t)gw * 128))[lane] = a0;
    } else if (D == 64) {
        float2 a = make_float2(0.f, 0.f);
        int e = start;
        for (; e + 2 <= end; e += 2) {
            int s0 = g_csr[e], s1i = g_csr[e + 1];
            float c0 = __expf(lrelu(g_as[s0]  + adn) - m) * inv_den;
            float c1 = __expf(lrelu(g_as[s1i] + adn) - m) * inv_den;
            float2 v0 = ((const float2*)(h + (size_t)s0  * 64))[lane];
            float2 v1 = ((const float2*)(h + (size_t)s1i * 64))[lane];
            a.x += c0 * v0.x + c1 * v1.x;
            a.y += c0 * v0.y + c1 * v1.y;
        }
        if (e < end) {
            int s0 = g_csr[e];
            float c0 = __expf(lrelu(g_as[s0] + adn) - m) * inv_den;
            float2 v0 = ((const float2*)(h + (size_t)s0 * 64))[lane];
            a.x += c0 * v0.x; a.y += c0 * v0.y;
        }
        if (DO_BIAS_ELU) {
            float2 bv = ((const float2*)bias)[lane];
            a.x = elu1(a.x + bv.x); a.y = elu1(a.y + bv.y);
        }
        ((float2*)(out + (size_t)gw * 64))[lane] = a;
    } else { // D == 1
        float a = 0.f;
        for (int e = start + lane; e < end; e += 32) {
            int sn = g_csr[e];
            float c = __expf(lrelu(g_as[sn] + adn) - m) * inv_den;
            a += c * h[sn];
        }
        #pragma unroll
        for (int off = 16; off; off >>= 1) a += __shfl_xor_sync(FULL, a, off);
        if (lane == 0) out[gw] = a + bias[0];
    }
}

// =============================== launcher ======================================
extern "C" void kernel_launch(void* const* d_in, const int* in_sizes, int n_in,
                              void* d_out, int out_size) {
    const float* x  = (const float*)d_in[0];
    const int*   ei = (const int*)d_in[1];
    const float *W1 = (const float*)d_in[2],  *as1 = (const float*)d_in[3],
                *ad1 = (const float*)d_in[4], *b1  = (const float*)d_in[5];
    const float *W2 = (const float*)d_in[6],  *as2 = (const float*)d_in[7],
                *ad2 = (const float*)d_in[8], *b2  = (const float*)d_in[9];
    const float *W3 = (const float*)d_in[10], *as3 = (const float*)d_in[11],
                *ad3 = (const float*)d_in[12], *b3 = (const float*)d_in[13];
    float* out = (float*)d_out;

    float *ph, *po, *pps, *ppd;
    cudaGetSymbolAddress((void**)&ph, g_h);
    cudaGetSymbolAddress((void**)&po, g_o);
    cudaGetSymbolAddress((void**)&pps, g_ps);
    cudaGetSymbolAddress((void**)&ppd, g_pd);

    const int TB = 256;
    const int nodeBlocks  = (Nn + TB - 1) / TB;
    const int warpNodeBlk = (Nn * 32 + TB - 1) / TB;
    const int mRows = (Nn + 127) / 128;

    // ---- CSR build (dst-grouped) ----
    init_cnt<<<nodeBlocks, TB>>>();
    count_k<<<(Ereal + TB - 1) / TB, TB>>>(ei);
    scan_k<<<1, 1024>>>();
    place_k<<<(Etot + TB - 1) / TB, TB>>>(ei);

    // ---- layer 1 (aggregate-then-transform): 128 -> 256 ----
    {
        prep_p<<<1, 256>>>(W1, as1, ad1);                       // p = W1 @ a
        alpha_k<<<warpNodeBlk, TB>>>(x, pps, ppd, Cc);          // alpha = x . p
        agg_k<128, false><<<warpNodeBlk, TB>>>(x, po, nullptr); // agg over x (d=128)
        dim3 grid(D1 / 64, mRows);
        gemm_tc<true><<<grid, 256>>>(po, W1, ph, b1, Nn, Cc, D1); // (+b1, ELU)
    }
    // ---- layer 2: 256 -> 64 ----
    {
        dim3 grid(D2 / 64, mRows);
        gemm_tc<false><<<grid, 256>>>(ph, W2, po, nullptr, Nn, D1, D2);
        alpha_k<<<warpNodeBlk, TB>>>(po, as2, ad2, D2);
        agg_k<64, true><<<warpNodeBlk, TB>>>(po, ph, b2);       // (+b2, ELU)
    }
    // ---- layer 3: 64 -> 1 ----
    {
        matvec_alpha3<<<warpNodeBlk, TB>>>(ph, W3, as3, ad3, po, D2);
        agg_k<1, false><<<warpNodeBlk, TB>>>(po, out, b3);
    }
}

// round 6
// speedup vs baseline: 2.3496x; 1.0816x over previous
#include <cuda_runtime.h>
#include <cuda_bf16.h>
#include <math.h>

#define Nn     50000
#define Cc     128
#define D1     256
#define D2     64
#define Ereal  800000
#define Etot   (Ereal + Nn)
#define FULL   0xFFFFFFFFu
#define NBLK   ((Nn + 1023) / 1024)

// ---------------- scratch ------------------------------------------------------
__device__ float g_h [(size_t)Nn * D1];
__device__ float g_o [(size_t)Nn * D1];
__device__ float g_as[Nn];
__device__ float g_ad[Nn];
__device__ float g_ps[Cc];
__device__ float g_pd[Cc];
__device__ int   g_cnt [Nn];
__device__ int   g_wofs[Nn];
__device__ int   g_rowptr[Nn + 1];
__device__ int   g_csr[Etot];
__device__ int   g_bsum[64];
__device__ int   g_boff[64];

// ---------------- CSR build ----------------------------------------------------
__global__ void init_cnt() {
    int n = blockIdx.x * blockDim.x + threadIdx.x;
    if (n < Nn) g_cnt[n] = 1;                    // self-loop pre-counted
}
__global__ void count_k(const int* __restrict__ ei) {
    int e = blockIdx.x * blockDim.x + threadIdx.x;
    if (e < Ereal) atomicAdd(&g_cnt[ei[Ereal + e]], 1);
}
// multi-block scan: per-block local exclusive scan + block totals
__global__ void scan_blocks() {
    __shared__ int wsum[32];
    int tid = threadIdx.x, lane = tid & 31, wid = tid >> 5;
    int i = blockIdx.x * 1024 + tid;
    int v = (i < Nn) ? g_cnt[i] : 0;
    int p = v;
    #pragma unroll
    for (int o = 1; o < 32; o <<= 1) {
        int t = __shfl_up_sync(FULL, p, o);
        if (lane >= o) p += t;
    }
    if (lane == 31) wsum[wid] = p;
    __syncthreads();
    if (wid == 0) {
        int w = wsum[lane];
        #pragma unroll
        for (int o = 1; o < 32; o <<= 1) {
            int t = __shfl_up_sync(FULL, w, o);
            if (lane >= o) w += t;
        }
        wsum[lane] = w;
    }
    __syncthreads();
    int excl = (wid ? wsum[wid - 1] : 0) + p - v;
    if (i < Nn) g_rowptr[i] = excl;
    if (tid == 0) g_bsum[blockIdx.x] = wsum[31];
}
__global__ void scan_tops() {
    __shared__ int sb[64];
    int t = threadIdx.x;
    int v = (t < NBLK) ? g_bsum[t] : 0;
    sb[t] = v;
    __syncthreads();
    #pragma unroll
    for (int o = 1; o < 64; o <<= 1) {
        int x = (t >= o) ? sb[t - o] : 0;
        __syncthreads();
        sb[t] += x;
        __syncthreads();
    }
    if (t < NBLK) g_boff[t] = sb[t] - v;   // exclusive
}
__global__ void scan_add() {
    int i = blockIdx.x * blockDim.x + threadIdx.x;
    if (i < Nn) {
        int val = g_rowptr[i] + g_boff[i >> 10];
        g_rowptr[i] = val;
        g_wofs[i]   = val;
    }
    if (i == 0) g_rowptr[Nn] = Etot;
}
__global__ void place_k(const int* __restrict__ ei) {
    int e = blockIdx.x * blockDim.x + threadIdx.x;
    if (e >= Etot) return;
    int s, d;
    if (e < Ereal) { s = ei[e]; d = ei[Ereal + e]; } else { s = d = e - Ereal; }
    int pos = atomicAdd(&g_wofs[d], 1);
    g_csr[pos] = s;
}

// ---------------- fold attention vectors through W1: p = W1 @ a ----------------
__global__ void prep_p(const float* __restrict__ W1, const float* __restrict__ as1,
                       const float* __restrict__ ad1) {
    int t = threadIdx.x;            // 256 threads
    const float* a = (t < Cc) ? as1 : ad1;
    int i = t & (Cc - 1);
    float s = 0.f;
    const float* row = W1 + (size_t)i * D1;
    for (int j = 0; j < D1; j++) s += row[j] * a[j];
    if (t < Cc) g_ps[i] = s; else g_pd[i] = s;
}

// ================= split-tf32 tensor-core GEMM (register-prefetch) ==============
#define GSTRIDE 20

__device__ __forceinline__ unsigned tf32_hi(float v) {
    return __float_as_uint(v) & 0xFFFFE000u;
}
__device__ __forceinline__ void mma_tf32(float (&c)[4], const unsigned* a, const unsigned* b) {
    asm volatile(
        "mma.sync.aligned.m16n8k8.row.col.f32.tf32.tf32.f32 "
        "{%0,%1,%2,%3}, {%4,%5,%6,%7}, {%8,%9}, {%0,%1,%2,%3};\n"
        : "+f"(c[0]), "+f"(c[1]), "+f"(c[2]), "+f"(c[3])
        : "r"(a[0]), "r"(a[1]), "r"(a[2]), "r"(a[3]), "r"(b[0]), "r"(b[1]));
}
__device__ __forceinline__ float elu1(float v) { return v > 0.f ? v : expm1f(v); }

template<bool BIAS_ELU>
__global__ void __launch_bounds__(256) gemm_tc(const float* __restrict__ A,
                                               const float* __restrict__ B,
                                               float* __restrict__ C,
                                               const float* __restrict__ bias,
                                               int M, int K, int N) {
    __shared__ unsigned AsH[128 * GSTRIDE];
    __shared__ unsigned AsL[128 * GSTRIDE];
    __shared__ unsigned BsH[64 * GSTRIDE];   // transposed: Bs[n][k]
    __shared__ unsigned BsL[64 * GSTRIDE];

    const int br = blockIdx.y * 128;
    const int bn = blockIdx.x * 64;
    const int tid = threadIdx.x;
    const int lane = tid & 31;
    const int warp = tid >> 5;
    const int wm = (warp >> 1) * 32;
    const int wn = (warp & 1) * 32;

    float acc[2][4][4];
    #pragma unroll
    for (int m = 0; m < 2; m++)
        #pragma unroll
        for (int n = 0; n < 4; n++)
            #pragma unroll
            for (int r = 0; r < 4; r++) acc[m][n][r] = 0.f;

    const int q = lane >> 2;
    const int rr = lane & 3;

    // per-thread load coords
    const int aRow0 = tid >> 2,        aC0 = (tid & 3) * 4;         // t=0
    const int aRow1 = (tid + 256) >> 2, aC1 = aC0;                  // t=1
    const int bRow  = tid >> 4,        bN4 = (tid & 15) * 4;

    float4 aR[2], bR;
    // prologue load k0 = 0
    aR[0] = (br + aRow0 < M) ? *(const float4*)(A + (size_t)(br + aRow0) * K + aC0)
                             : make_float4(0.f, 0.f, 0.f, 0.f);
    aR[1] = (br + aRow1 < M) ? *(const float4*)(A + (size_t)(br + aRow1) * K + aC1)
                             : make_float4(0.f, 0.f, 0.f, 0.f);
    bR = *(const float4*)(B + (size_t)bRow * N + bn + bN4);

    for (int k0 = 0; k0 < K; k0 += 16) {
        // ---- store staged regs to smem (hi/lo split) ----
        #pragma unroll
        for (int t = 0; t < 2; t++) {
            int row = t ? aRow1 : aRow0;
            float4 v = aR[t];
            unsigned h0 = tf32_hi(v.x), h1 = tf32_hi(v.y), h2 = tf32_hi(v.z), h3 = tf32_hi(v.w);
            int o = row * GSTRIDE + aC0;
            AsH[o + 0] = h0; AsH[o + 1] = h1; AsH[o + 2] = h2; AsH[o + 3] = h3;
            AsL[o + 0] = tf32_hi(v.x - __uint_as_float(h0));
            AsL[o + 1] = tf32_hi(v.y - __uint_as_float(h1));
            AsL[o + 2] = tf32_hi(v.z - __uint_as_float(h2));
            AsL[o + 3] = tf32_hi(v.w - __uint_as_float(h3));
        }
        {
            float4 v = bR;
            unsigned h0 = tf32_hi(v.x), h1 = tf32_hi(v.y), h2 = tf32_hi(v.z), h3 = tf32_hi(v.w);
            BsH[(bN4 + 0) * GSTRIDE + bRow] = h0;
            BsH[(bN4 + 1) * GSTRIDE + bRow] = h1;
            BsH[(bN4 + 2) * GSTRIDE + bRow] = h2;
            BsH[(bN4 + 3) * GSTRIDE + bRow] = h3;
            BsL[(bN4 + 0) * GSTRIDE + bRow] = tf32_hi(v.x - __uint_as_float(h0));
            BsL[(bN4 + 1) * GSTRIDE + bRow] = tf32_hi(v.y - __uint_as_float(h1));
            BsL[(bN4 + 2) * GSTRIDE + bRow] = tf32_hi(v.z - __uint_as_float(h2));
            BsL[(bN4 + 3) * GSTRIDE + bRow] = tf32_hi(v.w - __uint_as_float(h3));
        }
        __syncthreads();

        // ---- prefetch next tile into registers (latency hidden by MMAs) ----
        if (k0 + 16 < K) {
            int kn = k0 + 16;
            aR[0] = (br + aRow0 < M) ? *(const float4*)(A + (size_t)(br + aRow0) * K + kn + aC0)
                                     : make_float4(0.f, 0.f, 0.f, 0.f);
            aR[1] = (br + aRow1 < M) ? *(const float4*)(A + (size_t)(br + aRow1) * K + kn + aC1)
                                     : make_float4(0.f, 0.f, 0.f, 0.f);
            bR = *(const float4*)(B + (size_t)(kn + bRow) * N + bn + bN4);
        }

        #pragma unroll
        for (int kk = 0; kk < 16; kk += 8) {
            unsigned ah[2][4], al[2][4], bh[4][2], bl[4][2];
            #pragma unroll
            for (int m = 0; m < 2; m++) {
                int rbase = (wm + m * 16 + q) * GSTRIDE + kk + rr;
                ah[m][0] = AsH[rbase];
                ah[m][1] = AsH[rbase + 8 * GSTRIDE];
                ah[m][2] = AsH[rbase + 4];
                ah[m][3] = AsH[rbase + 8 * GSTRIDE + 4];
                al[m][0] = AsL[rbase];
                al[m][1] = AsL[rbase + 8 * GSTRIDE];
                al[m][2] = AsL[rbase + 4];
                al[m][3] = AsL[rbase + 8 * GSTRIDE + 4];
            }
            #pragma unroll
            for (int n = 0; n < 4; n++) {
                int nbase = (wn + n * 8 + q) * GSTRIDE + kk + rr;
                bh[n][0] = BsH[nbase];
                bh[n][1] = BsH[nbase + 4];
                bl[n][0] = BsL[nbase];
                bl[n][1] = BsL[nbase + 4];
            }
            #pragma unroll
            for (int m = 0; m < 2; m++)
                #pragma unroll
                for (int n = 0; n < 4; n++) {
                    mma_tf32(acc[m][n], ah[m], bh[n]);
                    mma_tf32(acc[m][n], ah[m], bl[n]);
                    mma_tf32(acc[m][n], al[m], bh[n]);
                }
        }
        __syncthreads();
    }

    #pragma unroll
    for (int m = 0; m < 2; m++) {
        int row0 = br + wm + m * 16 + q;
        #pragma unroll
        for (int n = 0; n < 4; n++) {
            int col = bn + wn + n * 8 + rr * 2;
            float2 v0 = make_float2(acc[m][n][0], acc[m][n][1]);
            float2 v1 = make_float2(acc[m][n][2], acc[m][n][3]);
            if (BIAS_ELU) {
                float b0 = bias[col], b1v = bias[col + 1];
                v0.x = elu1(v0.x + b0); v0.y = elu1(v0.y + b1v);
                v1.x = elu1(v1.x + b0); v1.y = elu1(v1.y + b1v);
            }
            if (row0 < M)
                *(float2*)(C + (size_t)row0 * N + col) = v0;
            if (row0 + 8 < M)
                *(float2*)(C + (size_t)(row0 + 8) * N + col) = v1;
        }
    }
}

// ---------------- per-node attention dots --------------------------------------
__global__ void alpha_k(const float* __restrict__ h, const float* __restrict__ av,
                        const float* __restrict__ bv, int d) {
    int gw = (blockIdx.x * blockDim.x + threadIdx.x) >> 5;
    int lane = threadIdx.x & 31;
    if (gw >= Nn) return;
    float s1 = 0.f, s2 = 0.f;
    for (int j = lane; j < d; j += 32) {
        float v = h[(size_t)gw * d + j];
        s1 += v * av[j];
        s2 += v * bv[j];
    }
    #pragma unroll
    for (int o = 16; o; o >>= 1) {
        s1 += __shfl_xor_sync(FULL, s1, o);
        s2 += __shfl_xor_sync(FULL, s2, o);
    }
    if (lane == 0) { g_as[gw] = s1; g_ad[gw] = s2; }
}

// ---------------- layer 3 matvec + alpha scalars --------------------------------
__global__ void matvec_alpha3(const float* __restrict__ A, const float* __restrict__ w,
                              const float* __restrict__ as3, const float* __restrict__ ad3,
                              float* __restrict__ y, int k) {
    int gw = (blockIdx.x * blockDim.x + threadIdx.x) >> 5;
    int lane = threadIdx.x & 31;
    if (gw >= Nn) return;
    float s = 0.f;
    for (int j = lane; j < k; j += 32) s += A[(size_t)gw * k + j] * w[j];
    #pragma unroll
    for (int o = 16; o; o >>= 1) s += __shfl_xor_sync(FULL, s, o);
    if (lane == 0) {
        y[gw] = s;
        g_as[gw] = s * as3[0];
        g_ad[gw] = s * ad3[0];
    }
}

// ---------------- fused softmax + aggregate (warp per node) --------------------
__device__ __forceinline__ float lrelu(float l) { return l > 0.f ? l : 0.2f * l; }

template<int D, bool DO_BIAS_ELU>
__global__ void agg_k(const float* __restrict__ h, float* __restrict__ out,
                      const float* __restrict__ bias) {
    int gw   = (blockIdx.x * blockDim.x + threadIdx.x) >> 5;
    int lane = threadIdx.x & 31;
    if (gw >= Nn) return;
    const int start = g_rowptr[gw];
    const int end   = g_rowptr[gw + 1];
    const int deg   = end - start;
    const float adn = g_ad[gw];

    // ---- phase 1: logits in registers (lane covers edges start+lane, +32) ----
    float l0 = -3.0e38f, l1 = -3.0e38f;
    float m = -3.0e38f, s = 0.f;
    {
        int e = start + lane;
        if (e < end) { l0 = lrelu(g_as[g_csr[e]] + adn); m = l0; s = 1.f; }
        if (e + 32 < end) {
            l1 = lrelu(g_as[g_csr[e + 32]] + adn);
            float mn = fmaxf(m, l1);
            s = s * __expf(m - mn) + __expf(l1 - mn);
            m = mn;
        }
        for (int e2 = e + 64; e2 < end; e2 += 32) {   // overflow (deg > 64): ~never
            float l = lrelu(g_as[g_csr[e2]] + adn);
            float mn = fmaxf(m, l);
            s = s * __expf(m - mn) + __expf(l - mn);
            m = mn;
        }
    }
    #pragma unroll
    for (int off = 16; off; off >>= 1) {
        float mo = __shfl_xor_sync(FULL, m, off);
        float so = __shfl_xor_sync(FULL, s, off);
        float mn = fmaxf(m, mo);
        s = s * __expf(m - mn) + so * __expf(mo - mn);
        m = mn;
    }
    const float inv_den = 1.f / s;
    // per-lane coefficients (underflow to 0 for invalid slots; never read anyway)
    const float c0 = __expf(l0 - m) * inv_den;
    const float c1 = __expf(l1 - m) * inv_den;

    const int nreg = deg < 64 ? deg : 64;

    if (D == 128) {
        float4 a0 = make_float4(0.f, 0.f, 0.f, 0.f);
        int j = 0;
        for (; j + 4 <= nreg; j += 4) {
            int eb = start + j;
            int s0 = g_csr[eb], s1i = g_csr[eb + 1], s2i = g_csr[eb + 2], s3i = g_csr[eb + 3];
            float cc = (j & 32) ? c1 : c0;
            float ca = __shfl_sync(FULL, cc, j & 31);
            float cb = __shfl_sync(FULL, cc, (j & 31) + 1);
            float cg = __shfl_sync(FULL, cc, (j & 31) + 2);
            float cd = __shfl_sync(FULL, cc, (j & 31) + 3);
            float4 r0 = ((const float4*)(h + (size_t)s0  * 128))[lane];
            float4 r1 = ((const float4*)(h + (size_t)s1i * 128))[lane];
            float4 r2 = ((const float4*)(h + (size_t)s2i * 128))[lane];
            float4 r3 = ((const float4*)(h + (size_t)s3i * 128))[lane];
            a0.x += ca * r0.x + cb * r1.x + cg * r2.x + cd * r3.x;
            a0.y += ca * r0.y + cb * r1.y + cg * r2.y + cd * r3.y;
            a0.z += ca * r0.z + cb * r1.z + cg * r2.z + cd * r3.z;
            a0.w += ca * r0.w + cb * r1.w + cg * r2.w + cd * r3.w;
        }
        for (; j < nreg; j++) {
            float cc = (j & 32) ? c1 : c0;
            float ca = __shfl_sync(FULL, cc, j & 31);
            float4 r0 = ((const float4*)(h + (size_t)g_csr[start + j] * 128))[lane];
            a0.x += ca * r0.x; a0.y += ca * r0.y; a0.z += ca * r0.z; a0.w += ca * r0.w;
        }
        for (int e2 = start + 64; e2 < end; e2++) {   // overflow
            float c = __expf(lrelu(g_as[g_csr[e2]] + adn) - m) * inv_den;
            float4 r0 = ((const float4*)(h + (size_t)g_csr[e2] * 128))[lane];
            a0.x += c * r0.x; a0.y += c * r0.y; a0.z += c * r0.z; a0.w += c * r0.w;
        }
        ((float4*)(out + (size_t)gw * 128))[lane] = a0;
    } else if (D == 64) {
        float2 a = make_float2(0.f, 0.f);
        int j = 0;
        for (; j + 4 <= nreg; j += 4) {
            int eb = start + j;
            int s0 = g_csr[eb], s1i = g_csr[eb + 1], s2i = g_csr[eb + 2], s3i = g_csr[eb + 3];
            float cc = (j & 32) ? c1 : c0;
            float ca = __shfl_sync(FULL, cc, j & 31);
            float cb = __shfl_sync(FULL, cc, (j & 31) + 1);
            float cg = __shfl_sync(FULL, cc, (j & 31) + 2);
            float cd = __shfl_sync(FULL, cc, (j & 31) + 3);
            float2 r0 = ((const float2*)(h + (size_t)s0  * 64))[lane];
            float2 r1 = ((const float2*)(h + (size_t)s1i * 64))[lane];
            float2 r2 = ((const float2*)(h + (size_t)s2i * 64))[lane];
            float2 r3 = ((const float2*)(h + (size_t)s3i * 64))[lane];
            a.x += ca * r0.x + cb * r1.x + cg * r2.x + cd * r3.x;
            a.y += ca * r0.y + cb * r1.y + cg * r2.y + cd * r3.y;
        }
        for (; j < nreg; j++) {
            float cc = (j & 32) ? c1 : c0;
            float ca = __shfl_sync(FULL, cc, j & 31);
            float2 r0 = ((const float2*)(h + (size_t)g_csr[start + j] * 64))[lane];
            a.x += ca * r0.x; a.y += ca * r0.y;
        }
        for (int e2 = start + 64; e2 < end; e2++) {
            float c = __expf(lrelu(g_as[g_csr[e2]] + adn) - m) * inv_den;
            float2 r0 = ((const float2*)(h + (size_t)g_csr[e2] * 64))[lane];
            a.x += c * r0.x; a.y += c * r0.y;
        }
        if (DO_BIAS_ELU) {
            float2 bv = ((const float2*)bias)[lane];
            a.x = elu1(a.x + bv.x); a.y = elu1(a.y + bv.y);
        }
        ((float2*)(out + (size_t)gw * 64))[lane] = a;
    } else { // D == 1
        float a = 0.f;
        for (int e = start + lane; e < end; e += 32) {
            int sn = g_csr[e];
            float c = __expf(lrelu(g_as[sn] + adn) - m) * inv_den;
            a += c * h[sn];
        }
        #pragma unroll
        for (int off = 16; off; off >>= 1) a += __shfl_xor_sync(FULL, a, off);
        if (lane == 0) out[gw] = a + bias[0];
    }
}

// =============================== launcher ======================================
extern "C" void kernel_launch(void* const* d_in, const int* in_sizes, int n_in,
                              void* d_out, int out_size) {
    const float* x  = (const float*)d_in[0];
    const int*   ei = (const int*)d_in[1];
    const float *W1 = (const float*)d_in[2],  *as1 = (const float*)d_in[3],
                *ad1 = (const float*)d_in[4], *b1  = (const float*)d_in[5];
    const float *W2 = (const float*)d_in[6],  *as2 = (const float*)d_in[7],
                *ad2 = (const float*)d_in[8], *b2  = (const float*)d_in[9];
    const float *W3 = (const float*)d_in[10], *as3 = (const float*)d_in[11],
                *ad3 = (const float*)d_in[12], *b3 = (const float*)d_in[13];
    float* out = (float*)d_out;

    float *ph, *po, *pps, *ppd;
    cudaGetSymbolAddress((void**)&ph, g_h);
    cudaGetSymbolAddress((void**)&po, g_o);
    cudaGetSymbolAddress((void**)&pps, g_ps);
    cudaGetSymbolAddress((void**)&ppd, g_pd);

    const int TB = 256;
    const int nodeBlocks  = (Nn + TB - 1) / TB;
    const int warpNodeBlk = (Nn * 32 + TB - 1) / TB;
    const int mRows = (Nn + 127) / 128;

    // ---- CSR build (dst-grouped) ----
    init_cnt<<<nodeBlocks, TB>>>();
    count_k<<<(Ereal + TB - 1) / TB, TB>>>(ei);
    scan_blocks<<<NBLK, 1024>>>();
    scan_tops<<<1, 64>>>();
    scan_add<<<(Nn + 1023) / 1024, 1024>>>();
    place_k<<<(Etot + TB - 1) / TB, TB>>>(ei);

    // ---- layer 1 (aggregate-then-transform): 128 -> 256 ----
    {
        prep_p<<<1, 256>>>(W1, as1, ad1);                       // p = W1 @ a
        alpha_k<<<warpNodeBlk, TB>>>(x, pps, ppd, Cc);          // alpha = x . p
        agg_k<128, false><<<warpNodeBlk, TB>>>(x, po, nullptr); // agg over x (d=128)
        dim3 grid(D1 / 64, mRows);
        gemm_tc<true><<<grid, 256>>>(po, W1, ph, b1, Nn, Cc, D1); // (+b1, ELU)
    }
    // ---- layer 2: 256 -> 64 ----
    {
        dim3 grid(D2 / 64, mRows);
        gemm_tc<false><<<grid, 256>>>(ph, W2, po, nullptr, Nn, D1, D2);
        alpha_k<<<warpNodeBlk, TB>>>(po, as2, ad2, D2);
        agg_k<64, true><<<warpNodeBlk, TB>>>(po, ph, b2);       // (+b2, ELU)
    }
    // ---- layer 3: 64 -> 1 ----
    {
        matvec_alpha3<<<warpNodeBlk, TB>>>(ph, W3, as3, ad3, po, D2);
        agg_k<1, false><<<warpNodeBlk, TB>>>(po, out, b3);
    }
}

// round 7
// speedup vs baseline: 2.3961x; 1.0198x over previous
#include <cuda_runtime.h>
#include <cuda_bf16.h>
#include <math.h>

#define Nn     50000
#define Cc     128
#define D1     256
#define D2     64
#define Ereal  800000
#define Etot   (Ereal + Nn)
#define FULL   0xFFFFFFFFu
#define NBLK   ((Nn + 1023) / 1024)

// ---------------- scratch ------------------------------------------------------
__device__ float g_h [(size_t)Nn * D1];
__device__ float g_o [(size_t)Nn * D1];
__device__ float g_as[Nn];
__device__ float g_ad[Nn];
__device__ float g_as3[Nn];
__device__ float g_ad3[Nn];
__device__ float g_ps[Cc];
__device__ float g_pd[Cc];
__device__ int   g_cnt [Nn];
__device__ int   g_wofs[Nn];
__device__ int   g_rowptr[Nn + 1];
__device__ int   g_csr[Etot];
__device__ int   g_bsum[64];
__device__ int   g_boff[64];

// ---------------- init counters + fold attention vecs through W1 ---------------
__global__ void init_prep(const float* __restrict__ W1, const float* __restrict__ as1,
                          const float* __restrict__ ad1, int nodeBlocks) {
    if ((int)blockIdx.x < nodeBlocks) {
        int n = blockIdx.x * blockDim.x + threadIdx.x;
        if (n < Nn) g_cnt[n] = 1;                    // self-loop pre-counted
    } else {
        int t = threadIdx.x;                          // 256 threads: p = W1 @ a
        const float* a = (t < Cc) ? as1 : ad1;
        int i = t & (Cc - 1);
        float s = 0.f;
        const float* row = W1 + (size_t)i * D1;
        for (int j = 0; j < D1; j++) s += row[j] * a[j];
        if (t < Cc) g_ps[i] = s; else g_pd[i] = s;
    }
}
__global__ void count_k(const int* __restrict__ ei) {
    int e = blockIdx.x * blockDim.x + threadIdx.x;
    if (e < Ereal) atomicAdd(&g_cnt[ei[Ereal + e]], 1);
}
__global__ void scan_blocks() {
    __shared__ int wsum[32];
    int tid = threadIdx.x, lane = tid & 31, wid = tid >> 5;
    int i = blockIdx.x * 1024 + tid;
    int v = (i < Nn) ? g_cnt[i] : 0;
    int p = v;
    #pragma unroll
    for (int o = 1; o < 32; o <<= 1) {
        int t = __shfl_up_sync(FULL, p, o);
        if (lane >= o) p += t;
    }
    if (lane == 31) wsum[wid] = p;
    __syncthreads();
    if (wid == 0) {
        int w = wsum[lane];
        #pragma unroll
        for (int o = 1; o < 32; o <<= 1) {
            int t = __shfl_up_sync(FULL, w, o);
            if (lane >= o) w += t;
        }
        wsum[lane] = w;
    }
    __syncthreads();
    int excl = (wid ? wsum[wid - 1] : 0) + p - v;
    if (i < Nn) g_rowptr[i] = excl;
    if (tid == 0) g_bsum[blockIdx.x] = wsum[31];
}
__global__ void scan_tops() {
    __shared__ int sb[64];
    int t = threadIdx.x;
    int v = (t < NBLK) ? g_bsum[t] : 0;
    sb[t] = v;
    __syncthreads();
    #pragma unroll
    for (int o = 1; o < 64; o <<= 1) {
        int x = (t >= o) ? sb[t - o] : 0;
        __syncthreads();
        sb[t] += x;
        __syncthreads();
    }
    if (t < NBLK) g_boff[t] = sb[t] - v;   // exclusive
}
__global__ void scan_add() {
    int i = blockIdx.x * blockDim.x + threadIdx.x;
    if (i < Nn) {
        int val = g_rowptr[i] + g_boff[i >> 10];
        g_rowptr[i] = val;
        g_wofs[i]   = val;
    }
    if (i == 0) g_rowptr[Nn] = Etot;
}
__global__ void place_k(const int* __restrict__ ei) {
    int e = blockIdx.x * blockDim.x + threadIdx.x;
    if (e >= Etot) return;
    int s, d;
    if (e < Ereal) { s = ei[e]; d = ei[Ereal + e]; } else { s = d = e - Ereal; }
    int pos = atomicAdd(&g_wofs[d], 1);
    g_csr[pos] = s;
}

// ================= split-tf32 tensor-core GEMM (register-prefetch) ==============
#define GSTRIDE 20

__device__ __forceinline__ unsigned tf32_hi(float v) {
    return __float_as_uint(v) & 0xFFFFE000u;
}
__device__ __forceinline__ void mma_tf32(float (&c)[4], const unsigned* a, const unsigned* b) {
    asm volatile(
        "mma.sync.aligned.m16n8k8.row.col.f32.tf32.tf32.f32 "
        "{%0,%1,%2,%3}, {%4,%5,%6,%7}, {%8,%9}, {%0,%1,%2,%3};\n"
        : "+f"(c[0]), "+f"(c[1]), "+f"(c[2]), "+f"(c[3])
        : "r"(a[0]), "r"(a[1]), "r"(a[2]), "r"(a[3]), "r"(b[0]), "r"(b[1]));
}
__device__ __forceinline__ float elu1(float v) { return v > 0.f ? v : expm1f(v); }

// BIAS_ELU: apply bias+ELU to C. ALPHA: also emit g_as/g_ad = C-row . av/bv.
template<bool BIAS_ELU, bool ALPHA>
__global__ void __launch_bounds__(256) gemm_tc(const float* __restrict__ A,
                                               const float* __restrict__ B,
                                               float* __restrict__ C,
                                               const float* __restrict__ bias,
                                               const float* __restrict__ av,
                                               const float* __restrict__ bv,
                                               int M, int K, int N) {
    __shared__ unsigned AsH[128 * GSTRIDE];
    __shared__ unsigned AsL[128 * GSTRIDE];
    __shared__ unsigned BsH[64 * GSTRIDE];   // transposed: Bs[n][k]
    __shared__ unsigned BsL[64 * GSTRIDE];

    const int br = blockIdx.y * 128;
    const int bn = blockIdx.x * 64;
    const int tid = threadIdx.x;
    const int lane = tid & 31;
    const int warp = tid >> 5;
    const int wm = (warp >> 1) * 32;
    const int wn = (warp & 1) * 32;

    float acc[2][4][4];
    #pragma unroll
    for (int m = 0; m < 2; m++)
        #pragma unroll
        for (int n = 0; n < 4; n++)
            #pragma unroll
            for (int r = 0; r < 4; r++) acc[m][n][r] = 0.f;

    const int q = lane >> 2;
    const int rr = lane & 3;

    const int aRow0 = tid >> 2,         aC0 = (tid & 3) * 4;
    const int aRow1 = (tid + 256) >> 2, aC1 = aC0;
    const int bRow  = tid >> 4,         bN4 = (tid & 15) * 4;

    float4 aR[2], bR;
    aR[0] = (br + aRow0 < M) ? *(const float4*)(A + (size_t)(br + aRow0) * K + aC0)
                             : make_float4(0.f, 0.f, 0.f, 0.f);
    aR[1] = (br + aRow1 < M) ? *(const float4*)(A + (size_t)(br + aRow1) * K + aC1)
                             : make_float4(0.f, 0.f, 0.f, 0.f);
    bR = *(const float4*)(B + (size_t)bRow * N + bn + bN4);

    for (int k0 = 0; k0 < K; k0 += 16) {
        #pragma unroll
        for (int t = 0; t < 2; t++) {
            int row = t ? aRow1 : aRow0;
            float4 v = aR[t];
            unsigned h0 = tf32_hi(v.x), h1 = tf32_hi(v.y), h2 = tf32_hi(v.z), h3 = tf32_hi(v.w);
            int o = row * GSTRIDE + aC0;
            AsH[o + 0] = h0; AsH[o + 1] = h1; AsH[o + 2] = h2; AsH[o + 3] = h3;
            AsL[o + 0] = tf32_hi(v.x - __uint_as_float(h0));
            AsL[o + 1] = tf32_hi(v.y - __uint_as_float(h1));
            AsL[o + 2] = tf32_hi(v.z - __uint_as_float(h2));
            AsL[o + 3] = tf32_hi(v.w - __uint_as_float(h3));
        }
        {
            float4 v = bR;
            unsigned h0 = tf32_hi(v.x), h1 = tf32_hi(v.y), h2 = tf32_hi(v.z), h3 = tf32_hi(v.w);
            BsH[(bN4 + 0) * GSTRIDE + bRow] = h0;
            BsH[(bN4 + 1) * GSTRIDE + bRow] = h1;
            BsH[(bN4 + 2) * GSTRIDE + bRow] = h2;
            BsH[(bN4 + 3) * GSTRIDE + bRow] = h3;
            BsL[(bN4 + 0) * GSTRIDE + bRow] = tf32_hi(v.x - __uint_as_float(h0));
            BsL[(bN4 + 1) * GSTRIDE + bRow] = tf32_hi(v.y - __uint_as_float(h1));
            BsL[(bN4 + 2) * GSTRIDE + bRow] = tf32_hi(v.z - __uint_as_float(h2));
            BsL[(bN4 + 3) * GSTRIDE + bRow] = tf32_hi(v.w - __uint_as_float(h3));
        }
        __syncthreads();

        if (k0 + 16 < K) {
            int kn = k0 + 16;
            aR[0] = (br + aRow0 < M) ? *(const float4*)(A + (size_t)(br + aRow0) * K + kn + aC0)
                                     : make_float4(0.f, 0.f, 0.f, 0.f);
            aR[1] = (br + aRow1 < M) ? *(const float4*)(A + (size_t)(br + aRow1) * K + kn + aC1)
                                     : make_float4(0.f, 0.f, 0.f, 0.f);
            bR = *(const float4*)(B + (size_t)(kn + bRow) * N + bn + bN4);
        }

        #pragma unroll
        for (int kk = 0; kk < 16; kk += 8) {
            unsigned ah[2][4], al[2][4], bh[4][2], bl[4][2];
            #pragma unroll
            for (int m = 0; m < 2; m++) {
                int rbase = (wm + m * 16 + q) * GSTRIDE + kk + rr;
                ah[m][0] = AsH[rbase];
                ah[m][1] = AsH[rbase + 8 * GSTRIDE];
                ah[m][2] = AsH[rbase + 4];
                ah[m][3] = AsH[rbase + 8 * GSTRIDE + 4];
                al[m][0] = AsL[rbase];
                al[m][1] = AsL[rbase + 8 * GSTRIDE];
                al[m][2] = AsL[rbase + 4];
                al[m][3] = AsL[rbase + 8 * GSTRIDE + 4];
            }
            #pragma unroll
            for (int n = 0; n < 4; n++) {
                int nbase = (wn + n * 8 + q) * GSTRIDE + kk + rr;
                bh[n][0] = BsH[nbase];
                bh[n][1] = BsH[nbase + 4];
                bl[n][0] = BsL[nbase];
                bl[n][1] = BsL[nbase + 4];
            }
            #pragma unroll
            for (int m = 0; m < 2; m++)
                #pragma unroll
                for (int n = 0; n < 4; n++) {
                    mma_tf32(acc[m][n], ah[m], bh[n]);
                    mma_tf32(acc[m][n], ah[m], bl[n]);
                    mma_tf32(acc[m][n], al[m], bh[n]);
                }
        }
        __syncthreads();
    }

    #pragma unroll
    for (int m = 0; m < 2; m++) {
        int row0 = br + wm + m * 16 + q;
        #pragma unroll
        for (int n = 0; n < 4; n++) {
            int col = bn + wn + n * 8 + rr * 2;
            float2 v0 = make_float2(acc[m][n][0], acc[m][n][1]);
            float2 v1 = make_float2(acc[m][n][2], acc[m][n][3]);
            if (BIAS_ELU) {
                float b0 = bias[col], b1v = bias[col + 1];
                v0.x = elu1(v0.x + b0); v0.y = elu1(v0.y + b1v);
                v1.x = elu1(v1.x + b0); v1.y = elu1(v1.y + b1v);
            }
            if (row0 < M)
                *(float2*)(C + (size_t)row0 * N + col) = v0;
            if (row0 + 8 < M)
                *(float2*)(C + (size_t)(row0 + 8) * N + col) = v1;
        }
    }

    if (ALPHA) {
        // block covers full row width (N == 64, single bn). Reduce per-row dots.
        float* sAs = (float*)AsH;          // reuse smem
        float* sAd = sAs + 128;
        if (tid < 128) { sAs[tid] = 0.f; sAd[tid] = 0.f; }
        __syncthreads();
        #pragma unroll
        for (int m = 0; m < 2; m++) {
            float pa = 0.f, pd = 0.f, qa = 0.f, qd = 0.f;
            #pragma unroll
            for (int n = 0; n < 4; n++) {
                int col = wn + n * 8 + rr * 2;
                float a0 = av[col], a1 = av[col + 1];
                float d0 = bv[col], d1 = bv[col + 1];
                pa += acc[m][n][0] * a0 + acc[m][n][1] * a1;
                pd += acc[m][n][0] * d0 + acc[m][n][1] * d1;
                qa += acc[m][n][2] * a0 + acc[m][n][3] * a1;
                qd += acc[m][n][2] * d0 + acc[m][n][3] * d1;
            }
            int r = wm + m * 16 + q;
            atomicAdd(&sAs[r], pa);     atomicAdd(&sAd[r], pd);
            atomicAdd(&sAs[r + 8], qa); atomicAdd(&sAd[r + 8], qd);
        }
        __syncthreads();
        if (tid < 128 && br + tid < M) {
            g_as[br + tid] = sAs[tid];
            g_ad[br + tid] = sAd[tid];
        }
    }
}

// ---------------- per-node attention dots (layer 1 on x) -----------------------
__global__ void alpha_k(const float* __restrict__ h, const float* __restrict__ av,
                        const float* __restrict__ bv, int d) {
    int gw = (blockIdx.x * blockDim.x + threadIdx.x) >> 5;
    int lane = threadIdx.x & 31;
    if (gw >= Nn) return;
    float s1 = 0.f, s2 = 0.f;
    for (int j = lane; j < d; j += 32) {
        float v = h[(size_t)gw * d + j];
        s1 += v * av[j];
        s2 += v * bv[j];
    }
    #pragma unroll
    for (int o = 16; o; o >>= 1) {
        s1 += __shfl_xor_sync(FULL, s1, o);
        s2 += __shfl_xor_sync(FULL, s2, o);
    }
    if (lane == 0) { g_as[gw] = s1; g_ad[gw] = s2; }
}

// ---------------- fused softmax + aggregate (warp per node) --------------------
// D=128: plain aggregate (layer 1, pre-GEMM). D=64: bias+ELU then fused y=h.W3,
// emitting y and g_as3/g_ad3 (layer 2+3 prep). D=1: final output (reads g_as3).
__device__ __forceinline__ float lrelu(float l) { return l > 0.f ? l : 0.2f * l; }

template<int D>
__global__ void agg_k(const float* __restrict__ h, float* __restrict__ out,
                      const float* __restrict__ bias,
                      const float* __restrict__ W3,
                      const float* __restrict__ as3,
                      const float* __restrict__ ad3) {
    int gw   = (blockIdx.x * blockDim.x + threadIdx.x) >> 5;
    int lane = threadIdx.x & 31;
    if (gw >= Nn) return;
    const int start = g_rowptr[gw];
    const int end   = g_rowptr[gw + 1];
    const int deg   = end - start;
    const float adn = (D == 1) ? g_ad3[gw] : g_ad[gw];
    const float* asrc = (D == 1) ? g_as3 : g_as;

    // ---- phase 1: logits + indices in registers ----
    int i0 = 0, i1 = 0;
    float l0 = -3.0e38f, l1 = -3.0e38f;
    float m = -3.0e38f, s = 0.f;
    {
        int e = start + lane;
        if (e < end) { i0 = g_csr[e]; l0 = lrelu(asrc[i0] + adn); m = l0; s = 1.f; }
        if (e + 32 < end) {
            i1 = g_csr[e + 32];
            l1 = lrelu(asrc[i1] + adn);
            float mn = fmaxf(m, l1);
            s = s * __expf(m - mn) + __expf(l1 - mn);
            m = mn;
        }
        for (int e2 = e + 64; e2 < end; e2 += 32) {   // deg > 64: ~never
            float l = lrelu(asrc[g_csr[e2]] + adn);
            float mn = fmaxf(m, l);
            s = s * __expf(m - mn) + __expf(l - mn);
            m = mn;
        }
    }
    #pragma unroll
    for (int off = 16; off; off >>= 1) {
        float mo = __shfl_xor_sync(FULL, m, off);
        float so = __shfl_xor_sync(FULL, s, off);
        float mn = fmaxf(m, mo);
        s = s * __expf(m - mn) + so * __expf(mo - mn);
        m = mn;
    }
    const float inv_den = 1.f / s;
    const float c0 = __expf(l0 - m) * inv_den;
    const float c1 = __expf(l1 - m) * inv_den;

    const int nreg = deg < 64 ? deg : 64;

    if (D == 128) {
        float4 a0 = make_float4(0.f, 0.f, 0.f, 0.f);
        int j = 0;
        for (; j + 4 <= nreg; j += 4) {
            int jj = j & 31;
            float cc = (j & 32) ? c1 : c0;
            int   ii = (j & 32) ? i1 : i0;
            float ca = __shfl_sync(FULL, cc, jj);
            float cb = __shfl_sync(FULL, cc, jj + 1);
            float cg = __shfl_sync(FULL, cc, jj + 2);
            float cd = __shfl_sync(FULL, cc, jj + 3);
            int s0 = __shfl_sync(FULL, ii, jj);
            int s1i = __shfl_sync(FULL, ii, jj + 1);
            int s2i = __shfl_sync(FULL, ii, jj + 2);
            int s3i = __shfl_sync(FULL, ii, jj + 3);
            float4 r0 = ((const float4*)(h + (size_t)s0  * 128))[lane];
            float4 r1 = ((const float4*)(h + (size_t)s1i * 128))[lane];
            float4 r2 = ((const float4*)(h + (size_t)s2i * 128))[lane];
            float4 r3 = ((const float4*)(h + (size_t)s3i * 128))[lane];
            a0.x += ca * r0.x + cb * r1.x + cg * r2.x + cd * r3.x;
            a0.y += ca * r0.y + cb * r1.y + cg * r2.y + cd * r3.y;
            a0.z += ca * r0.z + cb * r1.z + cg * r2.z + cd * r3.z;
            a0.w += ca * r0.w + cb * r1.w + cg * r2.w + cd * r3.w;
        }
        for (; j < nreg; j++) {
            int jj = j & 31;
            float cc = (j & 32) ? c1 : c0;
            int   ii = (j & 32) ? i1 : i0;
            float ca = __shfl_sync(FULL, cc, jj);
            int   s0 = __shfl_sync(FULL, ii, jj);
            float4 r0 = ((const float4*)(h + (size_t)s0 * 128))[lane];
            a0.x += ca * r0.x; a0.y += ca * r0.y; a0.z += ca * r0.z; a0.w += ca * r0.w;
        }
        for (int e2 = start + 64; e2 < end; e2++) {
            int sn = g_csr[e2];
            float c = __expf(lrelu(asrc[sn] + adn) - m) * inv_den;
            float4 r0 = ((const float4*)(h + (size_t)sn * 128))[lane];
            a0.x += c * r0.x; a0.y += c * r0.y; a0.z += c * r0.z; a0.w += c * r0.w;
        }
        ((float4*)(out + (size_t)gw * 128))[lane] = a0;
    } else if (D == 64) {
        float2 a = make_float2(0.f, 0.f);
        int j = 0;
        for (; j + 4 <= nreg; j += 4) {
            int jj = j & 31;
            float cc = (j & 32) ? c1 : c0;
            int   ii = (j & 32) ? i1 : i0;
            float ca = __shfl_sync(FULL, cc, jj);
            float cb = __shfl_sync(FULL, cc, jj + 1);
            float cg = __shfl_sync(FULL, cc, jj + 2);
            float cd = __shfl_sync(FULL, cc, jj + 3);
            int s0 = __shfl_sync(FULL, ii, jj);
            int s1i = __shfl_sync(FULL, ii, jj + 1);
            int s2i = __shfl_sync(FULL, ii, jj + 2);
            int s3i = __shfl_sync(FULL, ii, jj + 3);
            float2 r0 = ((const float2*)(h + (size_t)s0  * 64))[lane];
            float2 r1 = ((const float2*)(h + (size_t)s1i * 64))[lane];
            float2 r2 = ((const float2*)(h + (size_t)s2i * 64))[lane];
            float2 r3 = ((const float2*)(h + (size_t)s3i * 64))[lane];
            a.x += ca * r0.x + cb * r1.x + cg * r2.x + cd * r3.x;
            a.y += ca * r0.y + cb * r1.y + cg * r2.y + cd * r3.y;
        }
        for (; j < nreg; j++) {
            int jj = j & 31;
            float cc = (j & 32) ? c1 : c0;
            int   ii = (j & 32) ? i1 : i0;
            float ca = __shfl_sync(FULL, cc, jj);
            int   s0 = __shfl_sync(FULL, ii, jj);
            float2 r0 = ((const float2*)(h + (size_t)s0 * 64))[lane];
            a.x += ca * r0.x; a.y += ca * r0.y;
        }
        for (int e2 = start + 64; e2 < end; e2++) {
            int sn = g_csr[e2];
            float c = __expf(lrelu(asrc[sn] + adn) - m) * inv_den;
            float2 r0 = ((const float2*)(h + (size_t)sn * 64))[lane];
            a.x += c * r0.x; a.y += c * r0.y;
        }
        // bias + ELU, then fused layer-3 matvec: y = a . W3
        float2 bvv = ((const float2*)bias)[lane];
        a.x = elu1(a.x + bvv.x); a.y = elu1(a.y + bvv.y);
        float2 w = ((const float2*)W3)[lane];
        float dot = a.x * w.x + a.y * w.y;
        #pragma unroll
        for (int off = 16; off; off >>= 1) dot += __shfl_xor_sync(FULL, dot, off);
        if (lane == 0) {
            out[gw]   = dot;                 // y (input to final layer)
            g_as3[gw] = dot * as3[0];
            g_ad3[gw] = dot * ad3[0];
        }
    } else { // D == 1
        float a = 0.f;
        for (int e = start + lane; e < end; e += 32) {
            int sn = g_csr[e];
            float c = __expf(lrelu(g_as3[sn] + adn) - m) * inv_den;
            a += c * h[sn];
        }
        #pragma unroll
        for (int off = 16; off; off >>= 1) a += __shfl_xor_sync(FULL, a, off);
        if (lane == 0) out[gw] = a + bias[0];
    }
}

// =============================== launcher ======================================
extern "C" void kernel_launch(void* const* d_in, const int* in_sizes, int n_in,
                              void* d_out, int out_size) {
    const float* x  = (const float*)d_in[0];
    const int*   ei = (const int*)d_in[1];
    const float *W1 = (const float*)d_in[2],  *as1 = (const float*)d_in[3],
                *ad1 = (const float*)d_in[4], *b1  = (const float*)d_in[5];
    const float *W2 = (const float*)d_in[6],  *as2 = (const float*)d_in[7],
                *ad2 = (const float*)d_in[8], *b2  = (const float*)d_in[9];
    const float *W3 = (const float*)d_in[10], *as3 = (const float*)d_in[11],
                *ad3 = (const float*)d_in[12], *b3 = (const float*)d_in[13];
    float* out = (float*)d_out;

    float *ph, *po, *pps, *ppd;
    cudaGetSymbolAddress((void**)&ph, g_h);
    cudaGetSymbolAddress((void**)&po, g_o);
    cudaGetSymbolAddress((void**)&pps, g_ps);
    cudaGetSymbolAddress((void**)&ppd, g_pd);

    const int TB = 256;
    const int nodeBlocks  = (Nn + TB - 1) / TB;
    const int warpNodeBlk = (Nn * 32 + TB - 1) / TB;
    const int mRows = (Nn + 127) / 128;

    // ---- CSR build + W1-folded attention vectors ----
    init_prep<<<nodeBlocks + 1, TB>>>(W1, as1, ad1, nodeBlocks);
    count_k<<<(Ereal + TB - 1) / TB, TB>>>(ei);
    scan_blocks<<<NBLK, 1024>>>();
    scan_tops<<<1, 64>>>();
    scan_add<<<(Nn + 1023) / 1024, 1024>>>();
    place_k<<<(Etot + TB - 1) / TB, TB>>>(ei);

    // ---- layer 1 (aggregate-then-transform): 128 -> 256 ----
    alpha_k<<<warpNodeBlk, TB>>>(x, pps, ppd, Cc);
    agg_k<128><<<warpNodeBlk, TB>>>(x, po, nullptr, nullptr, nullptr, nullptr);
    {
        dim3 grid(D1 / 64, mRows);
        gemm_tc<true, false><<<grid, 256>>>(po, W1, ph, b1, nullptr, nullptr, Nn, Cc, D1);
    }
    // ---- layer 2: 256 -> 64 (alpha fused in GEMM; matvec3 fused in agg) ----
    {
        dim3 grid(D2 / 64, mRows);
        gemm_tc<false, true><<<grid, 256>>>(ph, W2, po, nullptr, as2, ad2, Nn, D1, D2);
        agg_k<64><<<warpNodeBlk, TB>>>(po, ph, b2, W3, as3, ad3);
    }
    // ---- layer 3: 64 -> 1 ----
    agg_k<1><<<warpNodeBlk, TB>>>(ph, out, b3, nullptr, nullptr, nullptr);
}

// round 8
// speedup vs baseline: 2.6448x; 1.1038x over previous
#include <cuda_runtime.h>
#include <cuda_bf16.h>
#include <math.h>

#define Nn     50000
#define Cc     128
#define D1     256
#define D2     64
#define Ereal  800000
#define Etot   (Ereal + Nn)
#define FULL   0xFFFFFFFFu
#define NBLK   ((Nn + 1023) / 1024)

// ---------------- scratch ------------------------------------------------------
__device__ float g_h [(size_t)Nn * D1];
__device__ float g_o [(size_t)Nn * D1];
__device__ float g_as[Nn];
__device__ float g_ad[Nn];
__device__ float g_as3[Nn];
__device__ float g_ad3[Nn];
__device__ float g_ps[Cc];
__device__ float g_pd[Cc];
__device__ int   g_cnt [Nn];
__device__ int   g_wofs[Nn];
__device__ int   g_rowptr[Nn + 1];
__device__ int   g_csr[Etot];
__device__ int   g_bsum[64];
__device__ int   g_boff[64];

// ---------------- init counters + fold attention vecs through W1 ---------------
__global__ void init_prep(const float* __restrict__ W1, const float* __restrict__ as1,
                          const float* __restrict__ ad1, int nodeBlocks) {
    if ((int)blockIdx.x < nodeBlocks) {
        int n = blockIdx.x * blockDim.x + threadIdx.x;
        if (n < Nn) g_cnt[n] = 1;                    // self-loop pre-counted
    } else {
        int t = threadIdx.x;                          // 256 threads: p = W1 @ a
        const float* a = (t < Cc) ? as1 : ad1;
        int i = t & (Cc - 1);
        float s = 0.f;
        const float* row = W1 + (size_t)i * D1;
        for (int j = 0; j < D1; j++) s += row[j] * a[j];
        if (t < Cc) g_ps[i] = s; else g_pd[i] = s;
    }
}
__global__ void count_k(const int* __restrict__ ei) {
    int e = blockIdx.x * blockDim.x + threadIdx.x;
    if (e < Ereal) atomicAdd(&g_cnt[ei[Ereal + e]], 1);
}
__global__ void scan_blocks() {
    __shared__ int wsum[32];
    int tid = threadIdx.x, lane = tid & 31, wid = tid >> 5;
    int i = blockIdx.x * 1024 + tid;
    int v = (i < Nn) ? g_cnt[i] : 0;
    int p = v;
    #pragma unroll
    for (int o = 1; o < 32; o <<= 1) {
        int t = __shfl_up_sync(FULL, p, o);
        if (lane >= o) p += t;
    }
    if (lane == 31) wsum[wid] = p;
    __syncthreads();
    if (wid == 0) {
        int w = wsum[lane];
        #pragma unroll
        for (int o = 1; o < 32; o <<= 1) {
            int t = __shfl_up_sync(FULL, w, o);
            if (lane >= o) w += t;
        }
        wsum[lane] = w;
    }
    __syncthreads();
    int excl = (wid ? wsum[wid - 1] : 0) + p - v;
    if (i < Nn) g_rowptr[i] = excl;
    if (tid == 0) g_bsum[blockIdx.x] = wsum[31];
}
__global__ void scan_tops() {
    __shared__ int sb[64];
    int t = threadIdx.x;
    int v = (t < NBLK) ? g_bsum[t] : 0;
    sb[t] = v;
    __syncthreads();
    #pragma unroll
    for (int o = 1; o < 64; o <<= 1) {
        int x = (t >= o) ? sb[t - o] : 0;
        __syncthreads();
        sb[t] += x;
        __syncthreads();
    }
    if (t < NBLK) g_boff[t] = sb[t] - v;   // exclusive
}
__global__ void scan_add() {
    int i = blockIdx.x * blockDim.x + threadIdx.x;
    if (i < Nn) {
        int val = g_rowptr[i] + g_boff[i >> 10];
        g_rowptr[i] = val;
        g_wofs[i]   = val;
    }
    if (i == 0) g_rowptr[Nn] = Etot;
}
__global__ void place_k(const int* __restrict__ ei) {
    int e = blockIdx.x * blockDim.x + threadIdx.x;
    if (e >= Etot) return;
    int s, d;
    if (e < Ereal) { s = ei[e]; d = ei[Ereal + e]; } else { s = d = e - Ereal; }
    int pos = atomicAdd(&g_wofs[d], 1);
    g_csr[pos] = s;
}

// ================= split-bf16 tensor-core GEMM (m16n8k16, register-prefetch) ====
// C[M,N] = A@B, fp32 in/out; each fp32 split into bf16 hi + bf16 lo residual.
// d += ah*bh + ah*bl + al*bh (lo*lo dropped, ~2^-18 rel).
#define GS 12   // smem row stride in uints (bf16x2); 12q+rr covers all 32 banks

__device__ __forceinline__ unsigned pack_hi(float a, float b, float& ra, float& rb) {
    __nv_bfloat16 ha = __float2bfloat16(a);
    __nv_bfloat16 hb = __float2bfloat16(b);
    ra = a - __bfloat162float(ha);
    rb = b - __bfloat162float(hb);
    return ((unsigned)__bfloat16_as_ushort(hb) << 16) | __bfloat16_as_ushort(ha);
}
__device__ __forceinline__ unsigned pack_bf(float a, float b) {
    return ((unsigned)__bfloat16_as_ushort(__float2bfloat16(b)) << 16)
         | __bfloat16_as_ushort(__float2bfloat16(a));
}
__device__ __forceinline__ void mma_bf16(float (&c)[4], const unsigned* a, const unsigned* b) {
    asm volatile(
        "mma.sync.aligned.m16n8k16.row.col.f32.bf16.bf16.f32 "
        "{%0,%1,%2,%3}, {%4,%5,%6,%7}, {%8,%9}, {%0,%1,%2,%3};\n"
        : "+f"(c[0]), "+f"(c[1]), "+f"(c[2]), "+f"(c[3])
        : "r"(a[0]), "r"(a[1]), "r"(a[2]), "r"(a[3]), "r"(b[0]), "r"(b[1]));
}
__device__ __forceinline__ float elu1(float v) { return v > 0.f ? v : expm1f(v); }

// BIAS_ELU: apply bias+ELU to C. ALPHA: also emit g_as/g_ad = C-row . av/bv (N==64).
template<bool BIAS_ELU, bool ALPHA>
__global__ void __launch_bounds__(256) gemm_tc(const float* __restrict__ A,
                                               const float* __restrict__ B,
                                               float* __restrict__ C,
                                               const float* __restrict__ bias,
                                               const float* __restrict__ av,
                                               const float* __restrict__ bv,
                                               int M, int K, int N) {
    __shared__ unsigned AsH[128 * GS];   // [row][k/2] bf16 pairs
    __shared__ unsigned AsL[128 * GS];
    __shared__ unsigned BsH[64 * GS];    // transposed: [n][k/2] bf16 pairs
    __shared__ unsigned BsL[64 * GS];

    const int br = blockIdx.y * 128;
    const int bn = blockIdx.x * 64;
    const int tid = threadIdx.x;
    const int lane = tid & 31;
    const int warp = tid >> 5;
    const int wm = (warp >> 1) * 32;
    const int wn = (warp & 1) * 32;

    float acc[2][4][4];
    #pragma unroll
    for (int m = 0; m < 2; m++)
        #pragma unroll
        for (int n = 0; n < 4; n++)
            #pragma unroll
            for (int r = 0; r < 4; r++) acc[m][n][r] = 0.f;

    const int q = lane >> 2;       // groupID
    const int rr = lane & 3;       // thread-in-group

    const int aRow0 = tid >> 2,         aC0 = (tid & 3) * 4;    // A: 128x16 floats
    const int aRow1 = (tid + 256) >> 2;
    const int bRow  = tid >> 4,         bN4 = (tid & 15) * 4;   // B: 16x64 floats

    float4 aR[2], bR;
    aR[0] = (br + aRow0 < M) ? *(const float4*)(A + (size_t)(br + aRow0) * K + aC0)
                             : make_float4(0.f, 0.f, 0.f, 0.f);
    aR[1] = (br + aRow1 < M) ? *(const float4*)(A + (size_t)(br + aRow1) * K + aC0)
                             : make_float4(0.f, 0.f, 0.f, 0.f);
    bR = *(const float4*)(B + (size_t)bRow * N + bn + bN4);

    for (int k0 = 0; k0 < K; k0 += 16) {
        // ---- stage A (rows of bf16 pairs) ----
        #pragma unroll
        for (int t = 0; t < 2; t++) {
            int row = t ? aRow1 : aRow0;
            float4 v = aR[t];
            float rx, ry, rz, rw;
            unsigned h01 = pack_hi(v.x, v.y, rx, ry);
            unsigned h23 = pack_hi(v.z, v.w, rz, rw);
            int o = row * GS + (aC0 >> 1);
            AsH[o]     = h01;  AsH[o + 1] = h23;
            AsL[o]     = pack_bf(rx, ry);
            AsL[o + 1] = pack_bf(rz, rw);
        }
        // ---- stage B transposed ([n][k] bf16 scalars) ----
        {
            __nv_bfloat16* bh = (__nv_bfloat16*)BsH;
            __nv_bfloat16* bl = (__nv_bfloat16*)BsL;
            float vv[4] = {bR.x, bR.y, bR.z, bR.w};
            #pragma unroll
            for (int j = 0; j < 4; j++) {
                int n = bN4 + j;
                __nv_bfloat16 h = __float2bfloat16(vv[j]);
                bh[n * (2 * GS) + bRow] = h;
                bl[n * (2 * GS) + bRow] = __float2bfloat16(vv[j] - __bfloat162float(h));
            }
        }
        __syncthreads();

        // ---- prefetch next tile ----
        if (k0 + 16 < K) {
            int kn = k0 + 16;
            aR[0] = (br + aRow0 < M) ? *(const float4*)(A + (size_t)(br + aRow0) * K + kn + aC0)
                                     : make_float4(0.f, 0.f, 0.f, 0.f);
            aR[1] = (br + aRow1 < M) ? *(const float4*)(A + (size_t)(br + aRow1) * K + kn + aC0)
                                     : make_float4(0.f, 0.f, 0.f, 0.f);
            bR = *(const float4*)(B + (size_t)(kn + bRow) * N + bn + bN4);
        }

        // ---- one m16n8k16 group per k-tile ----
        {
            unsigned ah[2][4], al[2][4], bh[4][2], bl[4][2];
            #pragma unroll
            for (int m = 0; m < 2; m++) {
                int r0 = (wm + m * 16 + q) * GS + rr;
                ah[m][0] = AsH[r0];
                ah[m][1] = AsH[r0 + 8 * GS];
                ah[m][2] = AsH[r0 + 4];
                ah[m][3] = AsH[r0 + 8 * GS + 4];
                al[m][0] = AsL[r0];
                al[m][1] = AsL[r0 + 8 * GS];
                al[m][2] = AsL[r0 + 4];
                al[m][3] = AsL[r0 + 8 * GS + 4];
            }
            #pragma unroll
            for (int n = 0; n < 4; n++) {
                int nb = (wn + n * 8 + q) * GS + rr;
                bh[n][0] = BsH[nb];
                bh[n][1] = BsH[nb + 4];
                bl[n][0] = BsL[nb];
                bl[n][1] = BsL[nb + 4];
            }
            #pragma unroll
            for (int m = 0; m < 2; m++)
                #pragma unroll
                for (int n = 0; n < 4; n++) {
                    mma_bf16(acc[m][n], ah[m], bh[n]);
                    mma_bf16(acc[m][n], ah[m], bl[n]);
                    mma_bf16(acc[m][n], al[m], bh[n]);
                }
        }
        __syncthreads();
    }

    #pragma unroll
    for (int m = 0; m < 2; m++) {
        int row0 = br + wm + m * 16 + q;
        #pragma unroll
        for (int n = 0; n < 4; n++) {
            int col = bn + wn + n * 8 + rr * 2;
            float2 v0 = make_float2(acc[m][n][0], acc[m][n][1]);
            float2 v1 = make_float2(acc[m][n][2], acc[m][n][3]);
            if (BIAS_ELU) {
                float b0 = bias[col], b1v = bias[col + 1];
                v0.x = elu1(v0.x + b0); v0.y = elu1(v0.y + b1v);
                v1.x = elu1(v1.x + b0); v1.y = elu1(v1.y + b1v);
            }
            if (row0 < M)
                *(float2*)(C + (size_t)row0 * N + col) = v0;
            if (row0 + 8 < M)
                *(float2*)(C + (size_t)(row0 + 8) * N + col) = v1;
        }
    }

    if (ALPHA) {
        float* sAs = (float*)AsH;
        float* sAd = sAs + 128;
        if (tid < 128) { sAs[tid] = 0.f; sAd[tid] = 0.f; }
        __syncthreads();
        #pragma unroll
        for (int m = 0; m < 2; m++) {
            float pa = 0.f, pd = 0.f, qa = 0.f, qd = 0.f;
            #pragma unroll
            for (int n = 0; n < 4; n++) {
                int col = wn + n * 8 + rr * 2;
                float a0 = av[col], a1 = av[col + 1];
                float d0 = bv[col], d1 = bv[col + 1];
                pa += acc[m][n][0] * a0 + acc[m][n][1] * a1;
                pd += acc[m][n][0] * d0 + acc[m][n][1] * d1;
                qa += acc[m][n][2] * a0 + acc[m][n][3] * a1;
                qd += acc[m][n][2] * d0 + acc[m][n][3] * d1;
            }
            int r = wm + m * 16 + q;
            atomicAdd(&sAs[r], pa);     atomicAdd(&sAd[r], pd);
            atomicAdd(&sAs[r + 8], qa); atomicAdd(&sAd[r + 8], qd);
        }
        __syncthreads();
        if (tid < 128 && br + tid < M) {
            g_as[br + tid] = sAs[tid];
            g_ad[br + tid] = sAd[tid];
        }
    }
}

// ---------------- per-node attention dots (layer 1 on x) -----------------------
__global__ void alpha_k(const float* __restrict__ h, const float* __restrict__ av,
                        const float* __restrict__ bv, int d) {
    int gw = (blockIdx.x * blockDim.x + threadIdx.x) >> 5;
    int lane = threadIdx.x & 31;
    if (gw >= Nn) return;
    float s1 = 0.f, s2 = 0.f;
    for (int j = lane; j < d; j += 32) {
        float v = h[(size_t)gw * d + j];
        s1 += v * av[j];
        s2 += v * bv[j];
    }
    #pragma unroll
    for (int o = 16; o; o >>= 1) {
        s1 += __shfl_xor_sync(FULL, s1, o);
        s2 += __shfl_xor_sync(FULL, s2, o);
    }
    if (lane == 0) { g_as[gw] = s1; g_ad[gw] = s2; }
}

// ---------------- fused softmax + aggregate (warp per node) --------------------
__device__ __forceinline__ float lrelu(float l) { return l > 0.f ? l : 0.2f * l; }

template<int D>
__global__ void agg_k(const float* __restrict__ h, float* __restrict__ out,
                      const float* __restrict__ bias,
                      const float* __restrict__ W3,
                      const float* __restrict__ as3,
                      const float* __restrict__ ad3) {
    int gw   = (blockIdx.x * blockDim.x + threadIdx.x) >> 5;
    int lane = threadIdx.x & 31;
    if (gw >= Nn) return;
    const int start = g_rowptr[gw];
    const int end   = g_rowptr[gw + 1];
    const int deg   = end - start;
    const float adn = (D == 1) ? g_ad3[gw] : g_ad[gw];
    const float* asrc = (D == 1) ? g_as3 : g_as;

    int i0 = 0, i1 = 0;
    float l0 = -3.0e38f, l1 = -3.0e38f;
    float m = -3.0e38f, s = 0.f;
    {
        int e = start + lane;
        if (e < end) { i0 = g_csr[e]; l0 = lrelu(asrc[i0] + adn); m = l0; s = 1.f; }
        if (e + 32 < end) {
            i1 = g_csr[e + 32];
            l1 = lrelu(asrc[i1] + adn);
            float mn = fmaxf(m, l1);
            s = s * __expf(m - mn) + __expf(l1 - mn);
            m = mn;
        }
        for (int e2 = e + 64; e2 < end; e2 += 32) {
            float l = lrelu(asrc[g_csr[e2]] + adn);
            float mn = fmaxf(m, l);
            s = s * __expf(m - mn) + __expf(l - mn);
            m = mn;
        }
    }
    #pragma unroll
    for (int off = 16; off; off >>= 1) {
        float mo = __shfl_xor_sync(FULL, m, off);
        float so = __shfl_xor_sync(FULL, s, off);
        float mn = fmaxf(m, mo);
        s = s * __expf(m - mn) + so * __expf(mo - mn);
        m = mn;
    }
    const float inv_den = 1.f / s;
    const float c0 = __expf(l0 - m) * inv_den;
    const float c1 = __expf(l1 - m) * inv_den;

    const int nreg = deg < 64 ? deg : 64;

    if (D == 128) {
        float4 a0 = make_float4(0.f, 0.f, 0.f, 0.f);
        int j = 0;
        for (; j + 4 <= nreg; j += 4) {
            int jj = j & 31;
            float cc = (j & 32) ? c1 : c0;
            int   ii = (j & 32) ? i1 : i0;
            float ca = __shfl_sync(FULL, cc, jj);
            float cb = __shfl_sync(FULL, cc, jj + 1);
            float cg = __shfl_sync(FULL, cc, jj + 2);
            float cd = __shfl_sync(FULL, cc, jj + 3);
            int s0 = __shfl_sync(FULL, ii, jj);
            int s1i = __shfl_sync(FULL, ii, jj + 1);
            int s2i = __shfl_sync(FULL, ii, jj + 2);
            int s3i = __shfl_sync(FULL, ii, jj + 3);
            float4 r0 = ((const float4*)(h + (size_t)s0  * 128))[lane];
            float4 r1 = ((const float4*)(h + (size_t)s1i * 128))[lane];
            float4 r2 = ((const float4*)(h + (size_t)s2i * 128))[lane];
            float4 r3 = ((const float4*)(h + (size_t)s3i * 128))[lane];
            a0.x += ca * r0.x + cb * r1.x + cg * r2.x + cd * r3.x;
            a0.y += ca * r0.y + cb * r1.y + cg * r2.y + cd * r3.y;
            a0.z += ca * r0.z + cb * r1.z + cg * r2.z + cd * r3.z;
            a0.w += ca * r0.w + cb * r1.w + cg * r2.w + cd * r3.w;
        }
        for (; j < nreg; j++) {
            int jj = j & 31;
            float cc = (j & 32) ? c1 : c0;
            int   ii = (j & 32) ? i1 : i0;
            float ca = __shfl_sync(FULL, cc, jj);
            int   s0 = __shfl_sync(FULL, ii, jj);
            float4 r0 = ((const float4*)(h + (size_t)s0 * 128))[lane];
            a0.x += ca * r0.x; a0.y += ca * r0.y; a0.z += ca * r0.z; a0.w += ca * r0.w;
        }
        for (int e2 = start + 64; e2 < end; e2++) {
            int sn = g_csr[e2];
            float c = __expf(lrelu(asrc[sn] + adn) - m) * inv_den;
            float4 r0 = ((const float4*)(h + (size_t)sn * 128))[lane];
            a0.x += c * r0.x; a0.y += c * r0.y; a0.z += c * r0.z; a0.w += c * r0.w;
        }
        ((float4*)(out + (size_t)gw * 128))[lane] = a0;
    } else if (D == 64) {
        float2 a = make_float2(0.f, 0.f);
        int j = 0;
        for (; j + 4 <= nreg; j += 4) {
            int jj = j & 31;
            float cc = (j & 32) ? c1 : c0;
            int   ii = (j & 32) ? i1 : i0;
            float ca = __shfl_sync(FULL, cc, jj);
            float cb = __shfl_sync(FULL, cc, jj + 1);
            float cg = __shfl_sync(FULL, cc, jj + 2);
            float cd = __shfl_sync(FULL, cc, jj + 3);
            int s0 = __shfl_sync(FULL, ii, jj);
            int s1i = __shfl_sync(FULL, ii, jj + 1);
            int s2i = __shfl_sync(FULL, ii, jj + 2);
            int s3i = __shfl_sync(FULL, ii, jj + 3);
            float2 r0 = ((const float2*)(h + (size_t)s0  * 64))[lane];
            float2 r1 = ((const float2*)(h + (size_t)s1i * 64))[lane];
            float2 r2 = ((const float2*)(h + (size_t)s2i * 64))[lane];
            float2 r3 = ((const float2*)(h + (size_t)s3i * 64))[lane];
            a.x += ca * r0.x + cb * r1.x + cg * r2.x + cd * r3.x;
            a.y += ca * r0.y + cb * r1.y + cg * r2.y + cd * r3.y;
        }
        for (; j < nreg; j++) {
            int jj = j & 31;
            float cc = (j & 32) ? c1 : c0;
            int   ii = (j & 32) ? i1 : i0;
            float ca = __shfl_sync(FULL, cc, jj);
            int   s0 = __shfl_sync(FULL, ii, jj);
            float2 r0 = ((const float2*)(h + (size_t)s0 * 64))[lane];
            a.x += ca * r0.x; a.y += ca * r0.y;
        }
        for (int e2 = start + 64; e2 < end; e2++) {
            int sn = g_csr[e2];
            float c = __expf(lrelu(asrc[sn] + adn) - m) * inv_den;
            float2 r0 = ((const float2*)(h + (size_t)sn * 64))[lane];
            a.x += c * r0.x; a.y += c * r0.y;
        }
        float2 bvv = ((const float2*)bias)[lane];
        a.x = elu1(a.x + bvv.x); a.y = elu1(a.y + bvv.y);
        float2 w = ((const float2*)W3)[lane];
        float dot = a.x * w.x + a.y * w.y;
        #pragma unroll
        for (int off = 16; off; off >>= 1) dot += __shfl_xor_sync(FULL, dot, off);
        if (lane == 0) {
            out[gw]   = dot;
            g_as3[gw] = dot * as3[0];
            g_ad3[gw] = dot * ad3[0];
        }
    } else { // D == 1
        float a = 0.f;
        for (int e = start + lane; e < end; e += 32) {
            int sn = g_csr[e];
            float c = __expf(lrelu(g_as3[sn] + adn) - m) * inv_den;
            a += c * h[sn];
        }
        #pragma unroll
        for (int off = 16; off; off >>= 1) a += __shfl_xor_sync(FULL, a, off);
        if (lane == 0) out[gw] = a + bias[0];
    }
}

// =============================== launcher ======================================
extern "C" void kernel_launch(void* const* d_in, const int* in_sizes, int n_in,
                              void* d_out, int out_size) {
    const float* x  = (const float*)d_in[0];
    const int*   ei = (const int*)d_in[1];
    const float *W1 = (const float*)d_in[2],  *as1 = (const float*)d_in[3],
                *ad1 = (const float*)d_in[4], *b1  = (const float*)d_in[5];
    const float *W2 = (const float*)d_in[6],  *as2 = (const float*)d_in[7],
                *ad2 = (const float*)d_in[8], *b2  = (const float*)d_in[9];
    const float *W3 = (const float*)d_in[10], *as3 = (const float*)d_in[11],
                *ad3 = (const float*)d_in[12], *b3 = (const float*)d_in[13];
    float* out = (float*)d_out;

    float *ph, *po, *pps, *ppd;
    cudaGetSymbolAddress((void**)&ph, g_h);
    cudaGetSymbolAddress((void**)&po, g_o);
    cudaGetSymbolAddress((void**)&pps, g_ps);
    cudaGetSymbolAddress((void**)&ppd, g_pd);

    const int TB = 256;
    const int nodeBlocks  = (Nn + TB - 1) / TB;
    const int warpNodeBlk = (Nn * 32 + TB - 1) / TB;
    const int mRows = (Nn + 127) / 128;

    // ---- CSR build + W1-folded attention vectors ----
    init_prep<<<nodeBlocks + 1, TB>>>(W1, as1, ad1, nodeBlocks);
    count_k<<<(Ereal + TB - 1) / TB, TB>>>(ei);
    scan_blocks<<<NBLK, 1024>>>();
    scan_tops<<<1, 64>>>();
    scan_add<<<(Nn + 1023) / 1024, 1024>>>();
    place_k<<<(Etot + TB - 1) / TB, TB>>>(ei);

    // ---- layer 1 (aggregate-then-transform): 128 -> 256 ----
    alpha_k<<<warpNodeBlk, TB>>>(x, pps, ppd, Cc);
    agg_k<128><<<warpNodeBlk, TB>>>(x, po, nullptr, nullptr, nullptr, nullptr);
    {
        dim3 grid(D1 / 64, mRows);
        gemm_tc<true, false><<<grid, 256>>>(po, W1, ph, b1, nullptr, nullptr, Nn, Cc, D1);
    }
    // ---- layer 2: 256 -> 64 (alpha fused in GEMM; matvec3 fused in agg) ----
    {
        dim3 grid(D2 / 64, mRows);
        gemm_tc<false, true><<<grid, 256>>>(ph, W2, po, nullptr, as2, ad2, Nn, D1, D2);
        agg_k<64><<<warpNodeBlk, TB>>>(po, ph, b2, W3, as3, ad3);
    }
    // ---- layer 3: 64 -> 1 ----
    agg_k<1><<<warpNodeBlk, TB>>>(ph, out, b3, nullptr, nullptr, nullptr);
}

// round 9
// speedup vs baseline: 2.6454x; 1.0002x over previous
#include <cuda_runtime.h>
#include <cuda_bf16.h>
#include <math.h>

#define Nn     50000
#define Cc     128
#define D1     256
#define D2     64
#define Ereal  800000
#define Etot   (Ereal + Nn)
#define FULL   0xFFFFFFFFu
#define NBLK   ((Nn + 1023) / 1024)

// ---------------- scratch ------------------------------------------------------
__device__ float g_h [(size_t)Nn * D1];
__device__ float g_o [(size_t)Nn * D1];
__device__ float g_as[Nn];
__device__ float g_ad[Nn];
__device__ float g_as3[Nn];
__device__ float g_ad3[Nn];
__device__ float g_ps[Cc];
__device__ float g_pd[Cc];
__device__ int   g_cnt [Nn];
__device__ int   g_epos[Ereal];
__device__ int   g_rowptr[Nn + 1];
__device__ int   g_csr[Etot];
__device__ int   g_bsum[64];

// ---------------- init counters + fold attention vecs through W1 ---------------
__global__ void init_prep(const float* __restrict__ W1, const float* __restrict__ as1,
                          const float* __restrict__ ad1, int nodeBlocks) {
    if ((int)blockIdx.x < nodeBlocks) {
        int n = blockIdx.x * blockDim.x + threadIdx.x;
        if (n < Nn) g_cnt[n] = 1;                    // slot 0 reserved for self-loop
    } else {
        int t = threadIdx.x;                          // 256 threads: p = W1 @ a
        const float* a = (t < Cc) ? as1 : ad1;
        int i = t & (Cc - 1);
        float s = 0.f;
        const float* row = W1 + (size_t)i * D1;
        for (int j = 0; j < D1; j++) s += row[j] * a[j];
        if (t < Cc) g_ps[i] = s; else g_pd[i] = s;
    }
}
// count + record per-edge slot (4 edges per thread)
__global__ void count_k(const int* __restrict__ ei) {
    int t = blockIdx.x * blockDim.x + threadIdx.x;
    if (t * 4 >= Ereal) return;
    int4 d4 = ((const int4*)(ei + Ereal))[t];
    int e = t * 4;
    g_epos[e + 0] = atomicAdd(&g_cnt[d4.x], 1);
    g_epos[e + 1] = atomicAdd(&g_cnt[d4.y], 1);
    g_epos[e + 2] = atomicAdd(&g_cnt[d4.z], 1);
    g_epos[e + 3] = atomicAdd(&g_cnt[d4.w], 1);
}
__global__ void scan_blocks() {
    __shared__ int wsum[32];
    int tid = threadIdx.x, lane = tid & 31, wid = tid >> 5;
    int i = blockIdx.x * 1024 + tid;
    int v = (i < Nn) ? g_cnt[i] : 0;
    int p = v;
    #pragma unroll
    for (int o = 1; o < 32; o <<= 1) {
        int t = __shfl_up_sync(FULL, p, o);
        if (lane >= o) p += t;
    }
    if (lane == 31) wsum[wid] = p;
    __syncthreads();
    if (wid == 0) {
        int w = wsum[lane];
        #pragma unroll
        for (int o = 1; o < 32; o <<= 1) {
            int t = __shfl_up_sync(FULL, w, o);
            if (lane >= o) w += t;
        }
        wsum[lane] = w;
    }
    __syncthreads();
    int excl = (wid ? wsum[wid - 1] : 0) + p - v;
    if (i < Nn) g_rowptr[i] = excl;
    if (tid == 0) g_bsum[blockIdx.x] = wsum[31];
}
// adds block offset (top-scan inlined), writes self-loop into csr slot 0
__global__ void scan_add() {
    __shared__ int soff;
    int tid = threadIdx.x;
    if (tid == 0) {
        int s = 0;
        for (int j = 0; j < (int)blockIdx.x; j++) s += g_bsum[j];
        soff = s;
    }
    __syncthreads();
    int i = blockIdx.x * 1024 + tid;
    if (i < Nn) {
        int val = g_rowptr[i] + soff;
        g_rowptr[i] = val;
        g_csr[val]  = i;          // self-loop at slot 0
    }
    if (i == 0) g_rowptr[Nn] = Etot;
}
// no atomics: slot precomputed in count_k (4 edges per thread)
__global__ void place_k(const int* __restrict__ ei) {
    int t = blockIdx.x * blockDim.x + threadIdx.x;
    if (t * 4 >= Ereal) return;
    int4 s4 = ((const int4*)ei)[t];
    int4 d4 = ((const int4*)(ei + Ereal))[t];
    int4 p4 = ((const int4*)g_epos)[t];
    g_csr[g_rowptr[d4.x] + p4.x] = s4.x;
    g_csr[g_rowptr[d4.y] + p4.y] = s4.y;
    g_csr[g_rowptr[d4.z] + p4.z] = s4.z;
    g_csr[g_rowptr[d4.w] + p4.w] = s4.w;
}

// ================= split-bf16 tensor-core GEMM (m16n8k16, register-prefetch) ====
#define GS 12

__device__ __forceinline__ unsigned pack_hi(float a, float b, float& ra, float& rb) {
    __nv_bfloat16 ha = __float2bfloat16(a);
    __nv_bfloat16 hb = __float2bfloat16(b);
    ra = a - __bfloat162float(ha);
    rb = b - __bfloat162float(hb);
    return ((unsigned)__bfloat16_as_ushort(hb) << 16) | __bfloat16_as_ushort(ha);
}
__device__ __forceinline__ unsigned pack_bf(float a, float b) {
    return ((unsigned)__bfloat16_as_ushort(__float2bfloat16(b)) << 16)
         | __bfloat16_as_ushort(__float2bfloat16(a));
}
__device__ __forceinline__ void mma_bf16(float (&c)[4], const unsigned* a, const unsigned* b) {
    asm volatile(
        "mma.sync.aligned.m16n8k16.row.col.f32.bf16.bf16.f32 "
        "{%0,%1,%2,%3}, {%4,%5,%6,%7}, {%8,%9}, {%0,%1,%2,%3};\n"
        : "+f"(c[0]), "+f"(c[1]), "+f"(c[2]), "+f"(c[3])
        : "r"(a[0]), "r"(a[1]), "r"(a[2]), "r"(a[3]), "r"(b[0]), "r"(b[1]));
}
__device__ __forceinline__ float elu1(float v) { return v > 0.f ? v : expm1f(v); }

template<bool BIAS_ELU, bool ALPHA>
__global__ void __launch_bounds__(256) gemm_tc(const float* __restrict__ A,
                                               const float* __restrict__ B,
                                               float* __restrict__ C,
                                               const float* __restrict__ bias,
                                               const float* __restrict__ av,
                                               const float* __restrict__ bv,
                                               int M, int K, int N) {
    __shared__ unsigned AsH[128 * GS];
    __shared__ unsigned AsL[128 * GS];
    __shared__ unsigned BsH[64 * GS];
    __shared__ unsigned BsL[64 * GS];

    const int br = blockIdx.y * 128;
    const int bn = blockIdx.x * 64;
    const int tid = threadIdx.x;
    const int lane = tid & 31;
    const int warp = tid >> 5;
    const int wm = (warp >> 1) * 32;
    const int wn = (warp & 1) * 32;

    float acc[2][4][4];
    #pragma unroll
    for (int m = 0; m < 2; m++)
        #pragma unroll
        for (int n = 0; n < 4; n++)
            #pragma unroll
            for (int r = 0; r < 4; r++) acc[m][n][r] = 0.f;

    const int q = lane >> 2;
    const int rr = lane & 3;

    const int aRow0 = tid >> 2,         aC0 = (tid & 3) * 4;
    const int aRow1 = (tid + 256) >> 2;
    const int bRow  = tid >> 4,         bN4 = (tid & 15) * 4;

    float4 aR[2], bR;
    aR[0] = (br + aRow0 < M) ? *(const float4*)(A + (size_t)(br + aRow0) * K + aC0)
                             : make_float4(0.f, 0.f, 0.f, 0.f);
    aR[1] = (br + aRow1 < M) ? *(const float4*)(A + (size_t)(br + aRow1) * K + aC0)
                             : make_float4(0.f, 0.f, 0.f, 0.f);
    bR = *(const float4*)(B + (size_t)bRow * N + bn + bN4);

    for (int k0 = 0; k0 < K; k0 += 16) {
        #pragma unroll
        for (int t = 0; t < 2; t++) {
            int row = t ? aRow1 : aRow0;
            float4 v = aR[t];
            float rx, ry, rz, rw;
            unsigned h01 = pack_hi(v.x, v.y, rx, ry);
            unsigned h23 = pack_hi(v.z, v.w, rz, rw);
            int o = row * GS + (aC0 >> 1);
            AsH[o]     = h01;  AsH[o + 1] = h23;
            AsL[o]     = pack_bf(rx, ry);
            AsL[o + 1] = pack_bf(rz, rw);
        }
        {
            __nv_bfloat16* bh = (__nv_bfloat16*)BsH;
            __nv_bfloat16* bl = (__nv_bfloat16*)BsL;
            float vv[4] = {bR.x, bR.y, bR.z, bR.w};
            #pragma unroll
            for (int j = 0; j < 4; j++) {
                int n = bN4 + j;
                __nv_bfloat16 h = __float2bfloat16(vv[j]);
                bh[n * (2 * GS) + bRow] = h;
                bl[n * (2 * GS) + bRow] = __float2bfloat16(vv[j] - __bfloat162float(h));
            }
        }
        __syncthreads();

        if (k0 + 16 < K) {
            int kn = k0 + 16;
            aR[0] = (br + aRow0 < M) ? *(const float4*)(A + (size_t)(br + aRow0) * K + kn + aC0)
                                     : make_float4(0.f, 0.f, 0.f, 0.f);
            aR[1] = (br + aRow1 < M) ? *(const float4*)(A + (size_t)(br + aRow1) * K + kn + aC0)
                                     : make_float4(0.f, 0.f, 0.f, 0.f);
            bR = *(const float4*)(B + (size_t)(kn + bRow) * N + bn + bN4);
        }

        {
            unsigned ah[2][4], al[2][4], bh[4][2], bl[4][2];
            #pragma unroll
            for (int m = 0; m < 2; m++) {
                int r0 = (wm + m * 16 + q) * GS + rr;
                ah[m][0] = AsH[r0];
                ah[m][1] = AsH[r0 + 8 * GS];
                ah[m][2] = AsH[r0 + 4];
                ah[m][3] = AsH[r0 + 8 * GS + 4];
                al[m][0] = AsL[r0];
                al[m][1] = AsL[r0 + 8 * GS];
                al[m][2] = AsL[r0 + 4];
                al[m][3] = AsL[r0 + 8 * GS + 4];
            }
            #pragma unroll
            for (int n = 0; n < 4; n++) {
                int nb = (wn + n * 8 + q) * GS + rr;
                bh[n][0] = BsH[nb];
                bh[n][1] = BsH[nb + 4];
                bl[n][0] = BsL[nb];
                bl[n][1] = BsL[nb + 4];
            }
            #pragma unroll
            for (int m = 0; m < 2; m++)
                #pragma unroll
                for (int n = 0; n < 4; n++) {
                    mma_bf16(acc[m][n], ah[m], bh[n]);
                    mma_bf16(acc[m][n], ah[m], bl[n]);
                    mma_bf16(acc[m][n], al[m], bh[n]);
                }
        }
        __syncthreads();
    }

    #pragma unroll
    for (int m = 0; m < 2; m++) {
        int row0 = br + wm + m * 16 + q;
        #pragma unroll
        for (int n = 0; n < 4; n++) {
            int col = bn + wn + n * 8 + rr * 2;
            float2 v0 = make_float2(acc[m][n][0], acc[m][n][1]);
            float2 v1 = make_float2(acc[m][n][2], acc[m][n][3]);
            if (BIAS_ELU) {
                float b0 = bias[col], b1v = bias[col + 1];
                v0.x = elu1(v0.x + b0); v0.y = elu1(v0.y + b1v);
                v1.x = elu1(v1.x + b0); v1.y = elu1(v1.y + b1v);
            }
            if (row0 < M)
                *(float2*)(C + (size_t)row0 * N + col) = v0;
            if (row0 + 8 < M)
                *(float2*)(C + (size_t)(row0 + 8) * N + col) = v1;
        }
    }

    if (ALPHA) {
        float* sAs = (float*)AsH;
        float* sAd = sAs + 128;
        if (tid < 128) { sAs[tid] = 0.f; sAd[tid] = 0.f; }
        __syncthreads();
        #pragma unroll
        for (int m = 0; m < 2; m++) {
            float pa = 0.f, pd = 0.f, qa = 0.f, qd = 0.f;
            #pragma unroll
            for (int n = 0; n < 4; n++) {
                int col = wn + n * 8 + rr * 2;
                float a0 = av[col], a1 = av[col + 1];
                float d0 = bv[col], d1 = bv[col + 1];
                pa += acc[m][n][0] * a0 + acc[m][n][1] * a1;
                pd += acc[m][n][0] * d0 + acc[m][n][1] * d1;
                qa += acc[m][n][2] * a0 + acc[m][n][3] * a1;
                qd += acc[m][n][2] * d0 + acc[m][n][3] * d1;
            }
            int r = wm + m * 16 + q;
            atomicAdd(&sAs[r], pa);     atomicAdd(&sAd[r], pd);
            atomicAdd(&sAs[r + 8], qa); atomicAdd(&sAd[r + 8], qd);
        }
        __syncthreads();
        if (tid < 128 && br + tid < M) {
            g_as[br + tid] = sAs[tid];
            g_ad[br + tid] = sAd[tid];
        }
    }
}

// ---------------- per-node attention dots (layer 1 on x) -----------------------
__global__ void alpha_k(const float* __restrict__ h, const float* __restrict__ av,
                        const float* __restrict__ bv, int d) {
    int gw = (blockIdx.x * blockDim.x + threadIdx.x) >> 5;
    int lane = threadIdx.x & 31;
    if (gw >= Nn) return;
    float s1 = 0.f, s2 = 0.f;
    for (int j = lane; j < d; j += 32) {
        float v = h[(size_t)gw * d + j];
        s1 += v * av[j];
        s2 += v * bv[j];
    }
    #pragma unroll
    for (int o = 16; o; o >>= 1) {
        s1 += __shfl_xor_sync(FULL, s1, o);
        s2 += __shfl_xor_sync(FULL, s2, o);
    }
    if (lane == 0) { g_as[gw] = s1; g_ad[gw] = s2; }
}

// ---------------- fused softmax + aggregate (warp per node) --------------------
__device__ __forceinline__ float lrelu(float l) { return l > 0.f ? l : 0.2f * l; }

template<int D>
__global__ void agg_k(const float* __restrict__ h, float* __restrict__ out,
                      const float* __restrict__ bias,
                      const float* __restrict__ W3,
                      const float* __restrict__ as3,
                      const float* __restrict__ ad3) {
    int gw   = (blockIdx.x * blockDim.x + threadIdx.x) >> 5;
    int lane = threadIdx.x & 31;
    if (gw >= Nn) return;
    const int start = g_rowptr[gw];
    const int end   = g_rowptr[gw + 1];
    const int deg   = end - start;
    const float adn = (D == 1) ? g_ad3[gw] : g_ad[gw];
    const float* asrc = (D == 1) ? g_as3 : g_as;

    int i0 = 0, i1 = 0;
    float l0 = -3.0e38f, l1 = -3.0e38f;
    float m = -3.0e38f, s = 0.f;
    {
        int e = start + lane;
        if (e < end) { i0 = g_csr[e]; l0 = lrelu(asrc[i0] + adn); m = l0; s = 1.f; }
        if (e + 32 < end) {
            i1 = g_csr[e + 32];
            l1 = lrelu(asrc[i1] + adn);
            float mn = fmaxf(m, l1);
            s = s * __expf(m - mn) + __expf(l1 - mn);
            m = mn;
        }
        for (int e2 = e + 64; e2 < end; e2 += 32) {
            float l = lrelu(asrc[g_csr[e2]] + adn);
            float mn = fmaxf(m, l);
            s = s * __expf(m - mn) + __expf(l - mn);
            m = mn;
        }
    }
    #pragma unroll
    for (int off = 16; off; off >>= 1) {
        float mo = __shfl_xor_sync(FULL, m, off);
        float so = __shfl_xor_sync(FULL, s, off);
        float mn = fmaxf(m, mo);
        s = s * __expf(m - mn) + so * __expf(mo - mn);
        m = mn;
    }
    const float inv_den = 1.f / s;
    const float c0 = __expf(l0 - m) * inv_den;
    const float c1 = __expf(l1 - m) * inv_den;

    const int nreg = deg < 64 ? deg : 64;

    if (D == 128) {
        float4 a0 = make_float4(0.f, 0.f, 0.f, 0.f);
        int j = 0;
        for (; j + 8 <= nreg; j += 8) {
            float cs[8]; int ss[8];
            #pragma unroll
            for (int u = 0; u < 8; u++) {
                int idx = j + u, jj = idx & 31;
                float cc = (idx & 32) ? c1 : c0;
                int   ii = (idx & 32) ? i1 : i0;
                cs[u] = __shfl_sync(FULL, cc, jj);
                ss[u] = __shfl_sync(FULL, ii, jj);
            }
            float4 r[8];
            #pragma unroll
            for (int u = 0; u < 8; u++)
                r[u] = ((const float4*)(h + (size_t)ss[u] * 128))[lane];
            #pragma unroll
            for (int u = 0; u < 8; u++) {
                a0.x += cs[u] * r[u].x; a0.y += cs[u] * r[u].y;
                a0.z += cs[u] * r[u].z; a0.w += cs[u] * r[u].w;
            }
        }
        for (; j < nreg; j++) {
            int jj = j & 31;
            float cc = (j & 32) ? c1 : c0;
            int   ii = (j & 32) ? i1 : i0;
            float ca = __shfl_sync(FULL, cc, jj);
            int   s0 = __shfl_sync(FULL, ii, jj);
            float4 r0 = ((const float4*)(h + (size_t)s0 * 128))[lane];
            a0.x += ca * r0.x; a0.y += ca * r0.y; a0.z += ca * r0.z; a0.w += ca * r0.w;
        }
        for (int e2 = start + 64; e2 < end; e2++) {
            int sn = g_csr[e2];
            float c = __expf(lrelu(asrc[sn] + adn) - m) * inv_den;
            float4 r0 = ((const float4*)(h + (size_t)sn * 128))[lane];
            a0.x += c * r0.x; a0.y += c * r0.y; a0.z += c * r0.z; a0.w += c * r0.w;
        }
        ((float4*)(out + (size_t)gw * 128))[lane] = a0;
    } else if (D == 64) {
        float2 a = make_float2(0.f, 0.f);
        int j = 0;
        for (; j + 8 <= nreg; j += 8) {
            float cs[8]; int ss[8];
            #pragma unroll
            for (int u = 0; u < 8; u++) {
                int idx = j + u, jj = idx & 31;
                float cc = (idx & 32) ? c1 : c0;
                int   ii = (idx & 32) ? i1 : i0;
                cs[u] = __shfl_sync(FULL, cc, jj);
                ss[u] = __shfl_sync(FULL, ii, jj);
            }
            float2 r[8];
            #pragma unroll
            for (int u = 0; u < 8; u++)
                r[u] = ((const float2*)(h + (size_t)ss[u] * 64))[lane];
            #pragma unroll
            for (int u = 0; u < 8; u++) {
                a.x += cs[u] * r[u].x; a.y += cs[u] * r[u].y;
            }
        }
        for (; j < nreg; j++) {
            int jj = j & 31;
            float cc = (j & 32) ? c1 : c0;
            int   ii = (j & 32) ? i1 : i0;
            float ca = __shfl_sync(FULL, cc, jj);
            int   s0 = __shfl_sync(FULL, ii, jj);
            float2 r0 = ((const float2*)(h + (size_t)s0 * 64))[lane];
            a.x += ca * r0.x; a.y += ca * r0.y;
        }
        for (int e2 = start + 64; e2 < end; e2++) {
            int sn = g_csr[e2];
            float c = __expf(lrelu(asrc[sn] + adn) - m) * inv_den;
            float2 r0 = ((const float2*)(h + (size_t)sn * 64))[lane];
            a.x += c * r0.x; a.y += c * r0.y;
        }
        float2 bvv = ((const float2*)bias)[lane];
        a.x = elu1(a.x + bvv.x); a.y = elu1(a.y + bvv.y);
        float2 w = ((const float2*)W3)[lane];
        float dot = a.x * w.x + a.y * w.y;
        #pragma unroll
        for (int off = 16; off; off >>= 1) dot += __shfl_xor_sync(FULL, dot, off);
        if (lane == 0) {
            out[gw]   = dot;
            g_as3[gw] = dot * as3[0];
            g_ad3[gw] = dot * ad3[0];
        }
    } else { // D == 1
        float a = 0.f;
        for (int e = start + lane; e < end; e += 32) {
            int sn = g_csr[e];
            float c = __expf(lrelu(g_as3[sn] + adn) - m) * inv_den;
            a += c * h[sn];
        }
        #pragma unroll
        for (int off = 16; off; off >>= 1) a += __shfl_xor_sync(FULL, a, off);
        if (lane == 0) out[gw] = a + bias[0];
    }
}

// =============================== launcher ======================================
extern "C" void kernel_launch(void* const* d_in, const int* in_sizes, int n_in,
                              void* d_out, int out_size) {
    const float* x  = (const float*)d_in[0];
    const int*   ei = (const int*)d_in[1];
    const float *W1 = (const float*)d_in[2],  *as1 = (const float*)d_in[3],
                *ad1 = (const float*)d_in[4], *b1  = (const float*)d_in[5];
    const float *W2 = (const float*)d_in[6],  *as2 = (const float*)d_in[7],
                *ad2 = (const float*)d_in[8], *b2  = (const float*)d_in[9];
    const float *W3 = (const float*)d_in[10], *as3 = (const float*)d_in[11],
                *ad3 = (const float*)d_in[12], *b3 = (const float*)d_in[13];
    float* out = (float*)d_out;

    float *ph, *po, *pps, *ppd;
    cudaGetSymbolAddress((void**)&ph, g_h);
    cudaGetSymbolAddress((void**)&po, g_o);
    cudaGetSymbolAddress((void**)&pps, g_ps);
    cudaGetSymbolAddress((void**)&ppd, g_pd);

    const int TB = 256;
    const int nodeBlocks  = (Nn + TB - 1) / TB;
    const int warpNodeBlk = (Nn * 32 + TB - 1) / TB;
    const int edge4Blk    = (Ereal / 4 + TB - 1) / TB;
    const int mRows = (Nn + 127) / 128;

    // ---- CSR build + W1-folded attention vectors ----
    init_prep<<<nodeBlocks + 1, TB>>>(W1, as1, ad1, nodeBlocks);
    count_k<<<edge4Blk, TB>>>(ei);
    scan_blocks<<<NBLK, 1024>>>();
    scan_add<<<NBLK, 1024>>>();
    place_k<<<edge4Blk, TB>>>(ei);

    // ---- layer 1 (aggregate-then-transform): 128 -> 256 ----
    alpha_k<<<warpNodeBlk, TB>>>(x, pps, ppd, Cc);
    agg_k<128><<<warpNodeBlk, TB>>>(x, po, nullptr, nullptr, nullptr, nullptr);
    {
        dim3 grid(D1 / 64, mRows);
        gemm_tc<true, false><<<grid, 256>>>(po, W1, ph, b1, nullptr, nullptr, Nn, Cc, D1);
    }
    // ---- layer 2: 256 -> 64 (alpha fused in GEMM; matvec3 fused in agg) ----
    {
        dim3 grid(D2 / 64, mRows);
        gemm_tc<false, true><<<grid, 256>>>(ph, W2, po, nullptr, as2, ad2, Nn, D1, D2);
        agg_k<64><<<warpNodeBlk, TB>>>(po, ph, b2, W3, as3, ad3);
    }
    // ---- layer 3: 64 -> 1 ----
    agg_k<1><<<warpNodeBlk, TB>>>(ph, out, b3, nullptr, nullptr, nullptr);
}

// round 10
// speedup vs baseline: 2.6843x; 1.0147x over previous
#include <cuda_runtime.h>
#include <cuda_bf16.h>
#include <math.h>

#define Nn     50000
#define Cc     128
#define D1     256
#define D2     64
#define Ereal  800000
#define Etot   (Ereal + Nn)
#define FULL   0xFFFFFFFFu
#define NBLK   ((Nn + 1023) / 1024)

// ---------------- scratch ------------------------------------------------------
__device__ unsigned short g_xh[(size_t)Nn * Cc];   // agg(x) hi/lo bf16 (GEMM1 A)
__device__ unsigned short g_xl[(size_t)Nn * Cc];
__device__ unsigned short g_hh[(size_t)Nn * D1];   // h hi/lo bf16 (GEMM2 A)
__device__ unsigned short g_hl[(size_t)Nn * D1];
__device__ unsigned short g_w1h[D1 * Cc];          // W1^T hi/lo  [n=256][k=128]
__device__ unsigned short g_w1l[D1 * Cc];
__device__ unsigned short g_w2h[D2 * D1];          // W2^T hi/lo  [n=64][k=256]
__device__ unsigned short g_w2l[D2 * D1];
__device__ float g_o [(size_t)Nn * D2];            // layer-2 GEMM out (fp32)
__device__ float g_y [Nn];                         // layer-3 input
__device__ float g_as[Nn];
__device__ float g_ad[Nn];
__device__ float g_as3[Nn];
__device__ float g_ad3[Nn];
__device__ float g_ps[Cc];
__device__ float g_pd[Cc];
__device__ int   g_cnt [Nn];
__device__ int   g_epos[Ereal];
__device__ int   g_rowptr[Nn + 1];
__device__ int   g_csr[Etot];
__device__ int   g_bsum[64];

__device__ __forceinline__ unsigned short bf_hi(float v, float& r) {
    __nv_bfloat16 h = __float2bfloat16(v);
    r = v - __bfloat162float(h);
    return __bfloat16_as_ushort(h);
}
__device__ __forceinline__ unsigned short bf_of(float v) {
    return __bfloat16_as_ushort(__float2bfloat16(v));
}
__device__ __forceinline__ unsigned pack_hi(float a, float b, float& ra, float& rb) {
    unsigned ha = bf_hi(a, ra), hb = bf_hi(b, rb);
    return (hb << 16) | ha;
}
__device__ __forceinline__ unsigned pack_bf(float a, float b) {
    return ((unsigned)bf_of(b) << 16) | bf_of(a);
}
__device__ __forceinline__ float elu1(float v) { return v > 0.f ? v : expm1f(v); }
__device__ __forceinline__ float lrelu(float l) { return l > 0.f ? l : 0.2f * l; }

// ---------------- init: counters + p=W1@a + weight split/transpose -------------
#define W1BLK 128   // 32768 / 256
#define W2BLK 64    // 16384 / 256
__global__ void init_prep(const float* __restrict__ W1, const float* __restrict__ as1,
                          const float* __restrict__ ad1, const float* __restrict__ W2,
                          int nodeBlocks) {
    int b = blockIdx.x;
    if (b < nodeBlocks) {
        int n = b * blockDim.x + threadIdx.x;
        if (n < Nn) g_cnt[n] = 1;                    // slot 0 reserved for self-loop
    } else if (b == nodeBlocks) {
        int t = threadIdx.x;                          // p = W1 @ a
        const float* a = (t < Cc) ? as1 : ad1;
        int i = t & (Cc - 1);
        float s = 0.f;
        const float* row = W1 + (size_t)i * D1;
        for (int j = 0; j < D1; j++) s += row[j] * a[j];
        if (t < Cc) g_ps[i] = s; else g_pd[i] = s;
    } else if (b < nodeBlocks + 1 + W1BLK) {
        int idx = (b - nodeBlocks - 1) * 256 + threadIdx.x;  // [0, 32768)
        int n = idx >> 7, k = idx & 127;
        float v = W1[(size_t)k * D1 + n];
        float r;
        g_w1h[idx] = bf_hi(v, r);
        g_w1l[idx] = bf_of(r);
    } else {
        int idx = (b - nodeBlocks - 1 - W1BLK) * 256 + threadIdx.x;  // [0, 16384)
        int n = idx >> 8, k = idx & 255;
        float v = W2[(size_t)k * D2 + n];
        float r;
        g_w2h[idx] = bf_hi(v, r);
        g_w2l[idx] = bf_of(r);
    }
}

// ---------------- count (+slot record) fused with layer-1 alpha ----------------
__global__ void count_alpha(const int* __restrict__ ei, const float* __restrict__ x,
                            int edge4Blk) {
    if ((int)blockIdx.x < edge4Blk) {
        int t = blockIdx.x * blockDim.x + threadIdx.x;
        if (t * 4 >= Ereal) return;
        int4 d4 = ((const int4*)(ei + Ereal))[t];
        int e = t * 4;
        g_epos[e + 0] = atomicAdd(&g_cnt[d4.x], 1);
        g_epos[e + 1] = atomicAdd(&g_cnt[d4.y], 1);
        g_epos[e + 2] = atomicAdd(&g_cnt[d4.z], 1);
        g_epos[e + 3] = atomicAdd(&g_cnt[d4.w], 1);
    } else {
        int gw = ((blockIdx.x - edge4Blk) * blockDim.x + threadIdx.x) >> 5;
        int lane = threadIdx.x & 31;
        if (gw >= Nn) return;
        float4 v = ((const float4*)(x + (size_t)gw * Cc))[lane];
        float4 p = ((const float4*)g_ps)[lane];
        float4 q = ((const float4*)g_pd)[lane];
        float s1 = v.x * p.x + v.y * p.y + v.z * p.z + v.w * p.w;
        float s2 = v.x * q.x + v.y * q.y + v.z * q.z + v.w * q.w;
        #pragma unroll
        for (int o = 16; o; o >>= 1) {
            s1 += __shfl_xor_sync(FULL, s1, o);
            s2 += __shfl_xor_sync(FULL, s2, o);
        }
        if (lane == 0) { g_as[gw] = s1; g_ad[gw] = s2; }
    }
}
__global__ void scan_blocks() {
    __shared__ int wsum[32];
    int tid = threadIdx.x, lane = tid & 31, wid = tid >> 5;
    int i = blockIdx.x * 1024 + tid;
    int v = (i < Nn) ? g_cnt[i] : 0;
    int p = v;
    #pragma unroll
    for (int o = 1; o < 32; o <<= 1) {
        int t = __shfl_up_sync(FULL, p, o);
        if (lane >= o) p += t;
    }
    if (lane == 31) wsum[wid] = p;
    __syncthreads();
    if (wid == 0) {
        int w = wsum[lane];
        #pragma unroll
        for (int o = 1; o < 32; o <<= 1) {
            int t = __shfl_up_sync(FULL, w, o);
            if (lane >= o) w += t;
        }
        wsum[lane] = w;
    }
    __syncthreads();
    int excl = (wid ? wsum[wid - 1] : 0) + p - v;
    if (i < Nn) g_rowptr[i] = excl;
    if (tid == 0) g_bsum[blockIdx.x] = wsum[31];
}
__global__ void scan_add() {
    __shared__ int soff;
    int tid = threadIdx.x;
    if (tid == 0) {
        int s = 0;
        for (int j = 0; j < (int)blockIdx.x; j++) s += g_bsum[j];
        soff = s;
    }
    __syncthreads();
    int i = blockIdx.x * 1024 + tid;
    if (i < Nn) {
        int val = g_rowptr[i] + soff;
        g_rowptr[i] = val;
        g_csr[val]  = i;          // self-loop at slot 0
    }
    if (i == 0) g_rowptr[Nn] = Etot;
}
__global__ void place_k(const int* __restrict__ ei) {
    int t = blockIdx.x * blockDim.x + threadIdx.x;
    if (t * 4 >= Ereal) return;
    int4 s4 = ((const int4*)ei)[t];
    int4 d4 = ((const int4*)(ei + Ereal))[t];
    int4 p4 = ((const int4*)g_epos)[t];
    g_csr[g_rowptr[d4.x] + p4.x] = s4.x;
    g_csr[g_rowptr[d4.y] + p4.y] = s4.y;
    g_csr[g_rowptr[d4.z] + p4.z] = s4.z;
    g_csr[g_rowptr[d4.w] + p4.w] = s4.w;
}

// ================= split-bf16 tensor-core GEMM (pre-split operands) =============
#define GS 12

__device__ __forceinline__ void mma_bf16(float (&c)[4], const unsigned* a, const unsigned* b) {
    asm volatile(
        "mma.sync.aligned.m16n8k16.row.col.f32.bf16.bf16.f32 "
        "{%0,%1,%2,%3}, {%4,%5,%6,%7}, {%8,%9}, {%0,%1,%2,%3};\n"
        : "+f"(c[0]), "+f"(c[1]), "+f"(c[2]), "+f"(c[3])
        : "r"(a[0]), "r"(a[1]), "r"(a[2]), "r"(a[3]), "r"(b[0]), "r"(b[1]));
}

// A: [M][K] bf16 hi/lo. B: transposed [N][K] bf16 hi/lo.
// BIAS_ELU: bias+ELU, write bf16 hi/lo (Ch/Cl, width N). ALPHA: write C fp32 + g_as/g_ad.
template<bool BIAS_ELU, bool ALPHA>
__global__ void __launch_bounds__(256) gemm_tc(const unsigned short* __restrict__ Ah,
                                               const unsigned short* __restrict__ Al,
                                               const unsigned short* __restrict__ Bh,
                                               const unsigned short* __restrict__ Bl,
                                               float* __restrict__ C,
                                               unsigned short* __restrict__ Ch,
                                               unsigned short* __restrict__ Cl,
                                               const float* __restrict__ bias,
                                               const float* __restrict__ av,
                                               const float* __restrict__ bv,
                                               int M, int K, int N) {
    __shared__ unsigned AsH[128 * GS];
    __shared__ unsigned AsL[128 * GS];
    __shared__ unsigned BsH[64 * GS];
    __shared__ unsigned BsL[64 * GS];

    const int br = blockIdx.y * 128;
    const int bn = blockIdx.x * 64;
    const int tid = threadIdx.x;
    const int lane = tid & 31;
    const int warp = tid >> 5;
    const int wm = (warp >> 1) * 32;
    const int wn = (warp & 1) * 32;

    float acc[2][4][4];
    #pragma unroll
    for (int m = 0; m < 2; m++)
        #pragma unroll
        for (int n = 0; n < 4; n++)
            #pragma unroll
            for (int r = 0; r < 4; r++) acc[m][n][r] = 0.f;

    const int q = lane >> 2;
    const int rr = lane & 3;

    const int aRow0 = tid >> 2,         aC0 = (tid & 3) * 4;    // 4 k-vals (1 uint2)
    const int aRow1 = (tid + 256) >> 2;
    const int bN    = tid >> 2,         bU = (tid & 3) * 4;     // 4 k-vals of row bn+bN

    const uint2 Z2 = make_uint2(0u, 0u);
    uint2 aRh[2], aRl[2], bRh, bRl;
    aRh[0] = (br + aRow0 < M) ? *(const uint2*)(Ah + (size_t)(br + aRow0) * K + aC0) : Z2;
    aRl[0] = (br + aRow0 < M) ? *(const uint2*)(Al + (size_t)(br + aRow0) * K + aC0) : Z2;
    aRh[1] = (br + aRow1 < M) ? *(const uint2*)(Ah + (size_t)(br + aRow1) * K + aC0) : Z2;
    aRl[1] = (br + aRow1 < M) ? *(const uint2*)(Al + (size_t)(br + aRow1) * K + aC0) : Z2;
    bRh = *(const uint2*)(Bh + (size_t)(bn + bN) * K + bU);
    bRl = *(const uint2*)(Bl + (size_t)(bn + bN) * K + bU);

    for (int k0 = 0; k0 < K; k0 += 16) {
        // ---- stage (pure copies) ----
        #pragma unroll
        for (int t = 0; t < 2; t++) {
            int o = (t ? aRow1 : aRow0) * GS + (aC0 >> 1);
            AsH[o] = aRh[t].x; AsH[o + 1] = aRh[t].y;
            AsL[o] = aRl[t].x; AsL[o + 1] = aRl[t].y;
        }
        {
            int o = bN * GS + (bU >> 1);
            BsH[o] = bRh.x; BsH[o + 1] = bRh.y;
            BsL[o] = bRl.x; BsL[o + 1] = bRl.y;
        }
        __syncthreads();

        if (k0 + 16 < K) {
            int kn = k0 + 16;
            aRh[0] = (br + aRow0 < M) ? *(const uint2*)(Ah + (size_t)(br + aRow0) * K + kn + aC0) : Z2;
            aRl[0] = (br + aRow0 < M) ? *(const uint2*)(Al + (size_t)(br + aRow0) * K + kn + aC0) : Z2;
            aRh[1] = (br + aRow1 < M) ? *(const uint2*)(Ah + (size_t)(br + aRow1) * K + kn + aC0) : Z2;
            aRl[1] = (br + aRow1 < M) ? *(const uint2*)(Al + (size_t)(br + aRow1) * K + kn + aC0) : Z2;
            bRh = *(const uint2*)(Bh + (size_t)(bn + bN) * K + kn + bU);
            bRl = *(const uint2*)(Bl + (size_t)(bn + bN) * K + kn + bU);
        }

        {
            unsigned ah[2][4], al[2][4], bh[4][2], bl[4][2];
            #pragma unroll
            for (int m = 0; m < 2; m++) {
                int r0 = (wm + m * 16 + q) * GS + rr;
                ah[m][0] = AsH[r0];
                ah[m][1] = AsH[r0 + 8 * GS];
                ah[m][2] = AsH[r0 + 4];
                ah[m][3] = AsH[r0 + 8 * GS + 4];
                al[m][0] = AsL[r0];
                al[m][1] = AsL[r0 + 8 * GS];
                al[m][2] = AsL[r0 + 4];
                al[m][3] = AsL[r0 + 8 * GS + 4];
            }
            #pragma unroll
            for (int n = 0; n < 4; n++) {
                int nb = (wn + n * 8 + q) * GS + rr;
                bh[n][0] = BsH[nb];
                bh[n][1] = BsH[nb + 4];
                bl[n][0] = BsL[nb];
                bl[n][1] = BsL[nb + 4];
            }
            #pragma unroll
            for (int m = 0; m < 2; m++)
                #pragma unroll
                for (int n = 0; n < 4; n++) {
                    mma_bf16(acc[m][n], ah[m], bh[n]);
                    mma_bf16(acc[m][n], ah[m], bl[n]);
                    mma_bf16(acc[m][n], al[m], bh[n]);
                }
        }
        __syncthreads();
    }

    #pragma unroll
    for (int m = 0; m < 2; m++) {
        int row0 = br + wm + m * 16 + q;
        #pragma unroll
        for (int n = 0; n < 4; n++) {
            int col = bn + wn + n * 8 + rr * 2;
            if (BIAS_ELU) {
                float b0 = bias[col], b1v = bias[col + 1];
                float r0x, r0y, r1x, r1y;
                float v0x = elu1(acc[m][n][0] + b0), v0y = elu1(acc[m][n][1] + b1v);
                float v1x = elu1(acc[m][n][2] + b0), v1y = elu1(acc[m][n][3] + b1v);
                if (row0 < M) {
                    *(unsigned*)(Ch + (size_t)row0 * N + col) = pack_hi(v0x, v0y, r0x, r0y);
                    *(unsigned*)(Cl + (size_t)row0 * N + col) = pack_bf(r0x, r0y);
                }
                if (row0 + 8 < M) {
                    *(unsigned*)(Ch + (size_t)(row0 + 8) * N + col) = pack_hi(v1x, v1y, r1x, r1y);
                    *(unsigned*)(Cl + (size_t)(row0 + 8) * N + col) = pack_bf(r1x, r1y);
                }
            } else {
                if (row0 < M)
                    *(float2*)(C + (size_t)row0 * N + col) = make_float2(acc[m][n][0], acc[m][n][1]);
                if (row0 + 8 < M)
                    *(float2*)(C + (size_t)(row0 + 8) * N + col) = make_float2(acc[m][n][2], acc[m][n][3]);
            }
        }
    }

    if (ALPHA) {
        float* sAs = (float*)AsH;
        float* sAd = sAs + 128;
        if (tid < 128) { sAs[tid] = 0.f; sAd[tid] = 0.f; }
        __syncthreads();
        #pragma unroll
        for (int m = 0; m < 2; m++) {
            float pa = 0.f, pd = 0.f, qa = 0.f, qd = 0.f;
            #pragma unroll
            for (int n = 0; n < 4; n++) {
                int col = wn + n * 8 + rr * 2;
                float a0 = av[col], a1 = av[col + 1];
                float d0 = bv[col], d1 = bv[col + 1];
                pa += acc[m][n][0] * a0 + acc[m][n][1] * a1;
                pd += acc[m][n][0] * d0 + acc[m][n][1] * d1;
                qa += acc[m][n][2] * a0 + acc[m][n][3] * a1;
                qd += acc[m][n][2] * d0 + acc[m][n][3] * d1;
            }
            int r = wm + m * 16 + q;
            atomicAdd(&sAs[r], pa);     atomicAdd(&sAd[r], pd);
            atomicAdd(&sAs[r + 8], qa); atomicAdd(&sAd[r + 8], qd);
        }
        __syncthreads();
        if (tid < 128 && br + tid < M) {
            g_as[br + tid] = sAs[tid];
            g_ad[br + tid] = sAd[tid];
        }
    }
}

// ---------------- agg layer 1: softmax-aggregate x, emit bf16 hi/lo ------------
__global__ void agg128_k(const float* __restrict__ x) {
    int gw   = (blockIdx.x * blockDim.x + threadIdx.x) >> 5;
    int lane = threadIdx.x & 31;
    if (gw >= Nn) return;
    const int start = g_rowptr[gw];
    const int end   = g_rowptr[gw + 1];
    const int deg   = end - start;
    const float adn = g_ad[gw];

    int i0 = 0, i1 = 0;
    float l0 = -3.0e38f, l1 = -3.0e38f;
    float m = -3.0e38f, s = 0.f;
    {
        int e = start + lane;
        if (e < end) { i0 = g_csr[e]; l0 = lrelu(g_as[i0] + adn); m = l0; s = 1.f; }
        if (e + 32 < end) {
            i1 = g_csr[e + 32];
            l1 = lrelu(g_as[i1] + adn);
            float mn = fmaxf(m, l1);
            s = s * __expf(m - mn) + __expf(l1 - mn);
            m = mn;
        }
        for (int e2 = e + 64; e2 < end; e2 += 32) {
            float l = lrelu(g_as[g_csr[e2]] + adn);
            float mn = fmaxf(m, l);
            s = s * __expf(m - mn) + __expf(l - mn);
            m = mn;
        }
    }
    #pragma unroll
    for (int off = 16; off; off >>= 1) {
        float mo = __shfl_xor_sync(FULL, m, off);
        float so = __shfl_xor_sync(FULL, s, off);
        float mn = fmaxf(m, mo);
        s = s * __expf(m - mn) + so * __expf(mo - mn);
        m = mn;
    }
    const float inv_den = 1.f / s;
    const float c0 = __expf(l0 - m) * inv_den;
    const float c1 = __expf(l1 - m) * inv_den;
    const int nreg = deg < 64 ? deg : 64;

    float4 a0 = make_float4(0.f, 0.f, 0.f, 0.f);
    int j = 0;
    for (; j + 8 <= nreg; j += 8) {
        float cs[8]; int ss[8];
        #pragma unroll
        for (int u = 0; u < 8; u++) {
            int idx = j + u, jj = idx & 31;
            float cc = (idx & 32) ? c1 : c0;
            int   ii = (idx & 32) ? i1 : i0;
            cs[u] = __shfl_sync(FULL, cc, jj);
            ss[u] = __shfl_sync(FULL, ii, jj);
        }
        float4 r[8];
        #pragma unroll
        for (int u = 0; u < 8; u++)
            r[u] = ((const float4*)(x + (size_t)ss[u] * 128))[lane];
        #pragma unroll
        for (int u = 0; u < 8; u++) {
            a0.x += cs[u] * r[u].x; a0.y += cs[u] * r[u].y;
            a0.z += cs[u] * r[u].z; a0.w += cs[u] * r[u].w;
        }
    }
    for (; j < nreg; j++) {
        int jj = j & 31;
        float cc = (j & 32) ? c1 : c0;
        int   ii = (j & 32) ? i1 : i0;
        float ca = __shfl_sync(FULL, cc, jj);
        int   s0 = __shfl_sync(FULL, ii, jj);
        float4 r0 = ((const float4*)(x + (size_t)s0 * 128))[lane];
        a0.x += ca * r0.x; a0.y += ca * r0.y; a0.z += ca * r0.z; a0.w += ca * r0.w;
    }
    for (int e2 = start + 64; e2 < end; e2++) {
        int sn = g_csr[e2];
        float c = __expf(lrelu(g_as[sn] + adn) - m) * inv_den;
        float4 r0 = ((const float4*)(x + (size_t)sn * 128))[lane];
        a0.x += c * r0.x; a0.y += c * r0.y; a0.z += c * r0.z; a0.w += c * r0.w;
    }
    // emit bf16 hi/lo
    float rx, ry, rz, rw;
    unsigned h01 = pack_hi(a0.x, a0.y, rx, ry);
    unsigned h23 = pack_hi(a0.z, a0.w, rz, rw);
    *(uint2*)(g_xh + (size_t)gw * 128 + lane * 4) = make_uint2(h01, h23);
    *(uint2*)(g_xl + (size_t)gw * 128 + lane * 4) = make_uint2(pack_bf(rx, ry), pack_bf(rz, rw));
}

// ---------------- agg layers 2/3 (warp per node) --------------------------------
template<int D>
__global__ void agg_k(const float* __restrict__ h, float* __restrict__ out,
                      const float* __restrict__ bias,
                      const float* __restrict__ W3,
                      const float* __restrict__ as3,
                      const float* __restrict__ ad3) {
    int gw   = (blockIdx.x * blockDim.x + threadIdx.x) >> 5;
    int lane = threadIdx.x & 31;
    if (gw >= Nn) return;
    const int start = g_rowptr[gw];
    const int end   = g_rowptr[gw + 1];
    const int deg   = end - start;
    const float adn = (D == 1) ? g_ad3[gw] : g_ad[gw];
    const float* asrc = (D == 1) ? g_as3 : g_as;

    int i0 = 0, i1 = 0;
    float l0 = -3.0e38f, l1 = -3.0e38f;
    float m = -3.0e38f, s = 0.f;
    {
        int e = start + lane;
        if (e < end) { i0 = g_csr[e]; l0 = lrelu(asrc[i0] + adn); m = l0; s = 1.f; }
        if (e + 32 < end) {
            i1 = g_csr[e + 32];
            l1 = lrelu(asrc[i1] + adn);
            float mn = fmaxf(m, l1);
            s = s * __expf(m - mn) + __expf(l1 - mn);
            m = mn;
        }
        for (int e2 = e + 64; e2 < end; e2 += 32) {
            float l = lrelu(asrc[g_csr[e2]] + adn);
            float mn = fmaxf(m, l);
            s = s * __expf(m - mn) + __expf(l - mn);
            m = mn;
        }
    }
    #pragma unroll
    for (int off = 16; off; off >>= 1) {
        float mo = __shfl_xor_sync(FULL, m, off);
        float so = __shfl_xor_sync(FULL, s, off);
        float mn = fmaxf(m, mo);
        s = s * __expf(m - mn) + so * __expf(mo - mn);
        m = mn;
    }
    const float inv_den = 1.f / s;
    const float c0 = __expf(l0 - m) * inv_den;
    const float c1 = __expf(l1 - m) * inv_den;
    const int nreg = deg < 64 ? deg : 64;

    if (D == 64) {
        float2 a = make_float2(0.f, 0.f);
        int j = 0;
        for (; j + 8 <= nreg; j += 8) {
            float cs[8]; int ss[8];
            #pragma unroll
            for (int u = 0; u < 8; u++) {
                int idx = j + u, jj = idx & 31;
                float cc = (idx & 32) ? c1 : c0;
                int   ii = (idx & 32) ? i1 : i0;
                cs[u] = __shfl_sync(FULL, cc, jj);
                ss[u] = __shfl_sync(FULL, ii, jj);
            }
            float2 r[8];
            #pragma unroll
            for (int u = 0; u < 8; u++)
                r[u] = ((const float2*)(h + (size_t)ss[u] * 64))[lane];
            #pragma unroll
            for (int u = 0; u < 8; u++) {
                a.x += cs[u] * r[u].x; a.y += cs[u] * r[u].y;
            }
        }
        for (; j < nreg; j++) {
            int jj = j & 31;
            float cc = (j & 32) ? c1 : c0;
            int   ii = (j & 32) ? i1 : i0;
            float ca = __shfl_sync(FULL, cc, jj);
            int   s0 = __shfl_sync(FULL, ii, jj);
            float2 r0 = ((const float2*)(h + (size_t)s0 * 64))[lane];
            a.x += ca * r0.x; a.y += ca * r0.y;
        }
        for (int e2 = start + 64; e2 < end; e2++) {
            int sn = g_csr[e2];
            float c = __expf(lrelu(asrc[sn] + adn) - m) * inv_den;
            float2 r0 = ((const float2*)(h + (size_t)sn * 64))[lane];
            a.x += c * r0.x; a.y += c * r0.y;
        }
        float2 bvv = ((const float2*)bias)[lane];
        a.x = elu1(a.x + bvv.x); a.y = elu1(a.y + bvv.y);
        float2 w = ((const float2*)W3)[lane];
        float dot = a.x * w.x + a.y * w.y;
        #pragma unroll
        for (int off = 16; off; off >>= 1) dot += __shfl_xor_sync(FULL, dot, off);
        if (lane == 0) {
            out[gw]   = dot;
            g_as3[gw] = dot * as3[0];
            g_ad3[gw] = dot * ad3[0];
        }
    } else { // D == 1
        float a = 0.f;
        for (int e = start + lane; e < end; e += 32) {
            int sn = g_csr[e];
            float c = __expf(lrelu(g_as3[sn] + adn) - m) * inv_den;
            a += c * h[sn];
        }
        #pragma unroll
        for (int off = 16; off; off >>= 1) a += __shfl_xor_sync(FULL, a, off);
        if (lane == 0) out[gw] = a + bias[0];
    }
}

// =============================== launcher ======================================
extern "C" void kernel_launch(void* const* d_in, const int* in_sizes, int n_in,
                              void* d_out, int out_size) {
    const float* x  = (const float*)d_in[0];
    const int*   ei = (const int*)d_in[1];
    const float *W1 = (const float*)d_in[2],  *as1 = (const float*)d_in[3],
                *ad1 = (const float*)d_in[4], *b1  = (const float*)d_in[5];
    const float *W2 = (const float*)d_in[6],  *as2 = (const float*)d_in[7],
                *ad2 = (const float*)d_in[8], *b2  = (const float*)d_in[9];
    const float *W3 = (const float*)d_in[10], *as3 = (const float*)d_in[11],
                *ad3 = (const float*)d_in[12], *b3 = (const float*)d_in[13];
    float* out = (float*)d_out;

    unsigned short *pxh, *pxl, *phh, *phl, *pw1h, *pw1l, *pw2h, *pw2l;
    float *po, *py;
    cudaGetSymbolAddress((void**)&pxh, g_xh);
    cudaGetSymbolAddress((void**)&pxl, g_xl);
    cudaGetSymbolAddress((void**)&phh, g_hh);
    cudaGetSymbolAddress((void**)&phl, g_hl);
    cudaGetSymbolAddress((void**)&pw1h, g_w1h);
    cudaGetSymbolAddress((void**)&pw1l, g_w1l);
    cudaGetSymbolAddress((void**)&pw2h, g_w2h);
    cudaGetSymbolAddress((void**)&pw2l, g_w2l);
    cudaGetSymbolAddress((void**)&po, g_o);
    cudaGetSymbolAddress((void**)&py, g_y);

    const int TB = 256;
    const int nodeBlocks  = (Nn + TB - 1) / TB;
    const int warpNodeBlk = (Nn * 32 + TB - 1) / TB;
    const int edge4Blk    = (Ereal / 4 + TB - 1) / TB;
    const int mRows = (Nn + 127) / 128;

    // ---- CSR build + weight prep + layer-1 alpha ----
    init_prep<<<nodeBlocks + 1 + W1BLK + W2BLK, TB>>>(W1, as1, ad1, W2, nodeBlocks);
    count_alpha<<<edge4Blk + warpNodeBlk, TB>>>(ei, x, edge4Blk);
    scan_blocks<<<NBLK, 1024>>>();
    scan_add<<<NBLK, 1024>>>();
    place_k<<<edge4Blk, TB>>>(ei);

    // ---- layer 1 (aggregate-then-transform): 128 -> 256 ----
    agg128_k<<<warpNodeBlk, TB>>>(x);
    {
        dim3 grid(D1 / 64, mRows);
        gemm_tc<true, false><<<grid, 256>>>(pxh, pxl, pw1h, pw1l, nullptr, phh, phl,
                                            b1, nullptr, nullptr, Nn, Cc, D1);
    }
    // ---- layer 2: 256 -> 64 ----
    {
        dim3 grid(D2 / 64, mRows);
        gemm_tc<false, true><<<grid, 256>>>(phh, phl, pw2h, pw2l, po, nullptr, nullptr,
                                            nullptr, as2, ad2, Nn, D1, D2);
        agg_k<64><<<warpNodeBlk, TB>>>(po, py, b2, W3, as3, ad3);
    }
    // ---- layer 3: 64 -> 1 ----
    agg_k<1><<<warpNodeBlk, TB>>>(py, out, b3, nullptr, nullptr, nullptr);
}

// round 11
// speedup vs baseline: 2.7432x; 1.0220x over previous
#include <cuda_runtime.h>
#include <cuda_bf16.h>
#include <math.h>

#define Nn     50000
#define Cc     128
#define D1     256
#define D2     64
#define Ereal  800000
#define Etot   (Ereal + Nn)
#define FULL   0xFFFFFFFFu
#define NBLK   ((Nn + 1023) / 1024)
#define AGGF   (1u << 30)
#define PREF   (1u << 31)
#define VMSK   0x3FFFFFFFu

// ---------------- scratch ------------------------------------------------------
__device__ unsigned short g_xh[(size_t)Nn * Cc];   // agg(x) hi/lo bf16 (GEMM1 A)
__device__ unsigned short g_xl[(size_t)Nn * Cc];
__device__ unsigned short g_hh[(size_t)Nn * D1];   // h hi/lo bf16 (GEMM2 A)
__device__ unsigned short g_hl[(size_t)Nn * D1];
__device__ unsigned short g_w1h[D1 * Cc];          // W1^T hi/lo  [n=256][k=128]
__device__ unsigned short g_w1l[D1 * Cc];
__device__ unsigned short g_w2h[D2 * D1];          // W2^T hi/lo  [n=64][k=256]
__device__ unsigned short g_w2l[D2 * D1];
__device__ float g_o [(size_t)Nn * D2];            // layer-2 GEMM out (fp32)
__device__ float g_y [Nn];                         // layer-3 input
__device__ float g_as[Nn];
__device__ float g_ad[Nn];
__device__ float g_as3[Nn];
__device__ float g_ad3[Nn];
__device__ float g_ps[Cc];
__device__ float g_pd[Cc];
__device__ int   g_cnt [Nn];      // zero-invariant between runs (scan resets)
__device__ int   g_epos[Ereal];
__device__ int   g_rowptr[Nn + 1];
__device__ int   g_csr[Etot];
__device__ unsigned g_bsum[64];   // lookback flags+values; reset by place_k

__device__ __forceinline__ unsigned short bf_hi(float v, float& r) {
    __nv_bfloat16 h = __float2bfloat16(v);
    r = v - __bfloat162float(h);
    return __bfloat16_as_ushort(h);
}
__device__ __forceinline__ unsigned short bf_of(float v) {
    return __bfloat16_as_ushort(__float2bfloat16(v));
}
__device__ __forceinline__ unsigned pack_hi(float a, float b, float& ra, float& rb) {
    unsigned ha = bf_hi(a, ra), hb = bf_hi(b, rb);
    return (hb << 16) | ha;
}
__device__ __forceinline__ unsigned pack_bf(float a, float b) {
    return ((unsigned)bf_of(b) << 16) | bf_of(a);
}
__device__ __forceinline__ float elu1(float v) { return v > 0.f ? v : expm1f(v); }
__device__ __forceinline__ float lrelu(float l) { return l > 0.f ? l : 0.2f * l; }

// ---------------- K1: edge count (first blocks) + weight split + p=W1@a --------
#define W1BLK 128   // 32768 / 256
#define W2BLK 64    // 16384 / 256
__global__ void prep_count(const int* __restrict__ ei,
                           const float* __restrict__ W1, const float* __restrict__ as1,
                           const float* __restrict__ ad1, const float* __restrict__ W2,
                           int edge4Blk) {
    int b = blockIdx.x;
    if (b < edge4Blk) {                              // edge counting starts first
        int t = b * blockDim.x + threadIdx.x;
        if (t * 4 >= Ereal) return;
        int4 d4 = ((const int4*)(ei + Ereal))[t];
        int e = t * 4;
        g_epos[e + 0] = atomicAdd(&g_cnt[d4.x], 1);  // cnt starts at 0 (invariant)
        g_epos[e + 1] = atomicAdd(&g_cnt[d4.y], 1);
        g_epos[e + 2] = atomicAdd(&g_cnt[d4.z], 1);
        g_epos[e + 3] = atomicAdd(&g_cnt[d4.w], 1);
    } else if (b < edge4Blk + W1BLK) {
        int idx = (b - edge4Blk) * 256 + threadIdx.x;          // [0, 32768)
        int n = idx >> 7, k = idx & 127;
        float v = W1[(size_t)k * D1 + n];
        float r;
        g_w1h[idx] = bf_hi(v, r);
        g_w1l[idx] = bf_of(r);
    } else if (b < edge4Blk + W1BLK + W2BLK) {
        int idx = (b - edge4Blk - W1BLK) * 256 + threadIdx.x;  // [0, 16384)
        int n = idx >> 8, k = idx & 255;
        float v = W2[(size_t)k * D2 + n];
        float r;
        g_w2h[idx] = bf_hi(v, r);
        g_w2l[idx] = bf_of(r);
    } else {
        int t = threadIdx.x;                          // p = W1 @ a
        const float* a = (t < Cc) ? as1 : ad1;
        int i = t & (Cc - 1);
        float s = 0.f;
        const float* row = W1 + (size_t)i * D1;
        for (int j = 0; j < D1; j++) s += row[j] * a[j];
        if (t < Cc) g_ps[i] = s; else g_pd[i] = s;
    }
}

// ---------------- K2: decoupled-lookback scan (+cnt reset, self-loop) + alpha ---
__global__ void scan_alpha(const float* __restrict__ x) {
    if ((int)blockIdx.x < NBLK) {
        __shared__ int wsum[32];
        __shared__ int bpref;
        int tid = threadIdx.x, lane = tid & 31, wid = tid >> 5;
        int i = blockIdx.x * 1024 + tid;
        int v = 0;
        if (i < Nn) {
            v = g_cnt[i] + 1;          // +1 self-loop
            g_cnt[i] = 0;              // restore zero-invariant for next run
        }
        int p = v;
        #pragma unroll
        for (int o = 1; o < 32; o <<= 1) {
            int t = __shfl_up_sync(FULL, p, o);
            if (lane >= o) p += t;
        }
        if (lane == 31) wsum[wid] = p;
        __syncthreads();
        if (wid == 0) {
            int w = wsum[lane];
            #pragma unroll
            for (int o = 1; o < 32; o <<= 1) {
                int t = __shfl_up_sync(FULL, w, o);
                if (lane >= o) w += t;
            }
            wsum[lane] = w;
        }
        __syncthreads();
        if (tid == 0) {
            unsigned total = (unsigned)wsum[31];
            if (blockIdx.x == 0) {
                atomicExch(&g_bsum[0], total | PREF);
                bpref = 0;
            } else {
                atomicExch(&g_bsum[blockIdx.x], total | AGGF);
                int pref = 0;
                int j = (int)blockIdx.x - 1;
                while (j >= 0) {
                    unsigned vv = *(volatile unsigned*)&g_bsum[j];
                    if (vv == 0u) continue;              // not published yet
                    pref += (int)(vv & VMSK);
                    if (vv & PREF) break;
                    j--;
                }
                atomicExch(&g_bsum[blockIdx.x], ((unsigned)pref + total) | PREF);
                bpref = pref;
            }
        }
        __syncthreads();
        int excl = bpref + (wid ? wsum[wid - 1] : 0) + p - v;
        if (i < Nn) {
            g_rowptr[i] = excl;
            g_csr[excl] = i;           // self-loop at slot 0
        }
        if (i == 0) g_rowptr[Nn] = Etot;
    } else {
        // layer-1 alpha: warp per node (32 warps per 1024-thread block)
        int gw = ((int)blockIdx.x - NBLK) * 32 + (threadIdx.x >> 5);
        int lane = threadIdx.x & 31;
        if (gw >= Nn) return;
        float4 v = ((const float4*)(x + (size_t)gw * Cc))[lane];
        float4 p = ((const float4*)g_ps)[lane];
        float4 q = ((const float4*)g_pd)[lane];
        float s1 = v.x * p.x + v.y * p.y + v.z * p.z + v.w * p.w;
        float s2 = v.x * q.x + v.y * q.y + v.z * q.z + v.w * q.w;
        #pragma unroll
        for (int o = 16; o; o >>= 1) {
            s1 += __shfl_xor_sync(FULL, s1, o);
            s2 += __shfl_xor_sync(FULL, s2, o);
        }
        if (lane == 0) { g_as[gw] = s1; g_ad[gw] = s2; }
    }
}

// ---------------- K3: place (slot +1 past self-loop) + bsum reset ---------------
__global__ void place_k(const int* __restrict__ ei) {
    if (blockIdx.x == 0 && threadIdx.x < 64) g_bsum[threadIdx.x] = 0u;
    int t = blockIdx.x * blockDim.x + threadIdx.x;
    if (t * 4 >= Ereal) return;
    int4 s4 = ((const int4*)ei)[t];
    int4 d4 = ((const int4*)(ei + Ereal))[t];
    int4 p4 = ((const int4*)g_epos)[t];
    g_csr[g_rowptr[d4.x] + 1 + p4.x] = s4.x;
    g_csr[g_rowptr[d4.y] + 1 + p4.y] = s4.y;
    g_csr[g_rowptr[d4.z] + 1 + p4.z] = s4.z;
    g_csr[g_rowptr[d4.w] + 1 + p4.w] = s4.w;
}

// ================= split-bf16 tensor-core GEMM (pre-split operands) =============
#define GS 12

__device__ __forceinline__ void mma_bf16(float (&c)[4], const unsigned* a, const unsigned* b) {
    asm volatile(
        "mma.sync.aligned.m16n8k16.row.col.f32.bf16.bf16.f32 "
        "{%0,%1,%2,%3}, {%4,%5,%6,%7}, {%8,%9}, {%0,%1,%2,%3};\n"
        : "+f"(c[0]), "+f"(c[1]), "+f"(c[2]), "+f"(c[3])
        : "r"(a[0]), "r"(a[1]), "r"(a[2]), "r"(a[3]), "r"(b[0]), "r"(b[1]));
}

template<bool BIAS_ELU, bool ALPHA>
__global__ void __launch_bounds__(256) gemm_tc(const unsigned short* __restrict__ Ah,
                                               const unsigned short* __restrict__ Al,
                                               const unsigned short* __restrict__ Bh,
                                               const unsigned short* __restrict__ Bl,
                                               float* __restrict__ C,
                                               unsigned short* __restrict__ Ch,
                                               unsigned short* __restrict__ Cl,
                                               const float* __restrict__ bias,
                                               const float* __restrict__ av,
                                               const float* __restrict__ bv,
                                               int M, int K, int N) {
    __shared__ unsigned AsH[128 * GS];
    __shared__ unsigned AsL[128 * GS];
    __shared__ unsigned BsH[64 * GS];
    __shared__ unsigned BsL[64 * GS];

    const int br = blockIdx.y * 128;
    const int bn = blockIdx.x * 64;
    const int tid = threadIdx.x;
    const int lane = tid & 31;
    const int warp = tid >> 5;
    const int wm = (warp >> 1) * 32;
    const int wn = (warp & 1) * 32;

    float acc[2][4][4];
    #pragma unroll
    for (int m = 0; m < 2; m++)
        #pragma unroll
        for (int n = 0; n < 4; n++)
            #pragma unroll
            for (int r = 0; r < 4; r++) acc[m][n][r] = 0.f;

    const int q = lane >> 2;
    const int rr = lane & 3;

    const int aRow0 = tid >> 2,         aC0 = (tid & 3) * 4;
    const int aRow1 = (tid + 256) >> 2;
    const int bN    = tid >> 2,         bU = (tid & 3) * 4;

    const uint2 Z2 = make_uint2(0u, 0u);
    uint2 aRh[2], aRl[2], bRh, bRl;
    aRh[0] = (br + aRow0 < M) ? *(const uint2*)(Ah + (size_t)(br + aRow0) * K + aC0) : Z2;
    aRl[0] = (br + aRow0 < M) ? *(const uint2*)(Al + (size_t)(br + aRow0) * K + aC0) : Z2;
    aRh[1] = (br + aRow1 < M) ? *(const uint2*)(Ah + (size_t)(br + aRow1) * K + aC0) : Z2;
    aRl[1] = (br + aRow1 < M) ? *(const uint2*)(Al + (size_t)(br + aRow1) * K + aC0) : Z2;
    bRh = *(const uint2*)(Bh + (size_t)(bn + bN) * K + bU);
    bRl = *(const uint2*)(Bl + (size_t)(bn + bN) * K + bU);

    for (int k0 = 0; k0 < K; k0 += 16) {
        #pragma unroll
        for (int t = 0; t < 2; t++) {
            int o = (t ? aRow1 : aRow0) * GS + (aC0 >> 1);
            AsH[o] = aRh[t].x; AsH[o + 1] = aRh[t].y;
            AsL[o] = aRl[t].x; AsL[o + 1] = aRl[t].y;
        }
        {
            int o = bN * GS + (bU >> 1);
            BsH[o] = bRh.x; BsH[o + 1] = bRh.y;
            BsL[o] = bRl.x; BsL[o + 1] = bRl.y;
        }
        __syncthreads();

        if (k0 + 16 < K) {
            int kn = k0 + 16;
            aRh[0] = (br + aRow0 < M) ? *(const uint2*)(Ah + (size_t)(br + aRow0) * K + kn + aC0) : Z2;
            aRl[0] = (br + aRow0 < M) ? *(const uint2*)(Al + (size_t)(br + aRow0) * K + kn + aC0) : Z2;
            aRh[1] = (br + aRow1 < M) ? *(const uint2*)(Ah + (size_t)(br + aRow1) * K + kn + aC0) : Z2;
            aRl[1] = (br + aRow1 < M) ? *(const uint2*)(Al + (size_t)(br + aRow1) * K + kn + aC0) : Z2;
            bRh = *(const uint2*)(Bh + (size_t)(bn + bN) * K + kn + bU);
            bRl = *(const uint2*)(Bl + (size_t)(bn + bN) * K + kn + bU);
        }

        {
            unsigned ah[2][4], al[2][4], bh[4][2], bl[4][2];
            #pragma unroll
            for (int m = 0; m < 2; m++) {
                int r0 = (wm + m * 16 + q) * GS + rr;
                ah[m][0] = AsH[r0];
                ah[m][1] = AsH[r0 + 8 * GS];
                ah[m][2] = AsH[r0 + 4];
                ah[m][3] = AsH[r0 + 8 * GS + 4];
                al[m][0] = AsL[r0];
                al[m][1] = AsL[r0 + 8 * GS];
                al[m][2] = AsL[r0 + 4];
                al[m][3] = AsL[r0 + 8 * GS + 4];
            }
            #pragma unroll
            for (int n = 0; n < 4; n++) {
                int nb = (wn + n * 8 + q) * GS + rr;
                bh[n][0] = BsH[nb];
                bh[n][1] = BsH[nb + 4];
                bl[n][0] = BsL[nb];
                bl[n][1] = BsL[nb + 4];
            }
            #pragma unroll
            for (int m = 0; m < 2; m++)
                #pragma unroll
                for (int n = 0; n < 4; n++) {
                    mma_bf16(acc[m][n], ah[m], bh[n]);
                    mma_bf16(acc[m][n], ah[m], bl[n]);
                    mma_bf16(acc[m][n], al[m], bh[n]);
                }
        }
        __syncthreads();
    }

    #pragma unroll
    for (int m = 0; m < 2; m++) {
        int row0 = br + wm + m * 16 + q;
        #pragma unroll
        for (int n = 0; n < 4; n++) {
            int col = bn + wn + n * 8 + rr * 2;
            if (BIAS_ELU) {
                float b0 = bias[col], b1v = bias[col + 1];
                float r0x, r0y, r1x, r1y;
                float v0x = elu1(acc[m][n][0] + b0), v0y = elu1(acc[m][n][1] + b1v);
                float v1x = elu1(acc[m][n][2] + b0), v1y = elu1(acc[m][n][3] + b1v);
                if (row0 < M) {
                    *(unsigned*)(Ch + (size_t)row0 * N + col) = pack_hi(v0x, v0y, r0x, r0y);
                    *(unsigned*)(Cl + (size_t)row0 * N + col) = pack_bf(r0x, r0y);
                }
                if (row0 + 8 < M) {
                    *(unsigned*)(Ch + (size_t)(row0 + 8) * N + col) = pack_hi(v1x, v1y, r1x, r1y);
                    *(unsigned*)(Cl + (size_t)(row0 + 8) * N + col) = pack_bf(r1x, r1y);
                }
            } else {
                if (row0 < M)
                    *(float2*)(C + (size_t)row0 * N + col) = make_float2(acc[m][n][0], acc[m][n][1]);
                if (row0 + 8 < M)
                    *(float2*)(C + (size_t)(row0 + 8) * N + col) = make_float2(acc[m][n][2], acc[m][n][3]);
            }
        }
    }

    if (ALPHA) {
        float* sAs = (float*)AsH;
        float* sAd = sAs + 128;
        if (tid < 128) { sAs[tid] = 0.f; sAd[tid] = 0.f; }
        __syncthreads();
        #pragma unroll
        for (int m = 0; m < 2; m++) {
            float pa = 0.f, pd = 0.f, qa = 0.f, qd = 0.f;
            #pragma unroll
            for (int n = 0; n < 4; n++) {
                int col = wn + n * 8 + rr * 2;
                float a0 = av[col], a1 = av[col + 1];
                float d0 = bv[col], d1 = bv[col + 1];
                pa += acc[m][n][0] * a0 + acc[m][n][1] * a1;
                pd += acc[m][n][0] * d0 + acc[m][n][1] * d1;
                qa += acc[m][n][2] * a0 + acc[m][n][3] * a1;
                qd += acc[m][n][2] * d0 + acc[m][n][3] * d1;
            }
            int r = wm + m * 16 + q;
            atomicAdd(&sAs[r], pa);     atomicAdd(&sAd[r], pd);
            atomicAdd(&sAs[r + 8], qa); atomicAdd(&sAd[r + 8], qd);
        }
        __syncthreads();
        if (tid < 128 && br + tid < M) {
            g_as[br + tid] = sAs[tid];
            g_ad[br + tid] = sAd[tid];
        }
    }
}

// ---------------- agg layer 1: softmax-aggregate x, emit bf16 hi/lo ------------
__global__ void agg128_k(const float* __restrict__ x) {
    int gw   = (blockIdx.x * blockDim.x + threadIdx.x) >> 5;
    int lane = threadIdx.x & 31;
    if (gw >= Nn) return;
    const int start = g_rowptr[gw];
    const int end   = g_rowptr[gw + 1];
    const int deg   = end - start;
    const float adn = g_ad[gw];

    int i0 = 0, i1 = 0;
    float l0 = -3.0e38f, l1 = -3.0e38f;
    float m = -3.0e38f, s = 0.f;
    {
        int e = start + lane;
        if (e < end) { i0 = g_csr[e]; l0 = lrelu(g_as[i0] + adn); m = l0; s = 1.f; }
        if (e + 32 < end) {
            i1 = g_csr[e + 32];
            l1 = lrelu(g_as[i1] + adn);
            float mn = fmaxf(m, l1);
            s = s * __expf(m - mn) + __expf(l1 - mn);
            m = mn;
        }
        for (int e2 = e + 64; e2 < end; e2 += 32) {
            float l = lrelu(g_as[g_csr[e2]] + adn);
            float mn = fmaxf(m, l);
            s = s * __expf(m - mn) + __expf(l - mn);
            m = mn;
        }
    }
    #pragma unroll
    for (int off = 16; off; off >>= 1) {
        float mo = __shfl_xor_sync(FULL, m, off);
        float so = __shfl_xor_sync(FULL, s, off);
        float mn = fmaxf(m, mo);
        s = s * __expf(m - mn) + so * __expf(mo - mn);
        m = mn;
    }
    const float inv_den = 1.f / s;
    const float c0 = __expf(l0 - m) * inv_den;
    const float c1 = __expf(l1 - m) * inv_den;
    const int nreg = deg < 64 ? deg : 64;

    float4 a0 = make_float4(0.f, 0.f, 0.f, 0.f);
    int j = 0;
    for (; j + 8 <= nreg; j += 8) {
        float cs[8]; int ss[8];
        #pragma unroll
        for (int u = 0; u < 8; u++) {
            int idx = j + u, jj = idx & 31;
            float cc = (idx & 32) ? c1 : c0;
            int   ii = (idx & 32) ? i1 : i0;
            cs[u] = __shfl_sync(FULL, cc, jj);
            ss[u] = __shfl_sync(FULL, ii, jj);
        }
        float4 r[8];
        #pragma unroll
        for (int u = 0; u < 8; u++)
            r[u] = ((const float4*)(x + (size_t)ss[u] * 128))[lane];
        #pragma unroll
        for (int u = 0; u < 8; u++) {
            a0.x += cs[u] * r[u].x; a0.y += cs[u] * r[u].y;
            a0.z += cs[u] * r[u].z; a0.w += cs[u] * r[u].w;
        }
    }
    for (; j < nreg; j++) {
        int jj = j & 31;
        float cc = (j & 32) ? c1 : c0;
        int   ii = (j & 32) ? i1 : i0;
        float ca = __shfl_sync(FULL, cc, jj);
        int   s0 = __shfl_sync(FULL, ii, jj);
        float4 r0 = ((const float4*)(x + (size_t)s0 * 128))[lane];
        a0.x += ca * r0.x; a0.y += ca * r0.y; a0.z += ca * r0.z; a0.w += ca * r0.w;
    }
    for (int e2 = start + 64; e2 < end; e2++) {
        int sn = g_csr[e2];
        float c = __expf(lrelu(g_as[sn] + adn) - m) * inv_den;
        float4 r0 = ((const float4*)(x + (size_t)sn * 128))[lane];
        a0.x += c * r0.x; a0.y += c * r0.y; a0.z += c * r0.z; a0.w += c * r0.w;
    }
    float rx, ry, rz, rw;
    unsigned h01 = pack_hi(a0.x, a0.y, rx, ry);
    unsigned h23 = pack_hi(a0.z, a0.w, rz, rw);
    *(uint2*)(g_xh + (size_t)gw * 128 + lane * 4) = make_uint2(h01, h23);
    *(uint2*)(g_xl + (size_t)gw * 128 + lane * 4) = make_uint2(pack_bf(rx, ry), pack_bf(rz, rw));
}

// ---------------- agg layers 2/3 (warp per node) --------------------------------
template<int D>
__global__ void agg_k(const float* __restrict__ h, float* __restrict__ out,
                      const float* __restrict__ bias,
                      const float* __restrict__ W3,
                      const float* __restrict__ as3,
                      const float* __restrict__ ad3) {
    int gw   = (blockIdx.x * blockDim.x + threadIdx.x) >> 5;
    int lane = threadIdx.x & 31;
    if (gw >= Nn) return;
    const int start = g_rowptr[gw];
    const int end   = g_rowptr[gw + 1];
    const int deg   = end - start;
    const float adn = (D == 1) ? g_ad3[gw] : g_ad[gw];
    const float* asrc = (D == 1) ? g_as3 : g_as;

    int i0 = 0, i1 = 0;
    float l0 = -3.0e38f, l1 = -3.0e38f;
    float m = -3.0e38f, s = 0.f;
    {
        int e = start + lane;
        if (e < end) { i0 = g_csr[e]; l0 = lrelu(asrc[i0] + adn); m = l0; s = 1.f; }
        if (e + 32 < end) {
            i1 = g_csr[e + 32];
            l1 = lrelu(asrc[i1] + adn);
            float mn = fmaxf(m, l1);
            s = s * __expf(m - mn) + __expf(l1 - mn);
            m = mn;
        }
        for (int e2 = e + 64; e2 < end; e2 += 32) {
            float l = lrelu(asrc[g_csr[e2]] + adn);
            float mn = fmaxf(m, l);
            s = s * __expf(m - mn) + __expf(l - mn);
            m = mn;
        }
    }
    #pragma unroll
    for (int off = 16; off; off >>= 1) {
        float mo = __shfl_xor_sync(FULL, m, off);
        float so = __shfl_xor_sync(FULL, s, off);
        float mn = fmaxf(m, mo);
        s = s * __expf(m - mn) + so * __expf(mo - mn);
        m = mn;
    }
    const float inv_den = 1.f / s;
    const float c0 = __expf(l0 - m) * inv_den;
    const float c1 = __expf(l1 - m) * inv_den;
    const int nreg = deg < 64 ? deg : 64;

    if (D == 64) {
        float2 a = make_float2(0.f, 0.f);
        int j = 0;
        for (; j + 8 <= nreg; j += 8) {
            float cs[8]; int ss[8];
            #pragma unroll
            for (int u = 0; u < 8; u++) {
                int idx = j + u, jj = idx & 31;
                float cc = (idx & 32) ? c1 : c0;
                int   ii = (idx & 32) ? i1 : i0;
                cs[u] = __shfl_sync(FULL, cc, jj);
                ss[u] = __shfl_sync(FULL, ii, jj);
            }
            float2 r[8];
            #pragma unroll
            for (int u = 0; u < 8; u++)
                r[u] = ((const float2*)(h + (size_t)ss[u] * 64))[lane];
            #pragma unroll
            for (int u = 0; u < 8; u++) {
                a.x += cs[u] * r[u].x; a.y += cs[u] * r[u].y;
            }
        }
        for (; j < nreg; j++) {
            int jj = j & 31;
            float cc = (j & 32) ? c1 : c0;
            int   ii = (j & 32) ? i1 : i0;
            float ca = __shfl_sync(FULL, cc, jj);
            int   s0 = __shfl_sync(FULL, ii, jj);
            float2 r0 = ((const float2*)(h + (size_t)s0 * 64))[lane];
            a.x += ca * r0.x; a.y += ca * r0.y;
        }
        for (int e2 = start + 64; e2 < end; e2++) {
            int sn = g_csr[e2];
            float c = __expf(lrelu(asrc[sn] + adn) - m) * inv_den;
            float2 r0 = ((const float2*)(h + (size_t)sn * 64))[lane];
            a.x += c * r0.x; a.y += c * r0.y;
        }
        float2 bvv = ((const float2*)bias)[lane];
        a.x = elu1(a.x + bvv.x); a.y = elu1(a.y + bvv.y);
        float2 w = ((const float2*)W3)[lane];
        float dot = a.x * w.x + a.y * w.y;
        #pragma unroll
        for (int off = 16; off; off >>= 1) dot += __shfl_xor_sync(FULL, dot, off);
        if (lane == 0) {
            out[gw]   = dot;
            g_as3[gw] = dot * as3[0];
            g_ad3[gw] = dot * ad3[0];
        }
    } else { // D == 1
        float a = 0.f;
        for (int e = start + lane; e < end; e += 32) {
            int sn = g_csr[e];
            float c = __expf(lrelu(g_as3[sn] + adn) - m) * inv_den;
            a += c * h[sn];
        }
        #pragma unroll
        for (int off = 16; off; off >>= 1) a += __shfl_xor_sync(FULL, a, off);
        if (lane == 0) out[gw] = a + bias[0];
    }
}

// =============================== launcher ======================================
extern "C" void kernel_launch(void* const* d_in, const int* in_sizes, int n_in,
                              void* d_out, int out_size) {
    const float* x  = (const float*)d_in[0];
    const int*   ei = (const int*)d_in[1];
    const float *W1 = (const float*)d_in[2],  *as1 = (const float*)d_in[3],
                *ad1 = (const float*)d_in[4], *b1  = (const float*)d_in[5];
    const float *W2 = (const float*)d_in[6],  *as2 = (const float*)d_in[7],
                *ad2 = (const float*)d_in[8], *b2  = (const float*)d_in[9];
    const float *W3 = (const float*)d_in[10], *as3 = (const float*)d_in[11],
                *ad3 = (const float*)d_in[12], *b3 = (const float*)d_in[13];
    float* out = (float*)d_out;

    unsigned short *pxh, *pxl, *phh, *phl, *pw1h, *pw1l, *pw2h, *pw2l;
    float *po, *py;
    cudaGetSymbolAddress((void**)&pxh, g_xh);
    cudaGetSymbolAddress((void**)&pxl, g_xl);
    cudaGetSymbolAddress((void**)&phh, g_hh);
    cudaGetSymbolAddress((void**)&phl, g_hl);
    cudaGetSymbolAddress((void**)&pw1h, g_w1h);
    cudaGetSymbolAddress((void**)&pw1l, g_w1l);
    cudaGetSymbolAddress((void**)&pw2h, g_w2h);
    cudaGetSymbolAddress((void**)&pw2l, g_w2l);
    cudaGetSymbolAddress((void**)&po, g_o);
    cudaGetSymbolAddress((void**)&py, g_y);

    const int TB = 256;
    const int warpNodeBlk = (Nn * 32 + TB - 1) / TB;
    const int edge4Blk    = (Ereal / 4 + TB - 1) / TB;
    const int alphaBlk    = (Nn + 31) / 32;          // 1024-thread blocks, warp/node
    const int mRows = (Nn + 127) / 128;

    // ---- K1: count (first) + weight split + p=W1@a ----
    prep_count<<<edge4Blk + W1BLK + W2BLK + 1, TB>>>(ei, W1, as1, ad1, W2, edge4Blk);
    // ---- K2: lookback scan (+cnt reset, self-loops) + layer-1 alpha ----
    scan_alpha<<<NBLK + alphaBlk, 1024>>>(x);
    // ---- K3: place edges ----
    place_k<<<edge4Blk, TB>>>(ei);

    // ---- layer 1 (aggregate-then-transform): 128 -> 256 ----
    agg128_k<<<warpNodeBlk, TB>>>(x);
    {
        dim3 grid(D1 / 64, mRows);
        gemm_tc<true, false><<<grid, 256>>>(pxh, pxl, pw1h, pw1l, nullptr, phh, phl,
                                            b1, nullptr, nullptr, Nn, Cc, D1);
    }
    // ---- layer 2: 256 -> 64 ----
    {
        dim3 grid(D2 / 64, mRows);
        gemm_tc<false, true><<<grid, 256>>>(phh, phl, pw2h, pw2l, po, nullptr, nullptr,
                                            nullptr, as2, ad2, Nn, D1, D2);
        agg_k<64><<<warpNodeBlk, TB>>>(po, py, b2, W3, as3, ad3);
    }
    // ---- layer 3: 64 -> 1 ----
    agg_k<1><<<warpNodeBlk, TB>>>(py, out, b3, nullptr, nullptr, nullptr);
}

// round 12
// speedup vs baseline: 2.9356x; 1.0701x over previous
#include <cuda_runtime.h>
#include <cuda_bf16.h>
#include <math.h>

#define Nn     50000
#define Cc     128
#define D1     256
#define D2     64
#define Ereal  800000
#define Etot   (Ereal + Nn)
#define FULL   0xFFFFFFFFu
#define NBLK   ((Nn + 1023) / 1024)
#define AGGF   (1u << 30)
#define PREF   (1u << 31)
#define VMSK   0x3FFFFFFFu

// ---------------- scratch ------------------------------------------------------
__device__ unsigned short g_xh[(size_t)Nn * Cc];   // agg(x) hi/lo bf16 (GEMM1 A)
__device__ unsigned short g_xl[(size_t)Nn * Cc];
__device__ unsigned short g_hh[(size_t)Nn * D1];   // h hi/lo bf16 (GEMM2 A)
__device__ unsigned short g_hl[(size_t)Nn * D1];
__device__ unsigned short g_w1h[D1 * Cc];          // W1^T hi/lo  [n=256][k=128]
__device__ unsigned short g_w1l[D1 * Cc];
__device__ unsigned short g_w2h[D2 * D1];          // W2^T hi/lo  [n=64][k=256]
__device__ unsigned short g_w2l[D2 * D1];
__device__ float g_o [(size_t)Nn * D2];            // layer-2 GEMM out (fp32)
__device__ float g_y [Nn];                         // layer-3 input
__device__ float g_as[Nn];
__device__ float g_ad[Nn];
__device__ float g_as3[Nn];
__device__ float g_ad3[Nn];
__device__ float g_ps[Cc];
__device__ float g_pd[Cc];
__device__ int   g_cnt [Nn];      // zero-invariant between runs (scan resets)
__device__ int   g_epos[Ereal];
__device__ int   g_rowptr[Nn + 1];
__device__ int   g_csr[Etot];
__device__ unsigned g_bsum[64];   // lookback flags+values; reset by place_k

__device__ __forceinline__ unsigned short bf_hi(float v, float& r) {
    __nv_bfloat16 h = __float2bfloat16(v);
    r = v - __bfloat162float(h);
    return __bfloat16_as_ushort(h);
}
__device__ __forceinline__ unsigned short bf_of(float v) {
    return __bfloat16_as_ushort(__float2bfloat16(v));
}
__device__ __forceinline__ unsigned pack_hi(float a, float b, float& ra, float& rb) {
    unsigned ha = bf_hi(a, ra), hb = bf_hi(b, rb);
    return (hb << 16) | ha;
}
__device__ __forceinline__ unsigned pack_bf(float a, float b) {
    return ((unsigned)bf_of(b) << 16) | bf_of(a);
}
__device__ __forceinline__ float elu1(float v) { return v > 0.f ? v : expm1f(v); }
__device__ __forceinline__ float lrelu(float l) { return l > 0.f ? l : 0.2f * l; }

// ---------------- K1: edge count (first blocks) + weight split + p=W1@a --------
#define W1BLK 128   // 32768 / 256
#define W2BLK 64    // 16384 / 256
__global__ void prep_count(const int* __restrict__ ei,
                           const float* __restrict__ W1, const float* __restrict__ as1,
                           const float* __restrict__ ad1, const float* __restrict__ W2,
                           int edge4Blk) {
    int b = blockIdx.x;
    if (b < edge4Blk) {
        int t = b * blockDim.x + threadIdx.x;
        if (t * 4 >= Ereal) return;
        int4 d4 = ((const int4*)(ei + Ereal))[t];
        int e = t * 4;
        g_epos[e + 0] = atomicAdd(&g_cnt[d4.x], 1);
        g_epos[e + 1] = atomicAdd(&g_cnt[d4.y], 1);
        g_epos[e + 2] = atomicAdd(&g_cnt[d4.z], 1);
        g_epos[e + 3] = atomicAdd(&g_cnt[d4.w], 1);
    } else if (b < edge4Blk + W1BLK) {
        int idx = (b - edge4Blk) * 256 + threadIdx.x;          // [0, 32768)
        int n = idx >> 7, k = idx & 127;
        float v = W1[(size_t)k * D1 + n];
        float r;
        g_w1h[idx] = bf_hi(v, r);
        g_w1l[idx] = bf_of(r);
    } else if (b < edge4Blk + W1BLK + W2BLK) {
        int idx = (b - edge4Blk - W1BLK) * 256 + threadIdx.x;  // [0, 16384)
        int n = idx >> 8, k = idx & 255;
        float v = W2[(size_t)k * D2 + n];
        float r;
        g_w2h[idx] = bf_hi(v, r);
        g_w2l[idx] = bf_of(r);
    } else {
        int t = threadIdx.x;                          // p = W1 @ a
        const float* a = (t < Cc) ? as1 : ad1;
        int i = t & (Cc - 1);
        float s = 0.f;
        const float* row = W1 + (size_t)i * D1;
        for (int j = 0; j < D1; j++) s += row[j] * a[j];
        if (t < Cc) g_ps[i] = s; else g_pd[i] = s;
    }
}

// ---------------- K2: decoupled-lookback scan (+cnt reset, self-loop) + alpha ---
__global__ void scan_alpha(const float* __restrict__ x) {
    if ((int)blockIdx.x < NBLK) {
        __shared__ int wsum[32];
        __shared__ int bpref;
        int tid = threadIdx.x, lane = tid & 31, wid = tid >> 5;
        int i = blockIdx.x * 1024 + tid;
        int v = 0;
        if (i < Nn) {
            v = g_cnt[i] + 1;          // +1 self-loop
            g_cnt[i] = 0;              // restore zero-invariant
        }
        int p = v;
        #pragma unroll
        for (int o = 1; o < 32; o <<= 1) {
            int t = __shfl_up_sync(FULL, p, o);
            if (lane >= o) p += t;
        }
        if (lane == 31) wsum[wid] = p;
        __syncthreads();
        if (wid == 0) {
            int w = wsum[lane];
            #pragma unroll
            for (int o = 1; o < 32; o <<= 1) {
                int t = __shfl_up_sync(FULL, w, o);
                if (lane >= o) w += t;
            }
            wsum[lane] = w;
        }
        __syncthreads();
        if (tid == 0) {
            unsigned total = (unsigned)wsum[31];
            if (blockIdx.x == 0) {
                atomicExch(&g_bsum[0], total | PREF);
                bpref = 0;
            } else {
                atomicExch(&g_bsum[blockIdx.x], total | AGGF);
                int pref = 0;
                int j = (int)blockIdx.x - 1;
                while (j >= 0) {
                    unsigned vv = *(volatile unsigned*)&g_bsum[j];
                    if (vv == 0u) continue;
                    pref += (int)(vv & VMSK);
                    if (vv & PREF) break;
                    j--;
                }
                atomicExch(&g_bsum[blockIdx.x], ((unsigned)pref + total) | PREF);
                bpref = pref;
            }
        }
        __syncthreads();
        int excl = bpref + (wid ? wsum[wid - 1] : 0) + p - v;
        if (i < Nn) {
            g_rowptr[i] = excl;
            g_csr[excl] = i;           // self-loop at slot 0
        }
        if (i == 0) g_rowptr[Nn] = Etot;
    } else {
        int gw = ((int)blockIdx.x - NBLK) * 32 + (threadIdx.x >> 5);
        int lane = threadIdx.x & 31;
        if (gw >= Nn) return;
        float4 v = ((const float4*)(x + (size_t)gw * Cc))[lane];
        float4 p = ((const float4*)g_ps)[lane];
        float4 q = ((const float4*)g_pd)[lane];
        float s1 = v.x * p.x + v.y * p.y + v.z * p.z + v.w * p.w;
        float s2 = v.x * q.x + v.y * q.y + v.z * q.z + v.w * q.w;
        #pragma unroll
        for (int o = 16; o; o >>= 1) {
            s1 += __shfl_xor_sync(FULL, s1, o);
            s2 += __shfl_xor_sync(FULL, s2, o);
        }
        if (lane == 0) { g_as[gw] = s1; g_ad[gw] = s2; }
    }
}

// ---------------- K3: place (slot +1 past self-loop) + bsum reset ---------------
__global__ void place_k(const int* __restrict__ ei) {
    if (blockIdx.x == 0 && threadIdx.x < 64) g_bsum[threadIdx.x] = 0u;
    int t = blockIdx.x * blockDim.x + threadIdx.x;
    if (t * 4 >= Ereal) return;
    int4 s4 = ((const int4*)ei)[t];
    int4 d4 = ((const int4*)(ei + Ereal))[t];
    int4 p4 = ((const int4*)g_epos)[t];
    g_csr[g_rowptr[d4.x] + 1 + p4.x] = s4.x;
    g_csr[g_rowptr[d4.y] + 1 + p4.y] = s4.y;
    g_csr[g_rowptr[d4.z] + 1 + p4.z] = s4.z;
    g_csr[g_rowptr[d4.w] + 1 + p4.w] = s4.w;
}

// ================= split-bf16 tensor-core GEMM (pre-split operands) =============
#define GS 12

__device__ __forceinline__ void mma_bf16(float (&c)[4], const unsigned* a, const unsigned* b) {
    asm volatile(
        "mma.sync.aligned.m16n8k16.row.col.f32.bf16.bf16.f32 "
        "{%0,%1,%2,%3}, {%4,%5,%6,%7}, {%8,%9}, {%0,%1,%2,%3};\n"
        : "+f"(c[0]), "+f"(c[1]), "+f"(c[2]), "+f"(c[3])
        : "r"(a[0]), "r"(a[1]), "r"(a[2]), "r"(a[3]), "r"(b[0]), "r"(b[1]));
}

template<bool BIAS_ELU, bool ALPHA>
__global__ void __launch_bounds__(256) gemm_tc(const unsigned short* __restrict__ Ah,
                                               const unsigned short* __restrict__ Al,
                                               const unsigned short* __restrict__ Bh,
                                               const unsigned short* __restrict__ Bl,
                                               float* __restrict__ C,
                                               unsigned short* __restrict__ Ch,
                                               unsigned short* __restrict__ Cl,
                                               const float* __restrict__ bias,
                                               const float* __restrict__ av,
                                               const float* __restrict__ bv,
                                               int M, int K, int N) {
    __shared__ unsigned AsH[128 * GS];
    __shared__ unsigned AsL[128 * GS];
    __shared__ unsigned BsH[64 * GS];
    __shared__ unsigned BsL[64 * GS];

    const int br = blockIdx.y * 128;
    const int bn = blockIdx.x * 64;
    const int tid = threadIdx.x;
    const int lane = tid & 31;
    const int warp = tid >> 5;
    const int wm = (warp >> 1) * 32;
    const int wn = (warp & 1) * 32;

    float acc[2][4][4];
    #pragma unroll
    for (int m = 0; m < 2; m++)
        #pragma unroll
        for (int n = 0; n < 4; n++)
            #pragma unroll
            for (int r = 0; r < 4; r++) acc[m][n][r] = 0.f;

    const int q = lane >> 2;
    const int rr = lane & 3;

    const int aRow0 = tid >> 2,         aC0 = (tid & 3) * 4;
    const int aRow1 = (tid + 256) >> 2;
    const int bN    = tid >> 2,         bU = (tid & 3) * 4;

    const uint2 Z2 = make_uint2(0u, 0u);
    uint2 aRh[2], aRl[2], bRh, bRl;
    aRh[0] = (br + aRow0 < M) ? *(const uint2*)(Ah + (size_t)(br + aRow0) * K + aC0) : Z2;
    aRl[0] = (br + aRow0 < M) ? *(const uint2*)(Al + (size_t)(br + aRow0) * K + aC0) : Z2;
    aRh[1] = (br + aRow1 < M) ? *(const uint2*)(Ah + (size_t)(br + aRow1) * K + aC0) : Z2;
    aRl[1] = (br + aRow1 < M) ? *(const uint2*)(Al + (size_t)(br + aRow1) * K + aC0) : Z2;
    bRh = *(const uint2*)(Bh + (size_t)(bn + bN) * K + bU);
    bRl = *(const uint2*)(Bl + (size_t)(bn + bN) * K + bU);

    for (int k0 = 0; k0 < K; k0 += 16) {
        #pragma unroll
        for (int t = 0; t < 2; t++) {
            int o = (t ? aRow1 : aRow0) * GS + (aC0 >> 1);
            AsH[o] = aRh[t].x; AsH[o + 1] = aRh[t].y;
            AsL[o] = aRl[t].x; AsL[o + 1] = aRl[t].y;
        }
        {
            int o = bN * GS + (bU >> 1);
            BsH[o] = bRh.x; BsH[o + 1] = bRh.y;
            BsL[o] = bRl.x; BsL[o + 1] = bRl.y;
        }
        __syncthreads();

        if (k0 + 16 < K) {
            int kn = k0 + 16;
            aRh[0] = (br + aRow0 < M) ? *(const uint2*)(Ah + (size_t)(br + aRow0) * K + kn + aC0) : Z2;
            aRl[0] = (br + aRow0 < M) ? *(const uint2*)(Al + (size_t)(br + aRow0) * K + kn + aC0) : Z2;
            aRh[1] = (br + aRow1 < M) ? *(const uint2*)(Ah + (size_t)(br + aRow1) * K + kn + aC0) : Z2;
            aRl[1] = (br + aRow1 < M) ? *(const uint2*)(Al + (size_t)(br + aRow1) * K + kn + aC0) : Z2;
            bRh = *(const uint2*)(Bh + (size_t)(bn + bN) * K + kn + bU);
            bRl = *(const uint2*)(Bl + (size_t)(bn + bN) * K + kn + bU);
        }

        {
            unsigned ah[2][4], al[2][4], bh[4][2], bl[4][2];
            #pragma unroll
            for (int m = 0; m < 2; m++) {
                int r0 = (wm + m * 16 + q) * GS + rr;
                ah[m][0] = AsH[r0];
                ah[m][1] = AsH[r0 + 8 * GS];
                ah[m][2] = AsH[r0 + 4];
                ah[m][3] = AsH[r0 + 8 * GS + 4];
                al[m][0] = AsL[r0];
                al[m][1] = AsL[r0 + 8 * GS];
                al[m][2] = AsL[r0 + 4];
                al[m][3] = AsL[r0 + 8 * GS + 4];
            }
            #pragma unroll
            for (int n = 0; n < 4; n++) {
                int nb = (wn + n * 8 + q) * GS + rr;
                bh[n][0] = BsH[nb];
                bh[n][1] = BsH[nb + 4];
                bl[n][0] = BsL[nb];
                bl[n][1] = BsL[nb + 4];
            }
            #pragma unroll
            for (int m = 0; m < 2; m++)
                #pragma unroll
                for (int n = 0; n < 4; n++) {
                    mma_bf16(acc[m][n], ah[m], bh[n]);
                    mma_bf16(acc[m][n], ah[m], bl[n]);
                    mma_bf16(acc[m][n], al[m], bh[n]);
                }
        }
        __syncthreads();
    }

    #pragma unroll
    for (int m = 0; m < 2; m++) {
        int row0 = br + wm + m * 16 + q;
        #pragma unroll
        for (int n = 0; n < 4; n++) {
            int col = bn + wn + n * 8 + rr * 2;
            if (BIAS_ELU) {
                float b0 = bias[col], b1v = bias[col + 1];
                float r0x, r0y, r1x, r1y;
                float v0x = elu1(acc[m][n][0] + b0), v0y = elu1(acc[m][n][1] + b1v);
                float v1x = elu1(acc[m][n][2] + b0), v1y = elu1(acc[m][n][3] + b1v);
                if (row0 < M) {
                    *(unsigned*)(Ch + (size_t)row0 * N + col) = pack_hi(v0x, v0y, r0x, r0y);
                    *(unsigned*)(Cl + (size_t)row0 * N + col) = pack_bf(r0x, r0y);
                }
                if (row0 + 8 < M) {
                    *(unsigned*)(Ch + (size_t)(row0 + 8) * N + col) = pack_hi(v1x, v1y, r1x, r1y);
                    *(unsigned*)(Cl + (size_t)(row0 + 8) * N + col) = pack_bf(r1x, r1y);
                }
            } else {
                if (row0 < M)
                    *(float2*)(C + (size_t)row0 * N + col) = make_float2(acc[m][n][0], acc[m][n][1]);
                if (row0 + 8 < M)
                    *(float2*)(C + (size_t)(row0 + 8) * N + col) = make_float2(acc[m][n][2], acc[m][n][3]);
            }
        }
    }

    if (ALPHA) {
        float* sAs = (float*)AsH;
        float* sAd = sAs + 128;
        if (tid < 128) { sAs[tid] = 0.f; sAd[tid] = 0.f; }
        __syncthreads();
        #pragma unroll
        for (int m = 0; m < 2; m++) {
            float pa = 0.f, pd = 0.f, qa = 0.f, qd = 0.f;
            #pragma unroll
            for (int n = 0; n < 4; n++) {
                int col = wn + n * 8 + rr * 2;
                float a0 = av[col], a1 = av[col + 1];
                float d0 = bv[col], d1 = bv[col + 1];
                pa += acc[m][n][0] * a0 + acc[m][n][1] * a1;
                pd += acc[m][n][0] * d0 + acc[m][n][1] * d1;
                qa += acc[m][n][2] * a0 + acc[m][n][3] * a1;
                qd += acc[m][n][2] * d0 + acc[m][n][3] * d1;
            }
            int r = wm + m * 16 + q;
            atomicAdd(&sAs[r], pa);     atomicAdd(&sAd[r], pd);
            atomicAdd(&sAs[r + 8], qa); atomicAdd(&sAd[r + 8], qd);
        }
        __syncthreads();
        if (tid < 128 && br + tid < M) {
            g_as[br + tid] = sAs[tid];
            g_ad[br + tid] = sAd[tid];
        }
    }
}

// ============ shared phase-1: per-warp coef/idx tables in smem ==================
// Computes softmax coefs for node gw's edge list; writes (coef, idx) for the
// first 64 edges into the warp's smem slab. Returns m, inv_den for overflow.
__device__ __forceinline__ void softmax_coefs(
    int gw, int start, int end, const float* __restrict__ asrc, float adn,
    float* wc, int* wi, int lane, float& m_out, float& inv_den_out) {
    int i0 = 0, i1 = 0;
    float l0 = -3.0e38f, l1 = -3.0e38f;
    float m = -3.0e38f, s = 0.f;
    int e = start + lane;
    if (e < end) { i0 = g_csr[e]; l0 = lrelu(asrc[i0] + adn); m = l0; s = 1.f; }
    if (e + 32 < end) {
        i1 = g_csr[e + 32];
        l1 = lrelu(asrc[i1] + adn);
        float mn = fmaxf(m, l1);
        s = s * __expf(m - mn) + __expf(l1 - mn);
        m = mn;
    }
    for (int e2 = e + 64; e2 < end; e2 += 32) {
        float l = lrelu(asrc[g_csr[e2]] + adn);
        float mn = fmaxf(m, l);
        s = s * __expf(m - mn) + __expf(l - mn);
        m = mn;
    }
    #pragma unroll
    for (int off = 16; off; off >>= 1) {
        float mo = __shfl_xor_sync(FULL, m, off);
        float so = __shfl_xor_sync(FULL, s, off);
        float mn = fmaxf(m, mo);
        s = s * __expf(m - mn) + so * __expf(mo - mn);
        m = mn;
    }
    float inv_den = 1.f / s;
    wc[lane]      = __expf(l0 - m) * inv_den;
    wc[lane + 32] = __expf(l1 - m) * inv_den;
    wi[lane]      = i0;
    wi[lane + 32] = i1;
    __syncwarp();
    m_out = m; inv_den_out = inv_den;
}

// ---------------- agg layer 1: softmax-aggregate x, emit bf16 hi/lo ------------
__global__ void __launch_bounds__(256, 6) agg128_k(const float* __restrict__ x) {
    __shared__ __align__(16) float scoef[8][64];
    __shared__ __align__(16) int   sidx [8][64];
    int gw   = (blockIdx.x * blockDim.x + threadIdx.x) >> 5;
    int lane = threadIdx.x & 31;
    int w    = (threadIdx.x >> 5);
    if (gw >= Nn) return;
    const int start = g_rowptr[gw];
    const int end   = g_rowptr[gw + 1];
    const int deg   = end - start;
    float m, inv_den;
    softmax_coefs(gw, start, end, g_as, g_ad[gw], scoef[w], sidx[w], lane, m, inv_den);
    const int nreg = deg < 64 ? deg : 64;
    const float* wc = scoef[w];
    const int*   wi = sidx[w];

    float4 a0 = make_float4(0.f, 0.f, 0.f, 0.f);
    int j = 0;
    for (; j + 8 <= nreg; j += 8) {
        float4 cA = *(const float4*)&wc[j];
        float4 cB = *(const float4*)&wc[j + 4];
        int4   iA = *(const int4*)&wi[j];
        int4   iB = *(const int4*)&wi[j + 4];
        float4 r0 = ((const float4*)(x + (size_t)iA.x * 128))[lane];
        float4 r1 = ((const float4*)(x + (size_t)iA.y * 128))[lane];
        float4 r2 = ((const float4*)(x + (size_t)iA.z * 128))[lane];
        float4 r3 = ((const float4*)(x + (size_t)iA.w * 128))[lane];
        float4 r4 = ((const float4*)(x + (size_t)iB.x * 128))[lane];
        float4 r5 = ((const float4*)(x + (size_t)iB.y * 128))[lane];
        float4 r6 = ((const float4*)(x + (size_t)iB.z * 128))[lane];
        float4 r7 = ((const float4*)(x + (size_t)iB.w * 128))[lane];
        a0.x += cA.x * r0.x + cA.y * r1.x + cA.z * r2.x + cA.w * r3.x
              + cB.x * r4.x + cB.y * r5.x + cB.z * r6.x + cB.w * r7.x;
        a0.y += cA.x * r0.y + cA.y * r1.y + cA.z * r2.y + cA.w * r3.y
              + cB.x * r4.y + cB.y * r5.y + cB.z * r6.y + cB.w * r7.y;
        a0.z += cA.x * r0.z + cA.y * r1.z + cA.z * r2.z + cA.w * r3.z
              + cB.x * r4.z + cB.y * r5.z + cB.z * r6.z + cB.w * r7.z;
        a0.w += cA.x * r0.w + cA.y * r1.w + cA.z * r2.w + cA.w * r3.w
              + cB.x * r4.w + cB.y * r5.w + cB.z * r6.w + cB.w * r7.w;
    }
    for (; j < nreg; j++) {
        float ca = wc[j];
        int   s0 = wi[j];
        float4 r0 = ((const float4*)(x + (size_t)s0 * 128))[lane];
        a0.x += ca * r0.x; a0.y += ca * r0.y; a0.z += ca * r0.z; a0.w += ca * r0.w;
    }
    for (int e2 = start + 64; e2 < end; e2++) {   // deg > 64: ~never
        int sn = g_csr[e2];
        float c = __expf(lrelu(g_as[sn] + g_ad[gw]) - m) * inv_den;
        float4 r0 = ((const float4*)(x + (size_t)sn * 128))[lane];
        a0.x += c * r0.x; a0.y += c * r0.y; a0.z += c * r0.z; a0.w += c * r0.w;
    }
    float rx, ry, rz, rw;
    unsigned h01 = pack_hi(a0.x, a0.y, rx, ry);
    unsigned h23 = pack_hi(a0.z, a0.w, rz, rw);
    *(uint2*)(g_xh + (size_t)gw * 128 + lane * 4) = make_uint2(h01, h23);
    *(uint2*)(g_xl + (size_t)gw * 128 + lane * 4) = make_uint2(pack_bf(rx, ry), pack_bf(rz, rw));
}

// ---------------- agg layer 2 (+fused bias/ELU/W3 matvec) -----------------------
__global__ void __launch_bounds__(256, 6) agg64_k(const float* __restrict__ h,
                      float* __restrict__ out, const float* __restrict__ bias,
                      const float* __restrict__ W3, const float* __restrict__ as3,
                      const float* __restrict__ ad3) {
    __shared__ __align__(16) float scoef[8][64];
    __shared__ __align__(16) int   sidx [8][64];
    int gw   = (blockIdx.x * blockDim.x + threadIdx.x) >> 5;
    int lane = threadIdx.x & 31;
    int w    = (threadIdx.x >> 5);
    if (gw >= Nn) return;
    const int start = g_rowptr[gw];
    const int end   = g_rowptr[gw + 1];
    const int deg   = end - start;
    float m, inv_den;
    softmax_coefs(gw, start, end, g_as, g_ad[gw], scoef[w], sidx[w], lane, m, inv_den);
    const int nreg = deg < 64 ? deg : 64;
    const float* wc = scoef[w];
    const int*   wi = sidx[w];

    float2 a = make_float2(0.f, 0.f);
    int j = 0;
    for (; j + 8 <= nreg; j += 8) {
        float4 cA = *(const float4*)&wc[j];
        float4 cB = *(const float4*)&wc[j + 4];
        int4   iA = *(const int4*)&wi[j];
        int4   iB = *(const int4*)&wi[j + 4];
        float2 r0 = ((const float2*)(h + (size_t)iA.x * 64))[lane];
        float2 r1 = ((const float2*)(h + (size_t)iA.y * 64))[lane];
        float2 r2 = ((const float2*)(h + (size_t)iA.z * 64))[lane];
        float2 r3 = ((const float2*)(h + (size_t)iA.w * 64))[lane];
        float2 r4 = ((const float2*)(h + (size_t)iB.x * 64))[lane];
        float2 r5 = ((const float2*)(h + (size_t)iB.y * 64))[lane];
        float2 r6 = ((const float2*)(h + (size_t)iB.z * 64))[lane];
        float2 r7 = ((const float2*)(h + (size_t)iB.w * 64))[lane];
        a.x += cA.x * r0.x + cA.y * r1.x + cA.z * r2.x + cA.w * r3.x
             + cB.x * r4.x + cB.y * r5.x + cB.z * r6.x + cB.w * r7.x;
        a.y += cA.x * r0.y + cA.y * r1.y + cA.z * r2.y + cA.w * r3.y
             + cB.x * r4.y + cB.y * r5.y + cB.z * r6.y + cB.w * r7.y;
    }
    for (; j < nreg; j++) {
        float ca = wc[j];
        int   s0 = wi[j];
        float2 r0 = ((const float2*)(h + (size_t)s0 * 64))[lane];
        a.x += ca * r0.x; a.y += ca * r0.y;
    }
    for (int e2 = start + 64; e2 < end; e2++) {
        int sn = g_csr[e2];
        float c = __expf(lrelu(g_as[sn] + g_ad[gw]) - m) * inv_den;
        float2 r0 = ((const float2*)(h + (size_t)sn * 64))[lane];
        a.x += c * r0.x; a.y += c * r0.y;
    }
    float2 bvv = ((const float2*)bias)[lane];
    a.x = elu1(a.x + bvv.x); a.y = elu1(a.y + bvv.y);
    float2 wv = ((const float2*)W3)[lane];
    float dot = a.x * wv.x + a.y * wv.y;
    #pragma unroll
    for (int off = 16; off; off >>= 1) dot += __shfl_xor_sync(FULL, dot, off);
    if (lane == 0) {
        out[gw]   = dot;
        g_as3[gw] = dot * as3[0];
        g_ad3[gw] = dot * ad3[0];
    }
}

// ---------------- agg layer 3 (scalar) ------------------------------------------
__global__ void agg1_k(const float* __restrict__ h, float* __restrict__ out,
                       const float* __restrict__ bias) {
    int gw   = (blockIdx.x * blockDim.x + threadIdx.x) >> 5;
    int lane = threadIdx.x & 31;
    if (gw >= Nn) return;
    const int start = g_rowptr[gw];
    const int end   = g_rowptr[gw + 1];
    const float adn = g_ad3[gw];

    float m = -3.0e38f, s = 0.f;
    for (int e = start + lane; e < end; e += 32) {
        float l = lrelu(g_as3[g_csr[e]] + adn);
        float mn = fmaxf(m, l);
        s = s * __expf(m - mn) + __expf(l - mn);
        m = mn;
    }
    #pragma unroll
    for (int off = 16; off; off >>= 1) {
        float mo = __shfl_xor_sync(FULL, m, off);
        float so = __shfl_xor_sync(FULL, s, off);
        float mn = fmaxf(m, mo);
        s = s * __expf(m - mn) + so * __expf(mo - mn);
        m = mn;
    }
    const float inv_den = 1.f / s;
    float a = 0.f;
    for (int e = start + lane; e < end; e += 32) {
        int sn = g_csr[e];
        float c = __expf(lrelu(g_as3[sn] + adn) - m) * inv_den;
        a += c * h[sn];
    }
    #pragma unroll
    for (int off = 16; off; off >>= 1) a += __shfl_xor_sync(FULL, a, off);
    if (lane == 0) out[gw] = a + bias[0];
}

// =============================== launcher ======================================
extern "C" void kernel_launch(void* const* d_in, const int* in_sizes, int n_in,
                              void* d_out, int out_size) {
    const float* x  = (const float*)d_in[0];
    const int*   ei = (const int*)d_in[1];
    const float *W1 = (const float*)d_in[2],  *as1 = (const float*)d_in[3],
                *ad1 = (const float*)d_in[4], *b1  = (const float*)d_in[5];
    const float *W2 = (const float*)d_in[6],  *as2 = (const float*)d_in[7],
                *ad2 = (const float*)d_in[8], *b2  = (const float*)d_in[9];
    const float *W3 = (const float*)d_in[10], *as3 = (const float*)d_in[11],
                *ad3 = (const float*)d_in[12], *b3 = (const float*)d_in[13];
    float* out = (float*)d_out;

    unsigned short *pxh, *pxl, *phh, *phl, *pw1h, *pw1l, *pw2h, *pw2l;
    float *po, *py;
    cudaGetSymbolAddress((void**)&pxh, g_xh);
    cudaGetSymbolAddress((void**)&pxl, g_xl);
    cudaGetSymbolAddress((void**)&phh, g_hh);
    cudaGetSymbolAddress((void**)&phl, g_hl);
    cudaGetSymbolAddress((void**)&pw1h, g_w1h);
    cudaGetSymbolAddress((void**)&pw1l, g_w1l);
    cudaGetSymbolAddress((void**)&pw2h, g_w2h);
    cudaGetSymbolAddress((void**)&pw2l, g_w2l);
    cudaGetSymbolAddress((void**)&po, g_o);
    cudaGetSymbolAddress((void**)&py, g_y);

    const int TB = 256;
    const int warpNodeBlk = (Nn * 32 + TB - 1) / TB;
    const int edge4Blk    = (Ereal / 4 + TB - 1) / TB;
    const int alphaBlk    = (Nn + 31) / 32;
    const int mRows = (Nn + 127) / 128;

    prep_count<<<edge4Blk + W1BLK + W2BLK + 1, TB>>>(ei, W1, as1, ad1, W2, edge4Blk);
    scan_alpha<<<NBLK + alphaBlk, 1024>>>(x);
    place_k<<<edge4Blk, TB>>>(ei);

    // ---- layer 1 (aggregate-then-transform): 128 -> 256 ----
    agg128_k<<<warpNodeBlk, TB>>>(x);
    {
        dim3 grid(D1 / 64, mRows);
        gemm_tc<true, false><<<grid, 256>>>(pxh, pxl, pw1h, pw1l, nullptr, phh, phl,
                                            b1, nullptr, nullptr, Nn, Cc, D1);
    }
    // ---- layer 2: 256 -> 64 ----
    {
        dim3 grid(D2 / 64, mRows);
        gemm_tc<false, true><<<grid, 256>>>(phh, phl, pw2h, pw2l, po, nullptr, nullptr,
                                            nullptr, as2, ad2, Nn, D1, D2);
        agg64_k<<<warpNodeBlk, TB>>>(po, py, b2, W3, as3, ad3);
    }
    // ---- layer 3: 64 -> 1 ----
    agg1_k<<<warpNodeBlk, TB>>>(py, out, b3);
}

// round 13
// speedup vs baseline: 3.1331x; 1.0673x over previous
#include <cuda_runtime.h>
#include <cuda_bf16.h>
#include <math.h>

#define Nn     50000
#define Cc     128
#define D1     256
#define D2     64
#define Ereal  800000
#define Etot   (Ereal + Nn)
#define FULL   0xFFFFFFFFu
#define NBLK   ((Nn + 1023) / 1024)
#define AGGF   (1u << 30)
#define PREF   (1u << 31)
#define VMSK   0x3FFFFFFFu

// ---------------- scratch ------------------------------------------------------
__device__ unsigned short g_xh[(size_t)Nn * Cc];
__device__ unsigned short g_xl[(size_t)Nn * Cc];
__device__ unsigned short g_hh[(size_t)Nn * D1];
__device__ unsigned short g_hl[(size_t)Nn * D1];
__device__ unsigned short g_w1h[D1 * Cc];
__device__ unsigned short g_w1l[D1 * Cc];
__device__ unsigned short g_w2h[D2 * D1];
__device__ unsigned short g_w2l[D2 * D1];
__device__ float g_o [(size_t)Nn * D2];
__device__ float g_y [Nn];
__device__ float g_as[Nn];
__device__ float g_ad[Nn];
__device__ float g_as3[Nn];
__device__ float g_ad3[Nn];
__device__ float g_ps[Cc];
__device__ float g_pd[Cc];
__device__ int   g_cnt [Nn];      // zero-invariant (scan resets)
__device__ int   g_epos[Ereal];
__device__ int   g_rowptr[Nn + 1];
__device__ int   g_csr[Etot];
__device__ unsigned g_bsum[64];   // lookback flags; reset by agg128 blk0
__device__ int   g_scandone;      // scan completion counter; reset by agg128 blk0

__device__ __forceinline__ unsigned short bf_hi(float v, float& r) {
    __nv_bfloat16 h = __float2bfloat16(v);
    r = v - __bfloat162float(h);
    return __bfloat16_as_ushort(h);
}
__device__ __forceinline__ unsigned short bf_of(float v) {
    return __bfloat16_as_ushort(__float2bfloat16(v));
}
__device__ __forceinline__ unsigned pack_hi(float a, float b, float& ra, float& rb) {
    unsigned ha = bf_hi(a, ra), hb = bf_hi(b, rb);
    return (hb << 16) | ha;
}
__device__ __forceinline__ unsigned pack_bf(float a, float b) {
    return ((unsigned)bf_of(b) << 16) | bf_of(a);
}
__device__ __forceinline__ float elu1(float v) { return v > 0.f ? v : expm1f(v); }
__device__ __forceinline__ float lrelu(float l) { return l > 0.f ? l : 0.2f * l; }

// ---------------- K1: edge count (first) + weight split + parallel p=W1@a ------
#define W1BLK 128
#define W2BLK 64
#define PBLK  32    // 32 blocks x 8 warps = 256 warps (one per p output)
__global__ void prep_count(const int* __restrict__ ei,
                           const float* __restrict__ W1, const float* __restrict__ as1,
                           const float* __restrict__ ad1, const float* __restrict__ W2,
                           int edge4Blk) {
    int b = blockIdx.x;
    if (b < edge4Blk) {
        int t = b * blockDim.x + threadIdx.x;
        if (t * 4 >= Ereal) return;
        int4 d4 = ((const int4*)(ei + Ereal))[t];
        int e = t * 4;
        g_epos[e + 0] = atomicAdd(&g_cnt[d4.x], 1);
        g_epos[e + 1] = atomicAdd(&g_cnt[d4.y], 1);
        g_epos[e + 2] = atomicAdd(&g_cnt[d4.z], 1);
        g_epos[e + 3] = atomicAdd(&g_cnt[d4.w], 1);
    } else if (b < edge4Blk + W1BLK) {
        int idx = (b - edge4Blk) * 256 + threadIdx.x;
        int n = idx >> 7, k = idx & 127;
        float v = W1[(size_t)k * D1 + n];
        float r;
        g_w1h[idx] = bf_hi(v, r);
        g_w1l[idx] = bf_of(r);
    } else if (b < edge4Blk + W1BLK + W2BLK) {
        int idx = (b - edge4Blk - W1BLK) * 256 + threadIdx.x;
        int n = idx >> 8, k = idx & 255;
        float v = W2[(size_t)k * D2 + n];
        float r;
        g_w2h[idx] = bf_hi(v, r);
        g_w2l[idx] = bf_of(r);
    } else {
        // p = W1 @ a : warp per output (256 warps)
        int w = (b - edge4Blk - W1BLK - W2BLK) * 8 + (threadIdx.x >> 5);
        int lane = threadIdx.x & 31;
        int i = w & 127;
        const float* a = (w < 128) ? as1 : ad1;
        const float* row = W1 + (size_t)i * D1;
        float s = 0.f;
        #pragma unroll
        for (int j = 0; j < 8; j++) s += row[lane + j * 32] * a[lane + j * 32];
        #pragma unroll
        for (int o = 16; o; o >>= 1) s += __shfl_xor_sync(FULL, s, o);
        if (lane == 0) { if (w < 128) g_ps[i] = s; else g_pd[i] = s; }
    }
}

// ---------------- K2: lookback scan + alpha + place (one launch) ----------------
__global__ void scan_alpha_place(const float* __restrict__ x, const int* __restrict__ ei,
                                 int alphaBlk) {
    int b = blockIdx.x;
    if (b < NBLK) {
        // ---- scan ----
        __shared__ int wsum[32];
        __shared__ int bpref;
        int tid = threadIdx.x, lane = tid & 31, wid = tid >> 5;
        int i = b * 1024 + tid;
        int v = 0;
        if (i < Nn) {
            v = g_cnt[i] + 1;          // +1 self-loop
            g_cnt[i] = 0;              // restore zero-invariant
        }
        int p = v;
        #pragma unroll
        for (int o = 1; o < 32; o <<= 1) {
            int t = __shfl_up_sync(FULL, p, o);
            if (lane >= o) p += t;
        }
        if (lane == 31) wsum[wid] = p;
        __syncthreads();
        if (wid == 0) {
            int w = wsum[lane];
            #pragma unroll
            for (int o = 1; o < 32; o <<= 1) {
                int t = __shfl_up_sync(FULL, w, o);
                if (lane >= o) w += t;
            }
            wsum[lane] = w;
        }
        __syncthreads();
        if (tid == 0) {
            unsigned total = (unsigned)wsum[31];
            if (b == 0) {
                atomicExch(&g_bsum[0], total | PREF);
                bpref = 0;
            } else {
                atomicExch(&g_bsum[b], total | AGGF);
                int pref = 0;
                int j = b - 1;
                while (j >= 0) {
                    unsigned vv = *(volatile unsigned*)&g_bsum[j];
                    if (vv == 0u) continue;
                    pref += (int)(vv & VMSK);
                    if (vv & PREF) break;
                    j--;
                }
                atomicExch(&g_bsum[b], ((unsigned)pref + total) | PREF);
                bpref = pref;
            }
        }
        __syncthreads();
        int excl = bpref + (wid ? wsum[wid - 1] : 0) + p - v;
        if (i < Nn) {
            g_rowptr[i] = excl;
            g_csr[excl] = i;           // self-loop at slot 0
        }
        if (i == 0) g_rowptr[Nn] = Etot;
        __syncthreads();
        if (tid == 0) {                // publish completion for place blocks
            __threadfence();
            atomicAdd(&g_scandone, 1);
        }
    } else if (b < NBLK + alphaBlk) {
        // ---- layer-1 alpha (warp per node) ----
        int gw = (b - NBLK) * 32 + (threadIdx.x >> 5);
        int lane = threadIdx.x & 31;
        if (gw >= Nn) return;
        float4 v = ((const float4*)(x + (size_t)gw * Cc))[lane];
        float4 p = ((const float4*)g_ps)[lane];
        float4 q = ((const float4*)g_pd)[lane];
        float s1 = v.x * p.x + v.y * p.y + v.z * p.z + v.w * p.w;
        float s2 = v.x * q.x + v.y * q.y + v.z * q.z + v.w * q.w;
        #pragma unroll
        for (int o = 16; o; o >>= 1) {
            s1 += __shfl_xor_sync(FULL, s1, o);
            s2 += __shfl_xor_sync(FULL, s2, o);
        }
        if (lane == 0) { g_as[gw] = s1; g_ad[gw] = s2; }
    } else {
        // ---- place edges (waits for scan completion) ----
        if (threadIdx.x == 0) {
            while (*(volatile int*)&g_scandone < NBLK) __nanosleep(64);
        }
        __syncthreads();
        int t = (b - NBLK - alphaBlk) * 1024 + threadIdx.x;
        if (t * 4 >= Ereal) return;
        int4 s4 = ((const int4*)ei)[t];
        int4 d4 = ((const int4*)(ei + Ereal))[t];
        int4 p4 = ((const int4*)g_epos)[t];
        g_csr[g_rowptr[d4.x] + 1 + p4.x] = s4.x;
        g_csr[g_rowptr[d4.y] + 1 + p4.y] = s4.y;
        g_csr[g_rowptr[d4.z] + 1 + p4.z] = s4.z;
        g_csr[g_rowptr[d4.w] + 1 + p4.w] = s4.w;
    }
}

// ================= split-bf16 tensor-core GEMM (templated warp-N) ===============
#define GS 12

__device__ __forceinline__ void mma_bf16(float (&c)[4], const unsigned* a, const unsigned* b) {
    asm volatile(
        "mma.sync.aligned.m16n8k16.row.col.f32.bf16.bf16.f32 "
        "{%0,%1,%2,%3}, {%4,%5,%6,%7}, {%8,%9}, {%0,%1,%2,%3};\n"
        : "+f"(c[0]), "+f"(c[1]), "+f"(c[2]), "+f"(c[3])
        : "r"(a[0]), "r"(a[1]), "r"(a[2]), "r"(a[3]), "r"(b[0]), "r"(b[1]));
}

// WN: warp n-extent. Block tile = 128 x (2*WN). NF = WN/8 fragments.
template<int WN, bool BIAS_ELU, bool ALPHA>
__global__ void __launch_bounds__(256) gemm_tc(const unsigned short* __restrict__ Ah,
                                               const unsigned short* __restrict__ Al,
                                               const unsigned short* __restrict__ Bh,
                                               const unsigned short* __restrict__ Bl,
                                               float* __restrict__ C,
                                               unsigned short* __restrict__ Ch,
                                               unsigned short* __restrict__ Cl,
                                               const float* __restrict__ bias,
                                               const float* __restrict__ av,
                                               const float* __restrict__ bv,
                                               int M, int K, int N) {
    constexpr int NF = WN / 8;
    constexpr int BT = WN / 32;            // B-load iterations per k-tile
    __shared__ unsigned AsH[128 * GS];
    __shared__ unsigned AsL[128 * GS];
    __shared__ unsigned BsH[128 * GS];
    __shared__ unsigned BsL[128 * GS];

    const int br = blockIdx.y * 128;
    const int bn = blockIdx.x * (2 * WN);
    const int tid = threadIdx.x;
    const int lane = tid & 31;
    const int warp = tid >> 5;
    const int wm = (warp >> 1) * 32;
    const int wn = (warp & 1) * WN;

    float acc[2][NF][4];
    #pragma unroll
    for (int m = 0; m < 2; m++)
        #pragma unroll
        for (int n = 0; n < NF; n++)
            #pragma unroll
            for (int r = 0; r < 4; r++) acc[m][n][r] = 0.f;

    const int q = lane >> 2;
    const int rr = lane & 3;

    const int aRow0 = tid >> 2,         aC0 = (tid & 3) * 4;
    const int aRow1 = (tid + 256) >> 2;

    const uint2 Z2 = make_uint2(0u, 0u);
    uint2 aRh[2], aRl[2], bRh[BT], bRl[BT];
    aRh[0] = (br + aRow0 < M) ? *(const uint2*)(Ah + (size_t)(br + aRow0) * K + aC0) : Z2;
    aRl[0] = (br + aRow0 < M) ? *(const uint2*)(Al + (size_t)(br + aRow0) * K + aC0) : Z2;
    aRh[1] = (br + aRow1 < M) ? *(const uint2*)(Ah + (size_t)(br + aRow1) * K + aC0) : Z2;
    aRl[1] = (br + aRow1 < M) ? *(const uint2*)(Al + (size_t)(br + aRow1) * K + aC0) : Z2;
    #pragma unroll
    for (int t = 0; t < BT; t++) {
        int idx = tid + t * 256;
        int row = idx >> 2, ku = (idx & 3) * 4;
        bRh[t] = *(const uint2*)(Bh + (size_t)(bn + row) * K + ku);
        bRl[t] = *(const uint2*)(Bl + (size_t)(bn + row) * K + ku);
    }

    for (int k0 = 0; k0 < K; k0 += 16) {
        #pragma unroll
        for (int t = 0; t < 2; t++) {
            int o = (t ? aRow1 : aRow0) * GS + (aC0 >> 1);
            AsH[o] = aRh[t].x; AsH[o + 1] = aRh[t].y;
            AsL[o] = aRl[t].x; AsL[o + 1] = aRl[t].y;
        }
        #pragma unroll
        for (int t = 0; t < BT; t++) {
            int idx = tid + t * 256;
            int row = idx >> 2, ku2 = (idx & 3) * 2;
            int o = row * GS + ku2;
            BsH[o] = bRh[t].x; BsH[o + 1] = bRh[t].y;
            BsL[o] = bRl[t].x; BsL[o + 1] = bRl[t].y;
        }
        __syncthreads();

        if (k0 + 16 < K) {
            int kn = k0 + 16;
            aRh[0] = (br + aRow0 < M) ? *(const uint2*)(Ah + (size_t)(br + aRow0) * K + kn + aC0) : Z2;
            aRl[0] = (br + aRow0 < M) ? *(const uint2*)(Al + (size_t)(br + aRow0) * K + kn + aC0) : Z2;
            aRh[1] = (br + aRow1 < M) ? *(const uint2*)(Ah + (size_t)(br + aRow1) * K + kn + aC0) : Z2;
            aRl[1] = (br + aRow1 < M) ? *(const uint2*)(Al + (size_t)(br + aRow1) * K + kn + aC0) : Z2;
            #pragma unroll
            for (int t = 0; t < BT; t++) {
                int idx = tid + t * 256;
                int row = idx >> 2, ku = (idx & 3) * 4;
                bRh[t] = *(const uint2*)(Bh + (size_t)(bn + row) * K + kn + ku);
                bRl[t] = *(const uint2*)(Bl + (size_t)(bn + row) * K + kn + ku);
            }
        }

        {
            unsigned ah[2][4], al[2][4], bh[NF][2], bl[NF][2];
            #pragma unroll
            for (int m = 0; m < 2; m++) {
                int r0 = (wm + m * 16 + q) * GS + rr;
                ah[m][0] = AsH[r0];
                ah[m][1] = AsH[r0 + 8 * GS];
                ah[m][2] = AsH[r0 + 4];
                ah[m][3] = AsH[r0 + 8 * GS + 4];
                al[m][0] = AsL[r0];
                al[m][1] = AsL[r0 + 8 * GS];
                al[m][2] = AsL[r0 + 4];
                al[m][3] = AsL[r0 + 8 * GS + 4];
            }
            #pragma unroll
            for (int n = 0; n < NF; n++) {
                int nb = (wn + n * 8 + q) * GS + rr;
                bh[n][0] = BsH[nb];
                bh[n][1] = BsH[nb + 4];
                bl[n][0] = BsL[nb];
                bl[n][1] = BsL[nb + 4];
            }
            #pragma unroll
            for (int m = 0; m < 2; m++)
                #pragma unroll
                for (int n = 0; n < NF; n++) {
                    mma_bf16(acc[m][n], ah[m], bh[n]);
                    mma_bf16(acc[m][n], ah[m], bl[n]);
                    mma_bf16(acc[m][n], al[m], bh[n]);
                }
        }
        __syncthreads();
    }

    #pragma unroll
    for (int m = 0; m < 2; m++) {
        int row0 = br + wm + m * 16 + q;
        #pragma unroll
        for (int n = 0; n < NF; n++) {
            int col = bn + wn + n * 8 + rr * 2;
            if (BIAS_ELU) {
                float b0 = bias[col], b1v = bias[col + 1];
                float r0x, r0y, r1x, r1y;
                float v0x = elu1(acc[m][n][0] + b0), v0y = elu1(acc[m][n][1] + b1v);
                float v1x = elu1(acc[m][n][2] + b0), v1y = elu1(acc[m][n][3] + b1v);
                if (row0 < M) {
                    *(unsigned*)(Ch + (size_t)row0 * N + col) = pack_hi(v0x, v0y, r0x, r0y);
                    *(unsigned*)(Cl + (size_t)row0 * N + col) = pack_bf(r0x, r0y);
                }
                if (row0 + 8 < M) {
                    *(unsigned*)(Ch + (size_t)(row0 + 8) * N + col) = pack_hi(v1x, v1y, r1x, r1y);
                    *(unsigned*)(Cl + (size_t)(row0 + 8) * N + col) = pack_bf(r1x, r1y);
                }
            } else {
                if (row0 < M)
                    *(float2*)(C + (size_t)row0 * N + col) = make_float2(acc[m][n][0], acc[m][n][1]);
                if (row0 + 8 < M)
                    *(float2*)(C + (size_t)(row0 + 8) * N + col) = make_float2(acc[m][n][2], acc[m][n][3]);
            }
        }
    }

    if (ALPHA) {
        float* sAs = (float*)AsH;
        float* sAd = sAs + 128;
        if (tid < 128) { sAs[tid] = 0.f; sAd[tid] = 0.f; }
        __syncthreads();
        #pragma unroll
        for (int m = 0; m < 2; m++) {
            float pa = 0.f, pd = 0.f, qa = 0.f, qd = 0.f;
            #pragma unroll
            for (int n = 0; n < NF; n++) {
                int col = wn + n * 8 + rr * 2;
                float a0 = av[col], a1 = av[col + 1];
                float d0 = bv[col], d1 = bv[col + 1];
                pa += acc[m][n][0] * a0 + acc[m][n][1] * a1;
                pd += acc[m][n][0] * d0 + acc[m][n][1] * d1;
                qa += acc[m][n][2] * a0 + acc[m][n][3] * a1;
                qd += acc[m][n][2] * d0 + acc[m][n][3] * d1;
            }
            int r = wm + m * 16 + q;
            atomicAdd(&sAs[r], pa);     atomicAdd(&sAd[r], pd);
            atomicAdd(&sAs[r + 8], qa); atomicAdd(&sAd[r + 8], qd);
        }
        __syncthreads();
        if (tid < 128 && br + tid < M) {
            g_as[br + tid] = sAs[tid];
            g_ad[br + tid] = sAd[tid];
        }
    }
}

// ============ shared phase-1: per-warp coef/idx tables in smem ==================
__device__ __forceinline__ void softmax_coefs(
    int gw, int start, int end, const float* __restrict__ asrc, float adn,
    float* wc, int* wi, int lane, float& m_out, float& inv_den_out) {
    int i0 = 0, i1 = 0;
    float l0 = -3.0e38f, l1 = -3.0e38f;
    float m = -3.0e38f, s = 0.f;
    int e = start + lane;
    if (e < end) { i0 = g_csr[e]; l0 = lrelu(asrc[i0] + adn); m = l0; s = 1.f; }
    if (e + 32 < end) {
        i1 = g_csr[e + 32];
        l1 = lrelu(asrc[i1] + adn);
        float mn = fmaxf(m, l1);
        s = s * __expf(m - mn) + __expf(l1 - mn);
        m = mn;
    }
    for (int e2 = e + 64; e2 < end; e2 += 32) {
        float l = lrelu(asrc[g_csr[e2]] + adn);
        float mn = fmaxf(m, l);
        s = s * __expf(m - mn) + __expf(l - mn);
        m = mn;
    }
    #pragma unroll
    for (int off = 16; off; off >>= 1) {
        float mo = __shfl_xor_sync(FULL, m, off);
        float so = __shfl_xor_sync(FULL, s, off);
        float mn = fmaxf(m, mo);
        s = s * __expf(m - mn) + so * __expf(mo - mn);
        m = mn;
    }
    float inv_den = 1.f / s;
    wc[lane]      = __expf(l0 - m) * inv_den;
    wc[lane + 32] = __expf(l1 - m) * inv_den;
    wi[lane]      = i0;
    wi[lane + 32] = i1;
    __syncwarp();
    m_out = m; inv_den_out = inv_den;
}

// ---------------- agg layer 1 (+bsum/scandone reset in block 0) -----------------
__global__ void __launch_bounds__(256, 6) agg128_k(const float* __restrict__ x) {
    __shared__ __align__(16) float scoef[8][64];
    __shared__ __align__(16) int   sidx [8][64];
    if (blockIdx.x == 0) {
        if (threadIdx.x < 64) g_bsum[threadIdx.x] = 0u;
        if (threadIdx.x == 64) g_scandone = 0;
    }
    int gw   = (blockIdx.x * blockDim.x + threadIdx.x) >> 5;
    int lane = threadIdx.x & 31;
    int w    = (threadIdx.x >> 5);
    if (gw >= Nn) return;
    const int start = g_rowptr[gw];
    const int end   = g_rowptr[gw + 1];
    const int deg   = end - start;
    float m, inv_den;
    softmax_coefs(gw, start, end, g_as, g_ad[gw], scoef[w], sidx[w], lane, m, inv_den);
    const int nreg = deg < 64 ? deg : 64;
    const float* wc = scoef[w];
    const int*   wi = sidx[w];

    float4 a0 = make_float4(0.f, 0.f, 0.f, 0.f);
    int j = 0;
    for (; j + 8 <= nreg; j += 8) {
        float4 cA = *(const float4*)&wc[j];
        float4 cB = *(const float4*)&wc[j + 4];
        int4   iA = *(const int4*)&wi[j];
        int4   iB = *(const int4*)&wi[j + 4];
        float4 r0 = ((const float4*)(x + (size_t)iA.x * 128))[lane];
        float4 r1 = ((const float4*)(x + (size_t)iA.y * 128))[lane];
        float4 r2 = ((const float4*)(x + (size_t)iA.z * 128))[lane];
        float4 r3 = ((const float4*)(x + (size_t)iA.w * 128))[lane];
        float4 r4 = ((const float4*)(x + (size_t)iB.x * 128))[lane];
        float4 r5 = ((const float4*)(x + (size_t)iB.y * 128))[lane];
        float4 r6 = ((const float4*)(x + (size_t)iB.z * 128))[lane];
        float4 r7 = ((const float4*)(x + (size_t)iB.w * 128))[lane];
        a0.x += cA.x * r0.x + cA.y * r1.x + cA.z * r2.x + cA.w * r3.x
              + cB.x * r4.x + cB.y * r5.x + cB.z * r6.x + cB.w * r7.x;
        a0.y += cA.x * r0.y + cA.y * r1.y + cA.z * r2.y + cA.w * r3.y
              + cB.x * r4.y + cB.y * r5.y + cB.z * r6.y + cB.w * r7.y;
        a0.z += cA.x * r0.z + cA.y * r1.z + cA.z * r2.z + cA.w * r3.z
              + cB.x * r4.z + cB.y * r5.z + cB.z * r6.z + cB.w * r7.z;
        a0.w += cA.x * r0.w + cA.y * r1.w + cA.z * r2.w + cA.w * r3.w
              + cB.x * r4.w + cB.y * r5.w + cB.z * r6.w + cB.w * r7.w;
    }
    for (; j < nreg; j++) {
        float ca = wc[j];
        int   s0 = wi[j];
        float4 r0 = ((const float4*)(x + (size_t)s0 * 128))[lane];
        a0.x += ca * r0.x; a0.y += ca * r0.y; a0.z += ca * r0.z; a0.w += ca * r0.w;
    }
    for (int e2 = start + 64; e2 < end; e2++) {
        int sn = g_csr[e2];
        float c = __expf(lrelu(g_as[sn] + g_ad[gw]) - m) * inv_den;
        float4 r0 = ((const float4*)(x + (size_t)sn * 128))[lane];
        a0.x += c * r0.x; a0.y += c * r0.y; a0.z += c * r0.z; a0.w += c * r0.w;
    }
    float rx, ry, rz, rw;
    unsigned h01 = pack_hi(a0.x, a0.y, rx, ry);
    unsigned h23 = pack_hi(a0.z, a0.w, rz, rw);
    *(uint2*)(g_xh + (size_t)gw * 128 + lane * 4) = make_uint2(h01, h23);
    *(uint2*)(g_xl + (size_t)gw * 128 + lane * 4) = make_uint2(pack_bf(rx, ry), pack_bf(rz, rw));
}

// ---------------- agg layer 2 (+fused bias/ELU/W3 matvec) -----------------------
__global__ void __launch_bounds__(256, 6) agg64_k(const float* __restrict__ h,
                      float* __restrict__ out, const float* __restrict__ bias,
                      const float* __restrict__ W3, const float* __restrict__ as3,
                      const float* __restrict__ ad3) {
    __shared__ __align__(16) float scoef[8][64];
    __shared__ __align__(16) int   sidx [8][64];
    int gw   = (blockIdx.x * blockDim.x + threadIdx.x) >> 5;
    int lane = threadIdx.x & 31;
    int w    = (threadIdx.x >> 5);
    if (gw >= Nn) return;
    const int start = g_rowptr[gw];
    const int end   = g_rowptr[gw + 1];
    const int deg   = end - start;
    float m, inv_den;
    softmax_coefs(gw, start, end, g_as, g_ad[gw], scoef[w], sidx[w], lane, m, inv_den);
    const int nreg = deg < 64 ? deg : 64;
    const float* wc = scoef[w];
    const int*   wi = sidx[w];

    float2 a = make_float2(0.f, 0.f);
    int j = 0;
    for (; j + 8 <= nreg; j += 8) {
        float4 cA = *(const float4*)&wc[j];
        float4 cB = *(const float4*)&wc[j + 4];
        int4   iA = *(const int4*)&wi[j];
        int4   iB = *(const int4*)&wi[j + 4];
        float2 r0 = ((const float2*)(h + (size_t)iA.x * 64))[lane];
        float2 r1 = ((const float2*)(h + (size_t)iA.y * 64))[lane];
        float2 r2 = ((const float2*)(h + (size_t)iA.z * 64))[lane];
        float2 r3 = ((const float2*)(h + (size_t)iA.w * 64))[lane];
        float2 r4 = ((const float2*)(h + (size_t)iB.x * 64))[lane];
        float2 r5 = ((const float2*)(h + (size_t)iB.y * 64))[lane];
        float2 r6 = ((const float2*)(h + (size_t)iB.z * 64))[lane];
        float2 r7 = ((const float2*)(h + (size_t)iB.w * 64))[lane];
        a.x += cA.x * r0.x + cA.y * r1.x + cA.z * r2.x + cA.w * r3.x
             + cB.x * r4.x + cB.y * r5.x + cB.z * r6.x + cB.w * r7.x;
        a.y += cA.x * r0.y + cA.y * r1.y + cA.z * r2.y + cA.w * r3.y
             + cB.x * r4.y + cB.y * r5.y + cB.z * r6.y + cB.w * r7.y;
    }
    for (; j < nreg; j++) {
        float ca = wc[j];
        int   s0 = wi[j];
        float2 r0 = ((const float2*)(h + (size_t)s0 * 64))[lane];
        a.x += ca * r0.x; a.y += ca * r0.y;
    }
    for (int e2 = start + 64; e2 < end; e2++) {
        int sn = g_csr[e2];
        float c = __expf(lrelu(g_as[sn] + g_ad[gw]) - m) * inv_den;
        float2 r0 = ((const float2*)(h + (size_t)sn * 64))[lane];
        a.x += c * r0.x; a.y += c * r0.y;
    }
    float2 bvv = ((const float2*)bias)[lane];
    a.x = elu1(a.x + bvv.x); a.y = elu1(a.y + bvv.y);
    float2 wv = ((const float2*)W3)[lane];
    float dot = a.x * wv.x + a.y * wv.y;
    #pragma unroll
    for (int off = 16; off; off >>= 1) dot += __shfl_xor_sync(FULL, dot, off);
    if (lane == 0) {
        out[gw]   = dot;
        g_as3[gw] = dot * as3[0];
        g_ad3[gw] = dot * ad3[0];
    }
}

// ---------------- agg layer 3 (scalar) ------------------------------------------
__global__ void agg1_k(const float* __restrict__ h, float* __restrict__ out,
                       const float* __restrict__ bias) {
    int gw   = (blockIdx.x * blockDim.x + threadIdx.x) >> 5;
    int lane = threadIdx.x & 31;
    if (gw >= Nn) return;
    const int start = g_rowptr[gw];
    const int end   = g_rowptr[gw + 1];
    const float adn = g_ad3[gw];

    float m = -3.0e38f, s = 0.f;
    for (int e = start + lane; e < end; e += 32) {
        float l = lrelu(g_as3[g_csr[e]] + adn);
        float mn = fmaxf(m, l);
        s = s * __expf(m - mn) + __expf(l - mn);
        m = mn;
    }
    #pragma unroll
    for (int off = 16; off; off >>= 1) {
        float mo = __shfl_xor_sync(FULL, m, off);
        float so = __shfl_xor_sync(FULL, s, off);
        float mn = fmaxf(m, mo);
        s = s * __expf(m - mn) + so * __expf(mo - mn);
        m = mn;
    }
    const float inv_den = 1.f / s;
    float a = 0.f;
    for (int e = start + lane; e < end; e += 32) {
        int sn = g_csr[e];
        float c = __expf(lrelu(g_as3[sn] + adn) - m) * inv_den;
        a += c * h[sn];
    }
    #pragma unroll
    for (int off = 16; off; off >>= 1) a += __shfl_xor_sync(FULL, a, off);
    if (lane == 0) out[gw] = a + bias[0];
}

// =============================== launcher ======================================
extern "C" void kernel_launch(void* const* d_in, const int* in_sizes, int n_in,
                              void* d_out, int out_size) {
    const float* x  = (const float*)d_in[0];
    const int*   ei = (const int*)d_in[1];
    const float *W1 = (const float*)d_in[2],  *as1 = (const float*)d_in[3],
                *ad1 = (const float*)d_in[4], *b1  = (const float*)d_in[5];
    const float *W2 = (const float*)d_in[6],  *as2 = (const float*)d_in[7],
                *ad2 = (const float*)d_in[8], *b2  = (const float*)d_in[9];
    const float *W3 = (const float*)d_in[10], *as3 = (const float*)d_in[11],
                *ad3 = (const float*)d_in[12], *b3 = (const float*)d_in[13];
    float* out = (float*)d_out;

    unsigned short *pxh, *pxl, *phh, *phl, *pw1h, *pw1l, *pw2h, *pw2l;
    float *po, *py;
    cudaGetSymbolAddress((void**)&pxh, g_xh);
    cudaGetSymbolAddress((void**)&pxl, g_xl);
    cudaGetSymbolAddress((void**)&phh, g_hh);
    cudaGetSymbolAddress((void**)&phl, g_hl);
    cudaGetSymbolAddress((void**)&pw1h, g_w1h);
    cudaGetSymbolAddress((void**)&pw1l, g_w1l);
    cudaGetSymbolAddress((void**)&pw2h, g_w2h);
    cudaGetSymbolAddress((void**)&pw2l, g_w2l);
    cudaGetSymbolAddress((void**)&po, g_o);
    cudaGetSymbolAddress((void**)&py, g_y);

    const int TB = 256;
    const int warpNodeBlk = (Nn * 32 + TB - 1) / TB;
    const int edge4Blk    = (Ereal / 4 + TB - 1) / TB;
    const int alphaBlk    = (Nn + 31) / 32;
    const int place1024   = (Ereal / 4 + 1023) / 1024;
    const int mRows = (Nn + 127) / 128;

    prep_count<<<edge4Blk + W1BLK + W2BLK + PBLK, TB>>>(ei, W1, as1, ad1, W2, edge4Blk);
    scan_alpha_place<<<NBLK + alphaBlk + place1024, 1024>>>(x, ei, alphaBlk);

    // ---- layer 1 (aggregate-then-transform): 128 -> 256 ----
    agg128_k<<<warpNodeBlk, TB>>>(x);
    {
        dim3 grid(D1 / 128, mRows);   // BN=128
        gemm_tc<64, true, false><<<grid, 256>>>(pxh, pxl, pw1h, pw1l, nullptr, phh, phl,
                                                b1, nullptr, nullptr, Nn, Cc, D1);
    }
    // ---- layer 2: 256 -> 64 ----
    {
        dim3 grid(D2 / 64, mRows);    // BN=64
        gemm_tc<32, false, true><<<grid, 256>>>(phh, phl, pw2h, pw2l, po, nullptr, nullptr,
                                                nullptr, as2, ad2, Nn, D1, D2);
        agg64_k<<<warpNodeBlk, TB>>>(po, py, b2, W3, as3, ad3);
    }
    // ---- layer 3: 64 -> 1 ----
    agg1_k<<<warpNodeBlk, TB>>>(py, out, b3);
}

// round 14
// speedup vs baseline: 3.4267x; 1.0937x over previous
#include <cuda_runtime.h>
#include <cuda_bf16.h>
#include <math.h>

#define Nn     50000
#define Cc     128
#define D1     256
#define D2     64
#define Ereal  800000
#define Etot   (Ereal + Nn)
#define FULL   0xFFFFFFFFu
#define NBLK   ((Nn + 1023) / 1024)
#define AGGF   (1u << 30)
#define PREF   (1u << 31)
#define VMSK   0x3FFFFFFFu

// ---------------- scratch ------------------------------------------------------
__device__ unsigned short g_xh[(size_t)Nn * Cc];
__device__ unsigned short g_xl[(size_t)Nn * Cc];
__device__ unsigned short g_hh[(size_t)Nn * D1];
__device__ unsigned short g_hl[(size_t)Nn * D1];
__device__ unsigned short g_w1h[D1 * Cc];
__device__ unsigned short g_w1l[D1 * Cc];
__device__ unsigned short g_w2h[D2 * D1];
__device__ unsigned short g_w2l[D2 * D1];
__device__ float g_o [(size_t)Nn * D2];
__device__ float g_y [Nn];
__device__ float g_as[Nn];
__device__ float g_ad[Nn];
__device__ float g_as3[Nn];
__device__ float g_ad3[Nn];
__device__ float g_ps[Cc];
__device__ float g_pd[Cc];
__device__ int   g_cnt [Nn];      // zero-invariant (scan resets)
__device__ int   g_epos[Ereal];
__device__ int   g_rowptr[Nn + 1];
__device__ int   g_csr[Etot];
__device__ unsigned g_bsum[64];   // lookback flags; reset by agg128 blk0
__device__ int   g_scandone;      // scan completion counter; reset by agg128 blk0

__device__ __forceinline__ unsigned short bf_hi(float v, float& r) {
    __nv_bfloat16 h = __float2bfloat16(v);
    r = v - __bfloat162float(h);
    return __bfloat16_as_ushort(h);
}
__device__ __forceinline__ unsigned short bf_of(float v) {
    return __bfloat16_as_ushort(__float2bfloat16(v));
}
__device__ __forceinline__ unsigned pack_hi(float a, float b, float& ra, float& rb) {
    unsigned ha = bf_hi(a, ra), hb = bf_hi(b, rb);
    return (hb << 16) | ha;
}
__device__ __forceinline__ unsigned pack_bf(float a, float b) {
    return ((unsigned)bf_of(b) << 16) | bf_of(a);
}
__device__ __forceinline__ float elu1(float v) { return v > 0.f ? v : expm1f(v); }
__device__ __forceinline__ float lrelu(float l) { return l > 0.f ? l : 0.2f * l; }

// ---------------- K1: edge count (first) + weight split + parallel p=W1@a ------
#define W1BLK 128
#define W2BLK 64
#define PBLK  32
__global__ void prep_count(const int* __restrict__ ei,
                           const float* __restrict__ W1, const float* __restrict__ as1,
                           const float* __restrict__ ad1, const float* __restrict__ W2,
                           int edge4Blk) {
    int b = blockIdx.x;
    if (b < edge4Blk) {
        int t = b * blockDim.x + threadIdx.x;
        if (t * 4 >= Ereal) return;
        int4 d4 = ((const int4*)(ei + Ereal))[t];
        int e = t * 4;
        g_epos[e + 0] = atomicAdd(&g_cnt[d4.x], 1);
        g_epos[e + 1] = atomicAdd(&g_cnt[d4.y], 1);
        g_epos[e + 2] = atomicAdd(&g_cnt[d4.z], 1);
        g_epos[e + 3] = atomicAdd(&g_cnt[d4.w], 1);
    } else if (b < edge4Blk + W1BLK) {
        int idx = (b - edge4Blk) * 256 + threadIdx.x;
        int n = idx >> 7, k = idx & 127;
        float v = W1[(size_t)k * D1 + n];
        float r;
        g_w1h[idx] = bf_hi(v, r);
        g_w1l[idx] = bf_of(r);
    } else if (b < edge4Blk + W1BLK + W2BLK) {
        int idx = (b - edge4Blk - W1BLK) * 256 + threadIdx.x;
        int n = idx >> 8, k = idx & 255;
        float v = W2[(size_t)k * D2 + n];
        float r;
        g_w2h[idx] = bf_hi(v, r);
        g_w2l[idx] = bf_of(r);
    } else {
        int w = (b - edge4Blk - W1BLK - W2BLK) * 8 + (threadIdx.x >> 5);
        int lane = threadIdx.x & 31;
        int i = w & 127;
        const float* a = (w < 128) ? as1 : ad1;
        const float* row = W1 + (size_t)i * D1;
        float s = 0.f;
        #pragma unroll
        for (int j = 0; j < 8; j++) s += row[lane + j * 32] * a[lane + j * 32];
        #pragma unroll
        for (int o = 16; o; o >>= 1) s += __shfl_xor_sync(FULL, s, o);
        if (lane == 0) { if (w < 128) g_ps[i] = s; else g_pd[i] = s; }
    }
}

// ---------------- K2: lookback scan + alpha + place (one launch) ----------------
__global__ void scan_alpha_place(const float* __restrict__ x, const int* __restrict__ ei,
                                 int alphaBlk) {
    int b = blockIdx.x;
    if (b < NBLK) {
        __shared__ int wsum[32];
        __shared__ int bpref;
        int tid = threadIdx.x, lane = tid & 31, wid = tid >> 5;
        int i = b * 1024 + tid;
        int v = 0;
        if (i < Nn) {
            v = g_cnt[i] + 1;          // +1 self-loop
            g_cnt[i] = 0;              // restore zero-invariant
        }
        int p = v;
        #pragma unroll
        for (int o = 1; o < 32; o <<= 1) {
            int t = __shfl_up_sync(FULL, p, o);
            if (lane >= o) p += t;
        }
        if (lane == 31) wsum[wid] = p;
        __syncthreads();
        if (wid == 0) {
            int w = wsum[lane];
            #pragma unroll
            for (int o = 1; o < 32; o <<= 1) {
                int t = __shfl_up_sync(FULL, w, o);
                if (lane >= o) w += t;
            }
            wsum[lane] = w;
        }
        __syncthreads();
        if (tid == 0) {
            unsigned total = (unsigned)wsum[31];
            if (b == 0) {
                atomicExch(&g_bsum[0], total | PREF);
                bpref = 0;
            } else {
                atomicExch(&g_bsum[b], total | AGGF);
                int pref = 0;
                int j = b - 1;
                while (j >= 0) {
                    unsigned vv = *(volatile unsigned*)&g_bsum[j];
                    if (vv == 0u) continue;
                    pref += (int)(vv & VMSK);
                    if (vv & PREF) break;
                    j--;
                }
                atomicExch(&g_bsum[b], ((unsigned)pref + total) | PREF);
                bpref = pref;
            }
        }
        __syncthreads();
        int excl = bpref + (wid ? wsum[wid - 1] : 0) + p - v;
        if (i < Nn) {
            g_rowptr[i] = excl;
            g_csr[excl] = i;           // self-loop at slot 0
        }
        if (i == 0) g_rowptr[Nn] = Etot;
        __syncthreads();
        if (tid == 0) {
            __threadfence();
            atomicAdd(&g_scandone, 1);
        }
    } else if (b < NBLK + alphaBlk) {
        int gw = (b - NBLK) * 32 + (threadIdx.x >> 5);
        int lane = threadIdx.x & 31;
        if (gw >= Nn) return;
        float4 v = ((const float4*)(x + (size_t)gw * Cc))[lane];
        float4 p = ((const float4*)g_ps)[lane];
        float4 q = ((const float4*)g_pd)[lane];
        float s1 = v.x * p.x + v.y * p.y + v.z * p.z + v.w * p.w;
        float s2 = v.x * q.x + v.y * q.y + v.z * q.z + v.w * q.w;
        #pragma unroll
        for (int o = 16; o; o >>= 1) {
            s1 += __shfl_xor_sync(FULL, s1, o);
            s2 += __shfl_xor_sync(FULL, s2, o);
        }
        if (lane == 0) { g_as[gw] = s1; g_ad[gw] = s2; }
    } else {
        if (threadIdx.x == 0) {
            while (*(volatile int*)&g_scandone < NBLK) __nanosleep(64);
        }
        __syncthreads();
        int t = (b - NBLK - alphaBlk) * 1024 + threadIdx.x;
        if (t * 4 >= Ereal) return;
        int4 s4 = ((const int4*)ei)[t];
        int4 d4 = ((const int4*)(ei + Ereal))[t];
        int4 p4 = ((const int4*)g_epos)[t];
        g_csr[g_rowptr[d4.x] + 1 + p4.x] = s4.x;
        g_csr[g_rowptr[d4.y] + 1 + p4.y] = s4.y;
        g_csr[g_rowptr[d4.z] + 1 + p4.z] = s4.z;
        g_csr[g_rowptr[d4.w] + 1 + p4.w] = s4.w;
    }
}

// ================= split-bf16 MMA helpers =======================================
#define GS 12

__device__ __forceinline__ void mma_bf16(float (&c)[4], const unsigned* a, const unsigned* b) {
    asm volatile(
        "mma.sync.aligned.m16n8k16.row.col.f32.bf16.bf16.f32 "
        "{%0,%1,%2,%3}, {%4,%5,%6,%7}, {%8,%9}, {%0,%1,%2,%3};\n"
        : "+f"(c[0]), "+f"(c[1]), "+f"(c[2]), "+f"(c[3])
        : "r"(a[0]), "r"(a[1]), "r"(a[2]), "r"(a[3]), "r"(b[0]), "r"(b[1]));
}

// ---------- GEMM1: 512 threads, block 128x128, warp 32x32, bias+ELU epilogue ----
// A = g_xh/g_xl [M][128], B = g_w1h/g_w1l [256][128], C -> g_hh/g_hl [M][256].
__global__ void __launch_bounds__(512) gemm1_k(const unsigned short* __restrict__ Ah,
                                               const unsigned short* __restrict__ Al,
                                               const unsigned short* __restrict__ Bh,
                                               const unsigned short* __restrict__ Bl,
                                               unsigned short* __restrict__ Ch,
                                               unsigned short* __restrict__ Cl,
                                               const float* __restrict__ bias,
                                               int M) {
    constexpr int K = Cc;      // 128
    constexpr int N = D1;      // 256
    __shared__ unsigned AsH[128 * GS];
    __shared__ unsigned AsL[128 * GS];
    __shared__ unsigned BsH[128 * GS];
    __shared__ unsigned BsL[128 * GS];

    const int br = blockIdx.y * 128;
    const int bn = blockIdx.x * 128;
    const int tid = threadIdx.x;
    const int lane = tid & 31;
    const int warp = tid >> 5;          // 0..15
    const int wm = (warp >> 2) * 32;    // 4 m-groups
    const int wn = (warp & 3) * 32;     // 4 n-groups

    float acc[2][4][4];
    #pragma unroll
    for (int m = 0; m < 2; m++)
        #pragma unroll
        for (int n = 0; n < 4; n++)
            #pragma unroll
            for (int r = 0; r < 4; r++) acc[m][n][r] = 0.f;

    const int q = lane >> 2;
    const int rr = lane & 3;

    const int ldRow = tid >> 2;          // 0..127
    const int ldC   = (tid & 3) * 4;     // k-offset (4 bf16 = 1 uint2)

    const uint2 Z2 = make_uint2(0u, 0u);
    uint2 aRh, aRl, bRh, bRl;
    bool aOK = (br + ldRow < M);
    aRh = aOK ? *(const uint2*)(Ah + (size_t)(br + ldRow) * K + ldC) : Z2;
    aRl = aOK ? *(const uint2*)(Al + (size_t)(br + ldRow) * K + ldC) : Z2;
    bRh = *(const uint2*)(Bh + (size_t)(bn + ldRow) * K + ldC);
    bRl = *(const uint2*)(Bl + (size_t)(bn + ldRow) * K + ldC);

    for (int k0 = 0; k0 < K; k0 += 16) {
        {
            int o = ldRow * GS + (ldC >> 1);
            AsH[o] = aRh.x; AsH[o + 1] = aRh.y;
            AsL[o] = aRl.x; AsL[o + 1] = aRl.y;
            BsH[o] = bRh.x; BsH[o + 1] = bRh.y;
            BsL[o] = bRl.x; BsL[o + 1] = bRl.y;
        }
        __syncthreads();

        if (k0 + 16 < K) {
            int kn = k0 + 16;
            aRh = aOK ? *(const uint2*)(Ah + (size_t)(br + ldRow) * K + kn + ldC) : Z2;
            aRl = aOK ? *(const uint2*)(Al + (size_t)(br + ldRow) * K + kn + ldC) : Z2;
            bRh = *(const uint2*)(Bh + (size_t)(bn + ldRow) * K + kn + ldC);
            bRl = *(const uint2*)(Bl + (size_t)(bn + ldRow) * K + kn + ldC);
        }

        {
            unsigned ah[2][4], al[2][4], bh[4][2], bl[4][2];
            #pragma unroll
            for (int m = 0; m < 2; m++) {
                int r0 = (wm + m * 16 + q) * GS + rr;
                ah[m][0] = AsH[r0];
                ah[m][1] = AsH[r0 + 8 * GS];
                ah[m][2] = AsH[r0 + 4];
                ah[m][3] = AsH[r0 + 8 * GS + 4];
                al[m][0] = AsL[r0];
                al[m][1] = AsL[r0 + 8 * GS];
                al[m][2] = AsL[r0 + 4];
                al[m][3] = AsL[r0 + 8 * GS + 4];
            }
            #pragma unroll
            for (int n = 0; n < 4; n++) {
                int nb = (wn + n * 8 + q) * GS + rr;
                bh[n][0] = BsH[nb];
                bh[n][1] = BsH[nb + 4];
                bl[n][0] = BsL[nb];
                bl[n][1] = BsL[nb + 4];
            }
            #pragma unroll
            for (int m = 0; m < 2; m++)
                #pragma unroll
                for (int n = 0; n < 4; n++) {
                    mma_bf16(acc[m][n], ah[m], bh[n]);
                    mma_bf16(acc[m][n], ah[m], bl[n]);
                    mma_bf16(acc[m][n], al[m], bh[n]);
                }
        }
        __syncthreads();
    }

    #pragma unroll
    for (int m = 0; m < 2; m++) {
        int row0 = br + wm + m * 16 + q;
        #pragma unroll
        for (int n = 0; n < 4; n++) {
            int col = bn + wn + n * 8 + rr * 2;
            float b0 = bias[col], b1v = bias[col + 1];
            float r0x, r0y, r1x, r1y;
            float v0x = elu1(acc[m][n][0] + b0), v0y = elu1(acc[m][n][1] + b1v);
            float v1x = elu1(acc[m][n][2] + b0), v1y = elu1(acc[m][n][3] + b1v);
            if (row0 < M) {
                *(unsigned*)(Ch + (size_t)row0 * N + col) = pack_hi(v0x, v0y, r0x, r0y);
                *(unsigned*)(Cl + (size_t)row0 * N + col) = pack_bf(r0x, r0y);
            }
            if (row0 + 8 < M) {
                *(unsigned*)(Ch + (size_t)(row0 + 8) * N + col) = pack_hi(v1x, v1y, r1x, r1y);
                *(unsigned*)(Cl + (size_t)(row0 + 8) * N + col) = pack_bf(r1x, r1y);
            }
        }
    }
}

// ---------- GEMM2: 256 threads, block 128x64, warp 32x32, fused alpha -----------
__global__ void __launch_bounds__(256) gemm2_k(const unsigned short* __restrict__ Ah,
                                               const unsigned short* __restrict__ Al,
                                               const unsigned short* __restrict__ Bh,
                                               const unsigned short* __restrict__ Bl,
                                               float* __restrict__ C,
                                               const float* __restrict__ av,
                                               const float* __restrict__ bv,
                                               int M) {
    constexpr int K = D1;   // 256
    constexpr int N = D2;   // 64
    constexpr int WN = 32, NF = 4, BT = 1;
    __shared__ unsigned AsH[128 * GS];
    __shared__ unsigned AsL[128 * GS];
    __shared__ unsigned BsH[64 * GS];
    __shared__ unsigned BsL[64 * GS];

    const int br = blockIdx.y * 128;
    const int bn = 0;
    const int tid = threadIdx.x;
    const int lane = tid & 31;
    const int warp = tid >> 5;
    const int wm = (warp >> 1) * 32;
    const int wn = (warp & 1) * WN;

    float acc[2][NF][4];
    #pragma unroll
    for (int m = 0; m < 2; m++)
        #pragma unroll
        for (int n = 0; n < NF; n++)
            #pragma unroll
            for (int r = 0; r < 4; r++) acc[m][n][r] = 0.f;

    const int q = lane >> 2;
    const int rr = lane & 3;

    const int aRow0 = tid >> 2,         aC0 = (tid & 3) * 4;
    const int aRow1 = (tid + 256) >> 2;

    const uint2 Z2 = make_uint2(0u, 0u);
    uint2 aRh[2], aRl[2], bRh[BT], bRl[BT];
    aRh[0] = (br + aRow0 < M) ? *(const uint2*)(Ah + (size_t)(br + aRow0) * K + aC0) : Z2;
    aRl[0] = (br + aRow0 < M) ? *(const uint2*)(Al + (size_t)(br + aRow0) * K + aC0) : Z2;
    aRh[1] = (br + aRow1 < M) ? *(const uint2*)(Ah + (size_t)(br + aRow1) * K + aC0) : Z2;
    aRl[1] = (br + aRow1 < M) ? *(const uint2*)(Al + (size_t)(br + aRow1) * K + aC0) : Z2;
    {
        int row = tid >> 2, ku = (tid & 3) * 4;
        bRh[0] = *(const uint2*)(Bh + (size_t)(bn + (row & 63)) * K + ku);
        bRl[0] = *(const uint2*)(Bl + (size_t)(bn + (row & 63)) * K + ku);
    }

    for (int k0 = 0; k0 < K; k0 += 16) {
        #pragma unroll
        for (int t = 0; t < 2; t++) {
            int o = (t ? aRow1 : aRow0) * GS + (aC0 >> 1);
            AsH[o] = aRh[t].x; AsH[o + 1] = aRh[t].y;
            AsL[o] = aRl[t].x; AsL[o + 1] = aRl[t].y;
        }
        if (tid < 256) {   // 64 rows x 4 loads = 256 threads exactly
            int row = tid >> 2, ku2 = (tid & 3) * 2;
            int o = row * GS + ku2;
            if (row < 64) {
                BsH[o] = bRh[0].x; BsH[o + 1] = bRh[0].y;
                BsL[o] = bRl[0].x; BsL[o + 1] = bRl[0].y;
            }
        }
        __syncthreads();

        if (k0 + 16 < K) {
            int kn = k0 + 16;
            aRh[0] = (br + aRow0 < M) ? *(const uint2*)(Ah + (size_t)(br + aRow0) * K + kn + aC0) : Z2;
            aRl[0] = (br + aRow0 < M) ? *(const uint2*)(Al + (size_t)(br + aRow0) * K + kn + aC0) : Z2;
            aRh[1] = (br + aRow1 < M) ? *(const uint2*)(Ah + (size_t)(br + aRow1) * K + kn + aC0) : Z2;
            aRl[1] = (br + aRow1 < M) ? *(const uint2*)(Al + (size_t)(br + aRow1) * K + kn + aC0) : Z2;
            int row = tid >> 2, ku = (tid & 3) * 4;
            bRh[0] = *(const uint2*)(Bh + (size_t)(bn + (row & 63)) * K + kn + ku);
            bRl[0] = *(const uint2*)(Bl + (size_t)(bn + (row & 63)) * K + kn + ku);
        }

        {
            unsigned ah[2][4], al[2][4], bh[NF][2], bl[NF][2];
            #pragma unroll
            for (int m = 0; m < 2; m++) {
                int r0 = (wm + m * 16 + q) * GS + rr;
                ah[m][0] = AsH[r0];
                ah[m][1] = AsH[r0 + 8 * GS];
                ah[m][2] = AsH[r0 + 4];
                ah[m][3] = AsH[r0 + 8 * GS + 4];
                al[m][0] = AsL[r0];
                al[m][1] = AsL[r0 + 8 * GS];
                al[m][2] = AsL[r0 + 4];
                al[m][3] = AsL[r0 + 8 * GS + 4];
            }
            #pragma unroll
            for (int n = 0; n < NF; n++) {
                int nb = (wn + n * 8 + q) * GS + rr;
                bh[n][0] = BsH[nb];
                bh[n][1] = BsH[nb + 4];
                bl[n][0] = BsL[nb];
                bl[n][1] = BsL[nb + 4];
            }
            #pragma unroll
            for (int m = 0; m < 2; m++)
                #pragma unroll
                for (int n = 0; n < NF; n++) {
                    mma_bf16(acc[m][n], ah[m], bh[n]);
                    mma_bf16(acc[m][n], ah[m], bl[n]);
                    mma_bf16(acc[m][n], al[m], bh[n]);
                }
        }
        __syncthreads();
    }

    #pragma unroll
    for (int m = 0; m < 2; m++) {
        int row0 = br + wm + m * 16 + q;
        #pragma unroll
        for (int n = 0; n < NF; n++) {
            int col = bn + wn + n * 8 + rr * 2;
            if (row0 < M)
                *(float2*)(C + (size_t)row0 * N + col) = make_float2(acc[m][n][0], acc[m][n][1]);
            if (row0 + 8 < M)
                *(float2*)(C + (size_t)(row0 + 8) * N + col) = make_float2(acc[m][n][2], acc[m][n][3]);
        }
    }

    // fused alpha: g_as/g_ad = C-row . av/bv (block covers all 64 cols)
    {
        float* sAs = (float*)AsH;
        float* sAd = sAs + 128;
        if (tid < 128) { sAs[tid] = 0.f; sAd[tid] = 0.f; }
        __syncthreads();
        #pragma unroll
        for (int m = 0; m < 2; m++) {
            float pa = 0.f, pd = 0.f, qa = 0.f, qd = 0.f;
            #pragma unroll
            for (int n = 0; n < NF; n++) {
                int col = wn + n * 8 + rr * 2;
                float a0 = av[col], a1 = av[col + 1];
                float d0 = bv[col], d1 = bv[col + 1];
                pa += acc[m][n][0] * a0 + acc[m][n][1] * a1;
                pd += acc[m][n][0] * d0 + acc[m][n][1] * d1;
                qa += acc[m][n][2] * a0 + acc[m][n][3] * a1;
                qd += acc[m][n][2] * d0 + acc[m][n][3] * d1;
            }
            int r = wm + m * 16 + q;
            atomicAdd(&sAs[r], pa);     atomicAdd(&sAd[r], pd);
            atomicAdd(&sAs[r + 8], qa); atomicAdd(&sAd[r + 8], qd);
        }
        __syncthreads();
        if (tid < 128 && br + tid < M) {
            g_as[br + tid] = sAs[tid];
            g_ad[br + tid] = sAd[tid];
        }
    }
}

// ============ shared phase-1: per-warp coef/idx tables in smem ==================
__device__ __forceinline__ void softmax_coefs(
    int gw, int start, int end, const float* __restrict__ asrc, float adn,
    float* wc, int* wi, int lane, float& m_out, float& inv_den_out) {
    int i0 = 0, i1 = 0;
    float l0 = -3.0e38f, l1 = -3.0e38f;
    float m = -3.0e38f, s = 0.f;
    int e = start + lane;
    if (e < end) { i0 = g_csr[e]; l0 = lrelu(asrc[i0] + adn); m = l0; s = 1.f; }
    if (e + 32 < end) {
        i1 = g_csr[e + 32];
        l1 = lrelu(asrc[i1] + adn);
        float mn = fmaxf(m, l1);
        s = s * __expf(m - mn) + __expf(l1 - mn);
        m = mn;
    }
    for (int e2 = e + 64; e2 < end; e2 += 32) {
        float l = lrelu(asrc[g_csr[e2]] + adn);
        float mn = fmaxf(m, l);
        s = s * __expf(m - mn) + __expf(l - mn);
        m = mn;
    }
    #pragma unroll
    for (int off = 16; off; off >>= 1) {
        float mo = __shfl_xor_sync(FULL, m, off);
        float so = __shfl_xor_sync(FULL, s, off);
        float mn = fmaxf(m, mo);
        s = s * __expf(m - mn) + so * __expf(mo - mn);
        m = mn;
    }
    float inv_den = 1.f / s;
    wc[lane]      = __expf(l0 - m) * inv_den;
    wc[lane + 32] = __expf(l1 - m) * inv_den;
    wi[lane]      = i0;
    wi[lane + 32] = i1;
    __syncwarp();
    m_out = m; inv_den_out = inv_den;
}

// ---------------- agg layer 1 (+bsum/scandone reset in block 0) -----------------
__global__ void __launch_bounds__(256, 6) agg128_k(const float* __restrict__ x) {
    __shared__ __align__(16) float scoef[8][64];
    __shared__ __align__(16) int   sidx [8][64];
    if (blockIdx.x == 0) {
        if (threadIdx.x < 64) g_bsum[threadIdx.x] = 0u;
        if (threadIdx.x == 64) g_scandone = 0;
    }
    int gw   = (blockIdx.x * blockDim.x + threadIdx.x) >> 5;
    int lane = threadIdx.x & 31;
    int w    = (threadIdx.x >> 5);
    if (gw >= Nn) return;
    const int start = g_rowptr[gw];
    const int end   = g_rowptr[gw + 1];
    const int deg   = end - start;
    float m, inv_den;
    softmax_coefs(gw, start, end, g_as, g_ad[gw], scoef[w], sidx[w], lane, m, inv_den);
    const int nreg = deg < 64 ? deg : 64;
    const float* wc = scoef[w];
    const int*   wi = sidx[w];

    float4 a0 = make_float4(0.f, 0.f, 0.f, 0.f);
    int j = 0;
    for (; j + 8 <= nreg; j += 8) {
        float4 cA = *(const float4*)&wc[j];
        float4 cB = *(const float4*)&wc[j + 4];
        int4   iA = *(const int4*)&wi[j];
        int4   iB = *(const int4*)&wi[j + 4];
        float4 r0 = ((const float4*)(x + (size_t)iA.x * 128))[lane];
        float4 r1 = ((const float4*)(x + (size_t)iA.y * 128))[lane];
        float4 r2 = ((const float4*)(x + (size_t)iA.z * 128))[lane];
        float4 r3 = ((const float4*)(x + (size_t)iA.w * 128))[lane];
        float4 r4 = ((const float4*)(x + (size_t)iB.x * 128))[lane];
        float4 r5 = ((const float4*)(x + (size_t)iB.y * 128))[lane];
        float4 r6 = ((const float4*)(x + (size_t)iB.z * 128))[lane];
        float4 r7 = ((const float4*)(x + (size_t)iB.w * 128))[lane];
        a0.x += cA.x * r0.x + cA.y * r1.x + cA.z * r2.x + cA.w * r3.x
              + cB.x * r4.x + cB.y * r5.x + cB.z * r6.x + cB.w * r7.x;
        a0.y += cA.x * r0.y + cA.y * r1.y + cA.z * r2.y + cA.w * r3.y
              + cB.x * r4.y + cB.y * r5.y + cB.z * r6.y + cB.w * r7.y;
        a0.z += cA.x * r0.z + cA.y * r1.z + cA.z * r2.z + cA.w * r3.z
              + cB.x * r4.z + cB.y * r5.z + cB.z * r6.z + cB.w * r7.z;
        a0.w += cA.x * r0.w + cA.y * r1.w + cA.z * r2.w + cA.w * r3.w
              + cB.x * r4.w + cB.y * r5.w + cB.z * r6.w + cB.w * r7.w;
    }
    for (; j < nreg; j++) {
        float ca = wc[j];
        int   s0 = wi[j];
        float4 r0 = ((const float4*)(x + (size_t)s0 * 128))[lane];
        a0.x += ca * r0.x; a0.y += ca * r0.y; a0.z += ca * r0.z; a0.w += ca * r0.w;
    }
    for (int e2 = start + 64; e2 < end; e2++) {
        int sn = g_csr[e2];
        float c = __expf(lrelu(g_as[sn] + g_ad[gw]) - m) * inv_den;
        float4 r0 = ((const float4*)(x + (size_t)sn * 128))[lane];
        a0.x += c * r0.x; a0.y += c * r0.y; a0.z += c * r0.z; a0.w += c * r0.w;
    }
    float rx, ry, rz, rw;
    unsigned h01 = pack_hi(a0.x, a0.y, rx, ry);
    unsigned h23 = pack_hi(a0.z, a0.w, rz, rw);
    *(uint2*)(g_xh + (size_t)gw * 128 + lane * 4) = make_uint2(h01, h23);
    *(uint2*)(g_xl + (size_t)gw * 128 + lane * 4) = make_uint2(pack_bf(rx, ry), pack_bf(rz, rw));
}

// ---------------- agg layer 2 (+fused bias/ELU/W3 matvec) -----------------------
__global__ void __launch_bounds__(256, 6) agg64_k(const float* __restrict__ h,
                      float* __restrict__ out, const float* __restrict__ bias,
                      const float* __restrict__ W3, const float* __restrict__ as3,
                      const float* __restrict__ ad3) {
    __shared__ __align__(16) float scoef[8][64];
    __shared__ __align__(16) int   sidx [8][64];
    int gw   = (blockIdx.x * blockDim.x + threadIdx.x) >> 5;
    int lane = threadIdx.x & 31;
    int w    = (threadIdx.x >> 5);
    if (gw >= Nn) return;
    const int start = g_rowptr[gw];
    const int end   = g_rowptr[gw + 1];
    const int deg   = end - start;
    float m, inv_den;
    softmax_coefs(gw, start, end, g_as, g_ad[gw], scoef[w], sidx[w], lane, m, inv_den);
    const int nreg = deg < 64 ? deg : 64;
    const float* wc = scoef[w];
    const int*   wi = sidx[w];

    float2 a = make_float2(0.f, 0.f);
    int j = 0;
    for (; j + 8 <= nreg; j += 8) {
        float4 cA = *(const float4*)&wc[j];
        float4 cB = *(const float4*)&wc[j + 4];
        int4   iA = *(const int4*)&wi[j];
        int4   iB = *(const int4*)&wi[j + 4];
        float2 r0 = ((const float2*)(h + (size_t)iA.x * 64))[lane];
        float2 r1 = ((const float2*)(h + (size_t)iA.y * 64))[lane];
        float2 r2 = ((const float2*)(h + (size_t)iA.z * 64))[lane];
        float2 r3 = ((const float2*)(h + (size_t)iA.w * 64))[lane];
        float2 r4 = ((const float2*)(h + (size_t)iB.x * 64))[lane];
        float2 r5 = ((const float2*)(h + (size_t)iB.y * 64))[lane];
        float2 r6 = ((const float2*)(h + (size_t)iB.z * 64))[lane];
        float2 r7 = ((const float2*)(h + (size_t)iB.w * 64))[lane];
        a.x += cA.x * r0.x + cA.y * r1.x + cA.z * r2.x + cA.w * r3.x
             + cB.x * r4.x + cB.y * r5.x + cB.z * r6.x + cB.w * r7.x;
        a.y += cA.x * r0.y + cA.y * r1.y + cA.z * r2.y + cA.w * r3.y
             + cB.x * r4.y + cB.y * r5.y + cB.z * r6.y + cB.w * r7.y;
    }
    for (; j < nreg; j++) {
        float ca = wc[j];
        int   s0 = wi[j];
        float2 r0 = ((const float2*)(h + (size_t)s0 * 64))[lane];
        a.x += ca * r0.x; a.y += ca * r0.y;
    }
    for (int e2 = start + 64; e2 < end; e2++) {
        int sn = g_csr[e2];
        float c = __expf(lrelu(g_as[sn] + g_ad[gw]) - m) * inv_den;
        float2 r0 = ((const float2*)(h + (size_t)sn * 64))[lane];
        a.x += c * r0.x; a.y += c * r0.y;
    }
    float2 bvv = ((const float2*)bias)[lane];
    a.x = elu1(a.x + bvv.x); a.y = elu1(a.y + bvv.y);
    float2 wv = ((const float2*)W3)[lane];
    float dot = a.x * wv.x + a.y * wv.y;
    #pragma unroll
    for (int off = 16; off; off >>= 1) dot += __shfl_xor_sync(FULL, dot, off);
    if (lane == 0) {
        out[gw]   = dot;
        g_as3[gw] = dot * as3[0];
        g_ad3[gw] = dot * ad3[0];
    }
}

// ---------------- agg layer 3 (scalar) ------------------------------------------
__global__ void agg1_k(const float* __restrict__ h, float* __restrict__ out,
                       const float* __restrict__ bias) {
    int gw   = (blockIdx.x * blockDim.x + threadIdx.x) >> 5;
    int lane = threadIdx.x & 31;
    if (gw >= Nn) return;
    const int start = g_rowptr[gw];
    const int end   = g_rowptr[gw + 1];
    const float adn = g_ad3[gw];

    float m = -3.0e38f, s = 0.f;
    for (int e = start + lane; e < end; e += 32) {
        float l = lrelu(g_as3[g_csr[e]] + adn);
        float mn = fmaxf(m, l);
        s = s * __expf(m - mn) + __expf(l - mn);
        m = mn;
    }
    #pragma unroll
    for (int off = 16; off; off >>= 1) {
        float mo = __shfl_xor_sync(FULL, m, off);
        float so = __shfl_xor_sync(FULL, s, off);
        float mn = fmaxf(m, mo);
        s = s * __expf(m - mn) + so * __expf(mo - mn);
        m = mn;
    }
    const float inv_den = 1.f / s;
    float a = 0.f;
    for (int e = start + lane; e < end; e += 32) {
        int sn = g_csr[e];
        float c = __expf(lrelu(g_as3[sn] + adn) - m) * inv_den;
        a += c * h[sn];
    }
    #pragma unroll
    for (int off = 16; off; off >>= 1) a += __shfl_xor_sync(FULL, a, off);
    if (lane == 0) out[gw] = a + bias[0];
}

// =============================== launcher ======================================
extern "C" void kernel_launch(void* const* d_in, const int* in_sizes, int n_in,
                              void* d_out, int out_size) {
    const float* x  = (const float*)d_in[0];
    const int*   ei = (const int*)d_in[1];
    const float *W1 = (const float*)d_in[2],  *as1 = (const float*)d_in[3],
                *ad1 = (const float*)d_in[4], *b1  = (const float*)d_in[5];
    const float *W2 = (const float*)d_in[6],  *as2 = (const float*)d_in[7],
                *ad2 = (const float*)d_in[8], *b2  = (const float*)d_in[9];
    const float *W3 = (const float*)d_in[10], *as3 = (const float*)d_in[11],
                *ad3 = (const float*)d_in[12], *b3 = (const float*)d_in[13];
    float* out = (float*)d_out;

    unsigned short *pxh, *pxl, *phh, *phl, *pw1h, *pw1l, *pw2h, *pw2l;
    float *po, *py;
    cudaGetSymbolAddress((void**)&pxh, g_xh);
    cudaGetSymbolAddress((void**)&pxl, g_xl);
    cudaGetSymbolAddress((void**)&phh, g_hh);
    cudaGetSymbolAddress((void**)&phl, g_hl);
    cudaGetSymbolAddress((void**)&pw1h, g_w1h);
    cudaGetSymbolAddress((void**)&pw1l, g_w1l);
    cudaGetSymbolAddress((void**)&pw2h, g_w2h);
    cudaGetSymbolAddress((void**)&pw2l, g_w2l);
    cudaGetSymbolAddress((void**)&po, g_o);
    cudaGetSymbolAddress((void**)&py, g_y);

    const int TB = 256;
    const int warpNodeBlk = (Nn * 32 + TB - 1) / TB;
    const int edge4Blk    = (Ereal / 4 + TB - 1) / TB;
    const int alphaBlk    = (Nn + 31) / 32;
    const int place1024   = (Ereal / 4 + 1023) / 1024;
    const int mRows = (Nn + 127) / 128;

    prep_count<<<edge4Blk + W1BLK + W2BLK + PBLK, TB>>>(ei, W1, as1, ad1, W2, edge4Blk);
    scan_alpha_place<<<NBLK + alphaBlk + place1024, 1024>>>(x, ei, alphaBlk);

    // ---- layer 1 (aggregate-then-transform): 128 -> 256 ----
    agg128_k<<<warpNodeBlk, TB>>>(x);
    {
        dim3 grid(D1 / 128, mRows);
        gemm1_k<<<grid, 512>>>(pxh, pxl, pw1h, pw1l, phh, phl, b1, Nn);
    }
    // ---- layer 2: 256 -> 64 ----
    {
        dim3 grid(1, mRows);
        gemm2_k<<<grid, 256>>>(phh, phl, pw2h, pw2l, po, as2, ad2, Nn);
        agg64_k<<<warpNodeBlk, TB>>>(po, py, b2, W3, as3, ad3);
    }
    // ---- layer 3: 64 -> 1 ----
    agg1_k<<<warpNodeBlk, TB>>>(py, out, b3);
}